// round 3
// baseline (speedup 1.0000x reference)
#include <cuda_runtime.h>
#include <math_constants.h>

#define NN 50000
#define NE 800000

// ---------------- scratch (static device globals; no allocation) ----------------
__device__ float g_feat[NN * 256];
__device__ float g_h1[NN * 256];
__device__ float g_h2[NN * 256];
__device__ float g_accum[NN * 256];
__device__ float g_res2[NN * 64];
__device__ float g_el[NN * 4];
__device__ float g_er[NN * 4];
__device__ float g_emax[NN * 4];
__device__ float g_denom[NN * 4];
__device__ float g_ebuf[NE * 4];

// float atomic max via signed/unsigned int ordering trick
__device__ __forceinline__ void atomicMaxF(float* addr, float val) {
    if (val >= 0.f)
        atomicMax((int*)addr, __float_as_int(val));
    else
        atomicMin((unsigned int*)addr, __float_as_uint(val));
}

// ---------------- SGEMM: C[M,N] = A[M,256] @ B[256,N], row-major ----------------
// BM=BN=64, BK=16, 256 threads, 4x4 per thread.
__global__ void sgemm_kernel(const float* __restrict__ A, const float* __restrict__ B,
                             float* __restrict__ C, int M, int N) {
    const int K = 256;
    __shared__ float As[16][65];  // padded: conflict-free transposed stores
    __shared__ float Bs[16][64];

    int tid  = threadIdx.x;
    int row0 = blockIdx.y * 64, col0 = blockIdx.x * 64;
    int tr = tid >> 4, tc = tid & 15;

    int arow = tid >> 2, ak = (tid & 3) << 2;   // A: 64 rows x 4 float4
    int bk   = tid >> 4, bcol = (tid & 15) << 2; // B: 16 rows x 16 float4

    float acc[4][4] = {{0.f}};

    int  ar_g   = row0 + arow;
    bool avalid = (ar_g < M);

    for (int k0 = 0; k0 < K; k0 += 16) {
        float4 av = avalid
            ? *reinterpret_cast<const float4*>(A + (size_t)ar_g * K + k0 + ak)
            : make_float4(0.f, 0.f, 0.f, 0.f);
        As[ak + 0][arow] = av.x;
        As[ak + 1][arow] = av.y;
        As[ak + 2][arow] = av.z;
        As[ak + 3][arow] = av.w;

        *reinterpret_cast<float4*>(&Bs[bk][bcol]) =
            *reinterpret_cast<const float4*>(B + (size_t)(k0 + bk) * N + col0 + bcol);

        __syncthreads();

#pragma unroll
        for (int k = 0; k < 16; k++) {
            float a[4], b[4];
#pragma unroll
            for (int i = 0; i < 4; i++) a[i] = As[k][tr * 4 + i];
            float4 bv = *reinterpret_cast<const float4*>(&Bs[k][tc * 4]);
            b[0] = bv.x; b[1] = bv.y; b[2] = bv.z; b[3] = bv.w;
#pragma unroll
            for (int i = 0; i < 4; i++)
#pragma unroll
                for (int j = 0; j < 4; j++)
                    acc[i][j] = fmaf(a[i], b[j], acc[i][j]);
        }
        __syncthreads();
    }

#pragma unroll
    for (int i = 0; i < 4; i++) {
        int r = row0 + tr * 4 + i;
        if (r < M) {
            float4 v = make_float4(acc[i][0], acc[i][1], acc[i][2], acc[i][3]);
            *reinterpret_cast<float4*>(C + (size_t)r * N + col0 + tc * 4) = v;
        }
    }
}

// ---------------- el/er: one warp per (node, head) ----------------
template <int H>
__global__ void elr_kernel(const float* __restrict__ feat, const float* __restrict__ al,
                           const float* __restrict__ ar, float* __restrict__ el,
                           float* __restrict__ er) {
    int wid  = blockIdx.x * (blockDim.x >> 5) + (threadIdx.x >> 5);
    int lane = threadIdx.x & 31;
    if (wid >= NN * H) return;
    int node = wid / H, head = wid % H;
    const float* f  = feat + (size_t)node * (H * 64) + head * 64;
    const float* pl = al + head * 64;
    const float* pr = ar + head * 64;
    float f0 = f[lane], f1 = f[lane + 32];
    float sl = f0 * pl[lane] + f1 * pl[lane + 32];
    float sr = f0 * pr[lane] + f1 * pr[lane + 32];
#pragma unroll
    for (int o = 16; o; o >>= 1) {
        sl += __shfl_xor_sync(0xffffffffu, sl, o);
        sr += __shfl_xor_sync(0xffffffffu, sr, o);
    }
    if (lane == 0) { el[wid] = sl; er[wid] = sr; }
}

// ---------------- init emax/denom/accum ----------------
__global__ void init_kernel(float* __restrict__ emax, float* __restrict__ denom,
                            float* __restrict__ accum, int nh, int nhd) {
    int i = blockIdx.x * blockDim.x + threadIdx.x;
    if (i < nh) { emax[i] = -CUDART_INF_F; denom[i] = 0.f; }
    if (i < nhd) accum[i] = 0.f;
}

// ---------------- edge pass A: e = leakyrelu(el[src]+er[dst]); segment max ----------------
template <int H, int HS>
__global__ void edge_a_kernel(const int* __restrict__ src, const int* __restrict__ dst,
                              const float* __restrict__ el, const float* __restrict__ er,
                              float* __restrict__ ebuf, float* __restrict__ emax) {
    int i = blockIdx.x * blockDim.x + threadIdx.x;
    if (i >= NE * H) return;
    int e = i >> HS, h = i & (H - 1);
    int s = src[e], d = dst[e];
    float v = el[s * H + h] + er[d * H + h];
    v = (v > 0.f) ? v : 0.2f * v;
    ebuf[i] = v;
    atomicMaxF(&emax[d * H + h], v);
}

// ---------------- edge pass B: ee = exp(e - emax[dst]); segment sum ----------------
template <int H, int HS>
__global__ void edge_b_kernel(const int* __restrict__ dst, float* __restrict__ ebuf,
                              const float* __restrict__ emax, float* __restrict__ denom) {
    int i = blockIdx.x * blockDim.x + threadIdx.x;
    if (i >= NE * H) return;
    int e = i >> HS, h = i & (H - 1);
    int d  = dst[e];
    float ee = __expf(ebuf[i] - emax[d * H + h]);
    ebuf[i]  = ee;
    atomicAdd(&denom[d * H + h], ee);
}

// ---------------- edge pass C: accum[dst] += feat[src] * alpha ----------------
// TS = log2(threads per edge) = log2(H*16); each thread handles 4 consecutive floats.
template <int H, int TS>
__global__ void edge_c_kernel(const int* __restrict__ src, const int* __restrict__ dst,
                              const float* __restrict__ ebuf, const float* __restrict__ denom,
                              const float* __restrict__ feat, float* __restrict__ accum) {
    int gid = blockIdx.x * blockDim.x + threadIdx.x;
    if (gid >= (NE << TS)) return;
    int e = gid >> TS;
    int t = gid & ((1 << TS) - 1);
    int h = t >> 4;  // 16 threads (64 floats) per head
    int s = src[e], d = dst[e];
    float alpha = ebuf[e * H + h] / denom[d * H + h];
    const int HD = H * 64;
    float4 fv = *reinterpret_cast<const float4*>(feat + (size_t)s * HD + (t << 2));
    float* p  = accum + (size_t)d * HD + (t << 2);
    atomicAdd(p + 0, fv.x * alpha);
    atomicAdd(p + 1, fv.y * alpha);
    atomicAdd(p + 2, fv.z * alpha);
    atomicAdd(p + 3, fv.w * alpha);
}

// ---------------- finalize: bias + residual + optional ELU ----------------
template <int HD, int ACT, int RES>
__global__ void finalize_kernel(const float* __restrict__ accum, const float* __restrict__ bias,
                                const float* __restrict__ resid, float* __restrict__ out, int n) {
    int i = blockIdx.x * blockDim.x + threadIdx.x;
    if (i >= n) return;
    float v = accum[i] + bias[i & (HD - 1)];
    if (RES) v += resid[i];
    if (ACT) v = (v > 0.f) ? v : expm1f(v);
    out[i] = v;
}

// ---------------- host ----------------
extern "C" void kernel_launch(void* const* d_in, const int* in_sizes, int n_in,
                              void* d_out, int out_size) {
    const float* x    = (const float*)d_in[0];
    const int*   src  = (const int*)d_in[1];
    const int*   dst  = (const int*)d_in[2];
    const float* W0   = (const float*)d_in[3];
    const float* al0  = (const float*)d_in[4];
    const float* ar0  = (const float*)d_in[5];
    const float* b0   = (const float*)d_in[6];
    const float* W1   = (const float*)d_in[7];
    const float* al1  = (const float*)d_in[8];
    const float* ar1  = (const float*)d_in[9];
    const float* b1   = (const float*)d_in[10];
    const float* W2   = (const float*)d_in[11];
    const float* al2  = (const float*)d_in[12];
    const float* ar2  = (const float*)d_in[13];
    const float* b2   = (const float*)d_in[14];
    const float* rw2  = (const float*)d_in[15];
    float* out = (float*)d_out;

    float *feat, *h1, *h2, *accum, *res2, *el, *er, *emax, *denom, *ebuf;
    cudaGetSymbolAddress((void**)&feat,  g_feat);
    cudaGetSymbolAddress((void**)&h1,    g_h1);
    cudaGetSymbolAddress((void**)&h2,    g_h2);
    cudaGetSymbolAddress((void**)&accum, g_accum);
    cudaGetSymbolAddress((void**)&res2,  g_res2);
    cudaGetSymbolAddress((void**)&el,    g_el);
    cudaGetSymbolAddress((void**)&er,    g_er);
    cudaGetSymbolAddress((void**)&emax,  g_emax);
    cudaGetSymbolAddress((void**)&denom, g_denom);
    cudaGetSymbolAddress((void**)&ebuf,  g_ebuf);

    const int MTILES = (NN + 63) / 64;  // 782

    // ================= layer 0: x -> h1, H=4, no residual, ELU =================
    {
        sgemm_kernel<<<dim3(4, MTILES), 256>>>(x, W0, feat, NN, 256);
        elr_kernel<4><<<(NN * 4 + 3) / 4, 128>>>(feat, al0, ar0, el, er);
        init_kernel<<<(NN * 256 + 255) / 256, 256>>>(emax, denom, accum, NN * 4, NN * 256);
        edge_a_kernel<4, 2><<<(NE * 4 + 255) / 256, 256>>>(src, dst, el, er, ebuf, emax);
        edge_b_kernel<4, 2><<<(NE * 4 + 255) / 256, 256>>>(dst, ebuf, emax, denom);
        edge_c_kernel<4, 6><<<((NE << 6) + 255) / 256, 256>>>(src, dst, ebuf, denom, feat, accum);
        finalize_kernel<256, 1, 0><<<(NN * 256 + 255) / 256, 256>>>(accum, b0, nullptr, h1, NN * 256);
    }

    // ================= layer 1: h1 -> h2, H=4, identity residual, ELU =================
    {
        sgemm_kernel<<<dim3(4, MTILES), 256>>>(h1, W1, feat, NN, 256);
        elr_kernel<4><<<(NN * 4 + 3) / 4, 128>>>(feat, al1, ar1, el, er);
        init_kernel<<<(NN * 256 + 255) / 256, 256>>>(emax, denom, accum, NN * 4, NN * 256);
        edge_a_kernel<4, 2><<<(NE * 4 + 255) / 256, 256>>>(src, dst, el, er, ebuf, emax);
        edge_b_kernel<4, 2><<<(NE * 4 + 255) / 256, 256>>>(dst, ebuf, emax, denom);
        edge_c_kernel<4, 6><<<((NE << 6) + 255) / 256, 256>>>(src, dst, ebuf, denom, feat, accum);
        finalize_kernel<256, 1, 1><<<(NN * 256 + 255) / 256, 256>>>(accum, b1, h1, h2, NN * 256);
    }

    // ================= layer 2: h2 -> out, H=1, linear residual, no act =================
    {
        sgemm_kernel<<<dim3(1, MTILES), 256>>>(h2, W2, feat, NN, 64);
        sgemm_kernel<<<dim3(1, MTILES), 256>>>(h2, rw2, res2, NN, 64);
        elr_kernel<1><<<(NN + 3) / 4, 128>>>(feat, al2, ar2, el, er);
        init_kernel<<<(NN * 64 + 255) / 256, 256>>>(emax, denom, accum, NN, NN * 64);
        edge_a_kernel<1, 0><<<(NE + 255) / 256, 256>>>(src, dst, el, er, ebuf, emax);
        edge_b_kernel<1, 0><<<(NE + 255) / 256, 256>>>(dst, ebuf, emax, denom);
        edge_c_kernel<1, 4><<<((NE << 4) + 255) / 256, 256>>>(src, dst, ebuf, denom, feat, accum);
        finalize_kernel<64, 0, 1><<<(NN * 64 + 255) / 256, 256>>>(accum, b2, res2, out, NN * 64);
    }
}

// round 4
// speedup vs baseline: 2.0920x; 2.0920x over previous
#include <cuda_runtime.h>
#include <math_constants.h>

#define NN 50000
#define NE 800000

// ---------------- scratch (static device globals; no allocation) ----------------
__device__ float g_feat[NN * 256];
__device__ float g_h1[NN * 256];
__device__ float g_h2[NN * 256];
__device__ float g_res2[NN * 64];
__device__ float g_el[NN * 4];
__device__ float g_er[NN * 4];
__device__ float g_alpha[NE * 4];   // alpha stored by CSR slot: [slot*H + h]
__device__ int   g_rowptr[NN + 1];
__device__ int   g_cursor[NN];      // used as degree counter, then scatter cursor
__device__ int   g_eidx[NE];

// ---------------- SGEMM: C[M,N] = A[M,256] @ B[256,N], row-major ----------------
__global__ void sgemm_kernel(const float* __restrict__ A, const float* __restrict__ B,
                             float* __restrict__ C, int M, int N) {
    const int K = 256;
    __shared__ float As[16][65];
    __shared__ float Bs[16][64];

    int tid  = threadIdx.x;
    int row0 = blockIdx.y * 64, col0 = blockIdx.x * 64;
    int tr = tid >> 4, tc = tid & 15;

    int arow = tid >> 2, ak = (tid & 3) << 2;
    int bk   = tid >> 4, bcol = (tid & 15) << 2;

    float acc[4][4] = {{0.f}};

    int  ar_g   = row0 + arow;
    bool avalid = (ar_g < M);

    for (int k0 = 0; k0 < K; k0 += 16) {
        float4 av = avalid
            ? *reinterpret_cast<const float4*>(A + (size_t)ar_g * K + k0 + ak)
            : make_float4(0.f, 0.f, 0.f, 0.f);
        As[ak + 0][arow] = av.x;
        As[ak + 1][arow] = av.y;
        As[ak + 2][arow] = av.z;
        As[ak + 3][arow] = av.w;

        *reinterpret_cast<float4*>(&Bs[bk][bcol]) =
            *reinterpret_cast<const float4*>(B + (size_t)(k0 + bk) * N + col0 + bcol);

        __syncthreads();

#pragma unroll
        for (int k = 0; k < 16; k++) {
            float a[4], b[4];
#pragma unroll
            for (int i = 0; i < 4; i++) a[i] = As[k][tr * 4 + i];
            float4 bv = *reinterpret_cast<const float4*>(&Bs[k][tc * 4]);
            b[0] = bv.x; b[1] = bv.y; b[2] = bv.z; b[3] = bv.w;
#pragma unroll
            for (int i = 0; i < 4; i++)
#pragma unroll
                for (int j = 0; j < 4; j++)
                    acc[i][j] = fmaf(a[i], b[j], acc[i][j]);
        }
        __syncthreads();
    }

#pragma unroll
    for (int i = 0; i < 4; i++) {
        int r = row0 + tr * 4 + i;
        if (r < M) {
            float4 v = make_float4(acc[i][0], acc[i][1], acc[i][2], acc[i][3]);
            *reinterpret_cast<float4*>(C + (size_t)r * N + col0 + tc * 4) = v;
        }
    }
}

// ---------------- el/er: one warp per (node, head) ----------------
template <int H>
__global__ void elr_kernel(const float* __restrict__ feat, const float* __restrict__ al,
                           const float* __restrict__ ar, float* __restrict__ el,
                           float* __restrict__ er) {
    int wid  = blockIdx.x * (blockDim.x >> 5) + (threadIdx.x >> 5);
    int lane = threadIdx.x & 31;
    if (wid >= NN * H) return;
    int node = wid / H, head = wid % H;
    const float* f  = feat + (size_t)node * (H * 64) + head * 64;
    const float* pl = al + head * 64;
    const float* pr = ar + head * 64;
    float f0 = f[lane], f1 = f[lane + 32];
    float sl = f0 * pl[lane] + f1 * pl[lane + 32];
    float sr = f0 * pr[lane] + f1 * pr[lane + 32];
#pragma unroll
    for (int o = 16; o; o >>= 1) {
        sl += __shfl_xor_sync(0xffffffffu, sl, o);
        sr += __shfl_xor_sync(0xffffffffu, sr, o);
    }
    if (lane == 0) { el[wid] = sl; er[wid] = sr; }
}

// ---------------- CSR build ----------------
__global__ void zero_deg_kernel(int* __restrict__ deg) {
    int i = blockIdx.x * blockDim.x + threadIdx.x;
    if (i < NN) deg[i] = 0;
}

__global__ void hist_kernel(const int* __restrict__ dst, int* __restrict__ deg) {
    int e = blockIdx.x * blockDim.x + threadIdx.x;
    if (e < NE) atomicAdd(&deg[dst[e]], 1);
}

// single-block exclusive scan of deg -> rowptr, and cursor=rowptr
__global__ void scan_kernel(int* __restrict__ deg_cursor, int* __restrict__ rowptr) {
    __shared__ int warp_sums[32];
    __shared__ int s_carry;
    int tid = threadIdx.x;  // 1024 threads
    if (tid == 0) s_carry = 0;
    __syncthreads();
    for (int base = 0; base < NN; base += 1024) {
        int i = base + tid;
        int v = (i < NN) ? deg_cursor[i] : 0;
        int x = v;
#pragma unroll
        for (int o = 1; o < 32; o <<= 1) {
            int y = __shfl_up_sync(0xffffffffu, x, o);
            if ((tid & 31) >= o) x += y;
        }
        if ((tid & 31) == 31) warp_sums[tid >> 5] = x;
        __syncthreads();
        if (tid < 32) {
            int s = warp_sums[tid];
#pragma unroll
            for (int o = 1; o < 32; o <<= 1) {
                int y = __shfl_up_sync(0xffffffffu, s, o);
                if (tid >= o) s += y;
            }
            warp_sums[tid] = s;
        }
        __syncthreads();
        int excl = x - v + ((tid >= 32) ? warp_sums[(tid >> 5) - 1] : 0);
        int val  = s_carry + excl;
        if (i < NN) { rowptr[i] = val; deg_cursor[i] = val; }
        int chunk_total = warp_sums[31];
        __syncthreads();
        if (tid == 0) s_carry += chunk_total;
        __syncthreads();
    }
    if (tid == 0) rowptr[NN] = NE;
}

__global__ void scatter_kernel(const int* __restrict__ dst, int* __restrict__ cursor,
                               int* __restrict__ eidx) {
    int e = blockIdx.x * blockDim.x + threadIdx.x;
    if (e < NE) {
        int p = atomicAdd(&cursor[dst[e]], 1);
        eidx[p] = e;
    }
}

// ---------------- softmax over incoming edges: one warp per node ----------------
// Lanes: h = lane & (H-1), group g = lane >> L2H; group strides over edges.
template <int H, int L2H>
__global__ void softmax_kernel(const int* __restrict__ rowptr, const int* __restrict__ eidx,
                               const int* __restrict__ src, const float* __restrict__ el,
                               const float* __restrict__ er, float* __restrict__ alpha) {
    const int GS = 32 >> L2H;
    int w = blockIdx.x * (blockDim.x >> 5) + (threadIdx.x >> 5);
    if (w >= NN) return;
    int lane = threadIdx.x & 31;
    int h = lane & (H - 1);
    int g = lane >> L2H;
    int start = rowptr[w], end = rowptr[w + 1];
    float erv = er[w * H + h];

    float m = -CUDART_INF_F;
    for (int i = start + g; i < end; i += GS) {
        int s = src[eidx[i]];
        float v = el[s * H + h] + erv;
        v = (v > 0.f) ? v : 0.2f * v;
        m = fmaxf(m, v);
    }
#pragma unroll
    for (int o = H; o <= 16; o <<= 1) m = fmaxf(m, __shfl_xor_sync(0xffffffffu, m, o));

    float ssum = 0.f;
    for (int i = start + g; i < end; i += GS) {
        int s = src[eidx[i]];
        float v = el[s * H + h] + erv;
        v = (v > 0.f) ? v : 0.2f * v;
        ssum += __expf(v - m);
    }
#pragma unroll
    for (int o = H; o <= 16; o <<= 1) ssum += __shfl_xor_sync(0xffffffffu, ssum, o);

    float inv = 1.f / ssum;
    for (int i = start + g; i < end; i += GS) {
        int s = src[eidx[i]];
        float v = el[s * H + h] + erv;
        v = (v > 0.f) ? v : 0.2f * v;
        alpha[i * H + h] = __expf(v - m) * inv;
    }
}

// ---------------- aggregate H=4 (+ fused bias/residual/ELU): one warp per node ----------------
// Lane covers cols [4*lane, 4*lane+4) (head lane>>4) and [128+4*lane, ...) (head 2+(lane>>4)).
template <int ACT, int RES>
__global__ void aggregate4_kernel(const int* __restrict__ rowptr, const int* __restrict__ eidx,
                                  const int* __restrict__ src, const float* __restrict__ alpha,
                                  const float* __restrict__ feat, const float* __restrict__ bias,
                                  const float* __restrict__ resid, float* __restrict__ out) {
    int w = blockIdx.x * (blockDim.x >> 5) + (threadIdx.x >> 5);
    if (w >= NN) return;
    int lane = threadIdx.x & 31;
    int start = rowptr[w], end = rowptr[w + 1];
    int hA = lane >> 4;       // head of first half
    int c0 = 4 * lane;        // first-half column
    float4 accA = make_float4(0.f, 0.f, 0.f, 0.f);
    float4 accB = make_float4(0.f, 0.f, 0.f, 0.f);

    for (int i = start; i < end; i++) {
        int e = eidx[i];
        int s = src[e];
        float a0 = alpha[i * 4 + hA];
        float a1 = alpha[i * 4 + 2 + hA];
        const float* fp = feat + (size_t)s * 256;
        float4 f0 = *reinterpret_cast<const float4*>(fp + c0);
        float4 f1 = *reinterpret_cast<const float4*>(fp + 128 + c0);
        accA.x = fmaf(a0, f0.x, accA.x); accA.y = fmaf(a0, f0.y, accA.y);
        accA.z = fmaf(a0, f0.z, accA.z); accA.w = fmaf(a0, f0.w, accA.w);
        accB.x = fmaf(a1, f1.x, accB.x); accB.y = fmaf(a1, f1.y, accB.y);
        accB.z = fmaf(a1, f1.z, accB.z); accB.w = fmaf(a1, f1.w, accB.w);
    }

    float4 bA = *reinterpret_cast<const float4*>(bias + c0);
    float4 bB = *reinterpret_cast<const float4*>(bias + 128 + c0);
    accA.x += bA.x; accA.y += bA.y; accA.z += bA.z; accA.w += bA.w;
    accB.x += bB.x; accB.y += bB.y; accB.z += bB.z; accB.w += bB.w;
    if (RES) {
        float4 rA = *reinterpret_cast<const float4*>(resid + (size_t)w * 256 + c0);
        float4 rB = *reinterpret_cast<const float4*>(resid + (size_t)w * 256 + 128 + c0);
        accA.x += rA.x; accA.y += rA.y; accA.z += rA.z; accA.w += rA.w;
        accB.x += rB.x; accB.y += rB.y; accB.z += rB.z; accB.w += rB.w;
    }
    if (ACT) {
        accA.x = (accA.x > 0.f) ? accA.x : expm1f(accA.x);
        accA.y = (accA.y > 0.f) ? accA.y : expm1f(accA.y);
        accA.z = (accA.z > 0.f) ? accA.z : expm1f(accA.z);
        accA.w = (accA.w > 0.f) ? accA.w : expm1f(accA.w);
        accB.x = (accB.x > 0.f) ? accB.x : expm1f(accB.x);
        accB.y = (accB.y > 0.f) ? accB.y : expm1f(accB.y);
        accB.z = (accB.z > 0.f) ? accB.z : expm1f(accB.z);
        accB.w = (accB.w > 0.f) ? accB.w : expm1f(accB.w);
    }
    *reinterpret_cast<float4*>(out + (size_t)w * 256 + c0)       = accA;
    *reinterpret_cast<float4*>(out + (size_t)w * 256 + 128 + c0) = accB;
}

// ---------------- aggregate H=1 (+ fused bias/residual): one warp per node ----------------
__global__ void aggregate1_kernel(const int* __restrict__ rowptr, const int* __restrict__ eidx,
                                  const int* __restrict__ src, const float* __restrict__ alpha,
                                  const float* __restrict__ feat, const float* __restrict__ bias,
                                  const float* __restrict__ resid, float* __restrict__ out) {
    int w = blockIdx.x * (blockDim.x >> 5) + (threadIdx.x >> 5);
    if (w >= NN) return;
    int lane = threadIdx.x & 31;
    int start = rowptr[w], end = rowptr[w + 1];
    int c0 = 2 * lane;
    float2 acc = make_float2(0.f, 0.f);

    for (int i = start; i < end; i++) {
        int e = eidx[i];
        int s = src[e];
        float a = alpha[i];
        float2 f = *reinterpret_cast<const float2*>(feat + (size_t)s * 64 + c0);
        acc.x = fmaf(a, f.x, acc.x);
        acc.y = fmaf(a, f.y, acc.y);
    }
    float2 b = *reinterpret_cast<const float2*>(bias + c0);
    float2 r = *reinterpret_cast<const float2*>(resid + (size_t)w * 64 + c0);
    acc.x += b.x + r.x;
    acc.y += b.y + r.y;
    *reinterpret_cast<float2*>(out + (size_t)w * 64 + c0) = acc;
}

// ---------------- host ----------------
extern "C" void kernel_launch(void* const* d_in, const int* in_sizes, int n_in,
                              void* d_out, int out_size) {
    const float* x    = (const float*)d_in[0];
    const int*   src  = (const int*)d_in[1];
    const int*   dst  = (const int*)d_in[2];
    const float* W0   = (const float*)d_in[3];
    const float* al0  = (const float*)d_in[4];
    const float* ar0  = (const float*)d_in[5];
    const float* b0   = (const float*)d_in[6];
    const float* W1   = (const float*)d_in[7];
    const float* al1  = (const float*)d_in[8];
    const float* ar1  = (const float*)d_in[9];
    const float* b1   = (const float*)d_in[10];
    const float* W2   = (const float*)d_in[11];
    const float* al2  = (const float*)d_in[12];
    const float* ar2  = (const float*)d_in[13];
    const float* b2   = (const float*)d_in[14];
    const float* rw2  = (const float*)d_in[15];
    float* out = (float*)d_out;

    float *feat, *h1, *h2, *res2, *el, *er, *alpha;
    int *rowptr, *cursor, *eidx;
    cudaGetSymbolAddress((void**)&feat,   g_feat);
    cudaGetSymbolAddress((void**)&h1,     g_h1);
    cudaGetSymbolAddress((void**)&h2,     g_h2);
    cudaGetSymbolAddress((void**)&res2,   g_res2);
    cudaGetSymbolAddress((void**)&el,     g_el);
    cudaGetSymbolAddress((void**)&er,     g_er);
    cudaGetSymbolAddress((void**)&alpha,  g_alpha);
    cudaGetSymbolAddress((void**)&rowptr, g_rowptr);
    cudaGetSymbolAddress((void**)&cursor, g_cursor);
    cudaGetSymbolAddress((void**)&eidx,   g_eidx);

    const int MTILES = (NN + 63) / 64;       // 782
    const int NODE_WARP_BLOCKS = (NN + 7) / 8;  // 6250 (8 warps/block)

    // ---------- CSR build (dst is shared by all layers; build once) ----------
    zero_deg_kernel<<<(NN + 255) / 256, 256>>>(cursor);
    hist_kernel<<<(NE + 255) / 256, 256>>>(dst, cursor);
    scan_kernel<<<1, 1024>>>(cursor, rowptr);
    scatter_kernel<<<(NE + 255) / 256, 256>>>(dst, cursor, eidx);

    // ================= layer 0: x -> h1, H=4, no residual, ELU =================
    sgemm_kernel<<<dim3(4, MTILES), 256>>>(x, W0, feat, NN, 256);
    elr_kernel<4><<<(NN * 4 + 3) / 4, 128>>>(feat, al0, ar0, el, er);
    softmax_kernel<4, 2><<<NODE_WARP_BLOCKS, 256>>>(rowptr, eidx, src, el, er, alpha);
    aggregate4_kernel<1, 0><<<NODE_WARP_BLOCKS, 256>>>(rowptr, eidx, src, alpha, feat, b0, nullptr, h1);

    // ================= layer 1: h1 -> h2, H=4, identity residual, ELU =================
    sgemm_kernel<<<dim3(4, MTILES), 256>>>(h1, W1, feat, NN, 256);
    elr_kernel<4><<<(NN * 4 + 3) / 4, 128>>>(feat, al1, ar1, el, er);
    softmax_kernel<4, 2><<<NODE_WARP_BLOCKS, 256>>>(rowptr, eidx, src, el, er, alpha);
    aggregate4_kernel<1, 1><<<NODE_WARP_BLOCKS, 256>>>(rowptr, eidx, src, alpha, feat, b1, h1, h2);

    // ================= layer 2: h2 -> out, H=1, linear residual, no act =================
    sgemm_kernel<<<dim3(1, MTILES), 256>>>(h2, W2, feat, NN, 64);
    sgemm_kernel<<<dim3(1, MTILES), 256>>>(h2, rw2, res2, NN, 64);
    elr_kernel<1><<<(NN + 3) / 4, 128>>>(feat, al2, ar2, el, er);
    softmax_kernel<1, 0><<<NODE_WARP_BLOCKS, 256>>>(rowptr, eidx, src, el, er, alpha);
    aggregate1_kernel<<<NODE_WARP_BLOCKS, 256>>>(rowptr, eidx, src, alpha, feat, b2, res2, out);
}

// round 6
// speedup vs baseline: 2.8617x; 1.3679x over previous
#include <cuda_runtime.h>
#include <math_constants.h>

#define NN 50000
#define NE 800000

// ---------------- scratch (static device globals; no allocation) ----------------
__device__ float g_feat[NN * 256];
__device__ float g_h1[NN * 256];
__device__ float g_h2[NN * 256];
__device__ float g_res2[NN * 64];
__device__ float g_el[NN * 4];
__device__ float g_er[NN * 4];
__device__ float g_alpha[NE * 4];   // alpha stored by CSR slot: [slot*H + h]
__device__ int   g_rowptr[NN + 1];
__device__ int   g_cursor[NN];
__device__ int   g_eidx[NE];

__device__ __forceinline__ unsigned f2tf(float f) {
    unsigned u;
    asm("cvt.rna.tf32.f32 %0, %1;" : "=r"(u) : "f"(f));
    return u;
}

// ---------------- TF32 tensor-core GEMM: C[M,N] = A[M,256] @ B[256,N] ----------------
// BM=64, BN=64, BK=32. 256 threads = 8 warps in 2(m) x 4(n); warp tile 32x16.
// SMEM stride 72 words (= 8 mod 32 banks) -> conflict-free fragment loads.
__global__ void __launch_bounds__(256) sgemm_tf32_kernel(
        const float* __restrict__ A, const float* __restrict__ B,
        float* __restrict__ C, int M, int N) {
    const int K = 256;
    __shared__ unsigned As[32 * 72];  // As[k][m], m in [0,64)
    __shared__ unsigned Bs[32 * 72];  // Bs[k][n], n in [0,64)

    int tid  = threadIdx.x;
    int wid  = tid >> 5;
    int lane = tid & 31;
    int row0 = blockIdx.y * 64, col0 = blockIdx.x * 64;

    int wm = (wid & 1) * 32;   // warp row base in block
    int wn = (wid >> 1) * 16;  // warp col base in block

    // global A load mapping: 64 rows x 8 float4 (32 k)
    int arow   = tid >> 2;          // 0..63
    int acol4  = (tid & 3) << 2;    // 0,4,8,12
    int ar_g   = row0 + arow;
    bool avalid = (ar_g < M);

    float acc[2][2][4];
#pragma unroll
    for (int i = 0; i < 2; i++)
#pragma unroll
        for (int j = 0; j < 2; j++)
#pragma unroll
            for (int v = 0; v < 4; v++) acc[i][j][v] = 0.f;

    int fr = lane >> 2;  // fragment row helper (0..7)
    int fc = lane & 3;   // fragment col helper (0..3)

    for (int k0 = 0; k0 < K; k0 += 32) {
        // ---- load A tile (transposed into As[k][m]) ----
#pragma unroll
        for (int j = 0; j < 2; j++) {
            int kk = acol4 + j * 16;
            float4 v = avalid
                ? *reinterpret_cast<const float4*>(A + (size_t)ar_g * K + k0 + kk)
                : make_float4(0.f, 0.f, 0.f, 0.f);
            As[(kk + 0) * 72 + arow] = f2tf(v.x);
            As[(kk + 1) * 72 + arow] = f2tf(v.y);
            As[(kk + 2) * 72 + arow] = f2tf(v.z);
            As[(kk + 3) * 72 + arow] = f2tf(v.w);
        }
        // ---- load B tile (natural Bs[k][n]) ----
#pragma unroll
        for (int j = 0; j < 2; j++) {
            int idx  = tid + j * 256;
            int krow = idx >> 4;
            int ncol = (idx & 15) << 2;
            float4 v = *reinterpret_cast<const float4*>(
                B + (size_t)(k0 + krow) * N + col0 + ncol);
            uint4 u = make_uint4(f2tf(v.x), f2tf(v.y), f2tf(v.z), f2tf(v.w));
            *reinterpret_cast<uint4*>(&Bs[krow * 72 + ncol]) = u;
        }
        __syncthreads();

        // ---- compute: 4 k-steps of 8 ----
#pragma unroll
        for (int kt = 0; kt < 4; kt++) {
            int kb = kt * 8;
            unsigned a[2][4], b[2][2];
#pragma unroll
            for (int mt = 0; mt < 2; mt++) {
                int r = wm + mt * 16 + fr;
                a[mt][0] = As[(kb + fc) * 72 + r];
                a[mt][1] = As[(kb + fc) * 72 + r + 8];
                a[mt][2] = As[(kb + fc + 4) * 72 + r];
                a[mt][3] = As[(kb + fc + 4) * 72 + r + 8];
            }
#pragma unroll
            for (int nt = 0; nt < 2; nt++) {
                int c = wn + nt * 8 + fr;
                b[nt][0] = Bs[(kb + fc) * 72 + c];
                b[nt][1] = Bs[(kb + fc + 4) * 72 + c];
            }
#pragma unroll
            for (int mt = 0; mt < 2; mt++)
#pragma unroll
                for (int nt = 0; nt < 2; nt++) {
                    asm volatile(
                        "mma.sync.aligned.m16n8k8.row.col.f32.tf32.tf32.f32 "
                        "{%0,%1,%2,%3}, {%4,%5,%6,%7}, {%8,%9}, {%0,%1,%2,%3};\n"
                        : "+f"(acc[mt][nt][0]), "+f"(acc[mt][nt][1]),
                          "+f"(acc[mt][nt][2]), "+f"(acc[mt][nt][3])
                        : "r"(a[mt][0]), "r"(a[mt][1]), "r"(a[mt][2]), "r"(a[mt][3]),
                          "r"(b[nt][0]), "r"(b[nt][1]));
                }
        }
        __syncthreads();
    }

    // ---- epilogue: c frag mapping: (row=l/4, col=2*(l%4)) ----
#pragma unroll
    for (int mt = 0; mt < 2; mt++) {
#pragma unroll
        for (int nt = 0; nt < 2; nt++) {
            int crow = row0 + wm + mt * 16 + fr;
            int ccol = col0 + wn + nt * 8 + 2 * fc;
            if (crow < M)
                *reinterpret_cast<float2*>(C + (size_t)crow * N + ccol) =
                    make_float2(acc[mt][nt][0], acc[mt][nt][1]);
            if (crow + 8 < M)
                *reinterpret_cast<float2*>(C + (size_t)(crow + 8) * N + ccol) =
                    make_float2(acc[mt][nt][2], acc[mt][nt][3]);
        }
    }
}

// ---------------- el/er: one warp per (node, head) ----------------
template <int H>
__global__ void elr_kernel(const float* __restrict__ feat, const float* __restrict__ al,
                           const float* __restrict__ ar, float* __restrict__ el,
                           float* __restrict__ er) {
    int wid  = blockIdx.x * (blockDim.x >> 5) + (threadIdx.x >> 5);
    int lane = threadIdx.x & 31;
    if (wid >= NN * H) return;
    int node = wid / H, head = wid % H;
    const float* f  = feat + (size_t)node * (H * 64) + head * 64;
    const float* pl = al + head * 64;
    const float* pr = ar + head * 64;
    float f0 = f[lane], f1 = f[lane + 32];
    float sl = f0 * pl[lane] + f1 * pl[lane + 32];
    float sr = f0 * pr[lane] + f1 * pr[lane + 32];
#pragma unroll
    for (int o = 16; o; o >>= 1) {
        sl += __shfl_xor_sync(0xffffffffu, sl, o);
        sr += __shfl_xor_sync(0xffffffffu, sr, o);
    }
    if (lane == 0) { el[wid] = sl; er[wid] = sr; }
}

// ---------------- CSR build ----------------
__global__ void zero_deg_kernel(int* __restrict__ deg) {
    int i = blockIdx.x * blockDim.x + threadIdx.x;
    if (i < NN) deg[i] = 0;
}

__global__ void hist_kernel(const int* __restrict__ dst, int* __restrict__ deg) {
    int e = blockIdx.x * blockDim.x + threadIdx.x;
    if (e < NE) atomicAdd(&deg[dst[e]], 1);
}

__global__ void scan_kernel(int* __restrict__ deg_cursor, int* __restrict__ rowptr) {
    __shared__ int warp_sums[32];
    __shared__ int s_carry;
    int tid = threadIdx.x;  // 1024 threads
    if (tid == 0) s_carry = 0;
    __syncthreads();
    for (int base = 0; base < NN; base += 1024) {
        int i = base + tid;
        int v = (i < NN) ? deg_cursor[i] : 0;
        int x = v;
#pragma unroll
        for (int o = 1; o < 32; o <<= 1) {
            int y = __shfl_up_sync(0xffffffffu, x, o);
            if ((tid & 31) >= o) x += y;
        }
        if ((tid & 31) == 31) warp_sums[tid >> 5] = x;
        __syncthreads();
        if (tid < 32) {
            int s = warp_sums[tid];
#pragma unroll
            for (int o = 1; o < 32; o <<= 1) {
                int y = __shfl_up_sync(0xffffffffu, s, o);
                if (tid >= o) s += y;
            }
            warp_sums[tid] = s;
        }
        __syncthreads();
        int excl = x - v + ((tid >= 32) ? warp_sums[(tid >> 5) - 1] : 0);
        int val  = s_carry + excl;
        if (i < NN) { rowptr[i] = val; deg_cursor[i] = val; }
        int chunk_total = warp_sums[31];
        __syncthreads();
        if (tid == 0) s_carry += chunk_total;
        __syncthreads();
    }
    if (tid == 0) rowptr[NN] = NE;
}

__global__ void scatter_kernel(const int* __restrict__ dst, int* __restrict__ cursor,
                               int* __restrict__ eidx) {
    int e = blockIdx.x * blockDim.x + threadIdx.x;
    if (e < NE) {
        int p = atomicAdd(&cursor[dst[e]], 1);
        eidx[p] = e;
    }
}

// ---------------- softmax over incoming edges: one warp per node ----------------
template <int H, int L2H>
__global__ void softmax_kernel(const int* __restrict__ rowptr, const int* __restrict__ eidx,
                               const int* __restrict__ src, const float* __restrict__ el,
                               const float* __restrict__ er, float* __restrict__ alpha) {
    const int GS = 32 >> L2H;
    int w = blockIdx.x * (blockDim.x >> 5) + (threadIdx.x >> 5);
    if (w >= NN) return;
    int lane = threadIdx.x & 31;
    int h = lane & (H - 1);
    int g = lane >> L2H;
    int start = rowptr[w], end = rowptr[w + 1];
    float erv = er[w * H + h];

    float m = -CUDART_INF_F;
    for (int i = start + g; i < end; i += GS) {
        int s = src[eidx[i]];
        float v = el[s * H + h] + erv;
        v = (v > 0.f) ? v : 0.2f * v;
        m = fmaxf(m, v);
    }
#pragma unroll
    for (int o = H; o <= 16; o <<= 1) m = fmaxf(m, __shfl_xor_sync(0xffffffffu, m, o));

    float ssum = 0.f;
    for (int i = start + g; i < end; i += GS) {
        int s = src[eidx[i]];
        float v = el[s * H + h] + erv;
        v = (v > 0.f) ? v : 0.2f * v;
        ssum += __expf(v - m);
    }
#pragma unroll
    for (int o = H; o <= 16; o <<= 1) ssum += __shfl_xor_sync(0xffffffffu, ssum, o);

    float inv = 1.f / ssum;
    for (int i = start + g; i < end; i += GS) {
        int s = src[eidx[i]];
        float v = el[s * H + h] + erv;
        v = (v > 0.f) ? v : 0.2f * v;
        alpha[i * H + h] = __expf(v - m) * inv;
    }
}

// ---------------- aggregate H=4 (+ fused bias/residual/ELU): one warp per node ----------------
template <int ACT, int RES>
__global__ void aggregate4_kernel(const int* __restrict__ rowptr, const int* __restrict__ eidx,
                                  const int* __restrict__ src, const float* __restrict__ alpha,
                                  const float* __restrict__ feat, const float* __restrict__ bias,
                                  const float* __restrict__ resid, float* __restrict__ out) {
    int w = blockIdx.x * (blockDim.x >> 5) + (threadIdx.x >> 5);
    if (w >= NN) return;
    int lane = threadIdx.x & 31;
    int start = rowptr[w], end = rowptr[w + 1];
    int hA = lane >> 4;
    int c0 = 4 * lane;
    float4 accA = make_float4(0.f, 0.f, 0.f, 0.f);
    float4 accB = make_float4(0.f, 0.f, 0.f, 0.f);

    for (int i = start; i < end; i++) {
        int e = eidx[i];
        int s = src[e];
        float a0 = alpha[i * 4 + hA];
        float a1 = alpha[i * 4 + 2 + hA];
        const float* fp = feat + (size_t)s * 256;
        float4 f0 = *reinterpret_cast<const float4*>(fp + c0);
        float4 f1 = *reinterpret_cast<const float4*>(fp + 128 + c0);
        accA.x = fmaf(a0, f0.x, accA.x); accA.y = fmaf(a0, f0.y, accA.y);
        accA.z = fmaf(a0, f0.z, accA.z); accA.w = fmaf(a0, f0.w, accA.w);
        accB.x = fmaf(a1, f1.x, accB.x); accB.y = fmaf(a1, f1.y, accB.y);
        accB.z = fmaf(a1, f1.z, accB.z); accB.w = fmaf(a1, f1.w, accB.w);
    }

    float4 bA = *reinterpret_cast<const float4*>(bias + c0);
    float4 bB = *reinterpret_cast<const float4*>(bias + 128 + c0);
    accA.x += bA.x; accA.y += bA.y; accA.z += bA.z; accA.w += bA.w;
    accB.x += bB.x; accB.y += bB.y; accB.z += bB.z; accB.w += bB.w;
    if (RES) {
        float4 rA = *reinterpret_cast<const float4*>(resid + (size_t)w * 256 + c0);
        float4 rB = *reinterpret_cast<const float4*>(resid + (size_t)w * 256 + 128 + c0);
        accA.x += rA.x; accA.y += rA.y; accA.z += rA.z; accA.w += rA.w;
        accB.x += rB.x; accB.y += rB.y; accB.z += rB.z; accB.w += rB.w;
    }
    if (ACT) {
        accA.x = (accA.x > 0.f) ? accA.x : expm1f(accA.x);
        accA.y = (accA.y > 0.f) ? accA.y : expm1f(accA.y);
        accA.z = (accA.z > 0.f) ? accA.z : expm1f(accA.z);
        accA.w = (accA.w > 0.f) ? accA.w : expm1f(accA.w);
        accB.x = (accB.x > 0.f) ? accB.x : expm1f(accB.x);
        accB.y = (accB.y > 0.f) ? accB.y : expm1f(accB.y);
        accB.z = (accB.z > 0.f) ? accB.z : expm1f(accB.z);
        accB.w = (accB.w > 0.f) ? accB.w : expm1f(accB.w);
    }
    *reinterpret_cast<float4*>(out + (size_t)w * 256 + c0)       = accA;
    *reinterpret_cast<float4*>(out + (size_t)w * 256 + 128 + c0) = accB;
}

// ---------------- aggregate H=1 (+ fused bias/residual): one warp per node ----------------
__global__ void aggregate1_kernel(const int* __restrict__ rowptr, const int* __restrict__ eidx,
                                  const int* __restrict__ src, const float* __restrict__ alpha,
                                  const float* __restrict__ feat, const float* __restrict__ bias,
                                  const float* __restrict__ resid, float* __restrict__ out) {
    int w = blockIdx.x * (blockDim.x >> 5) + (threadIdx.x >> 5);
    if (w >= NN) return;
    int lane = threadIdx.x & 31;
    int start = rowptr[w], end = rowptr[w + 1];
    int c0 = 2 * lane;
    float2 acc = make_float2(0.f, 0.f);

    for (int i = start; i < end; i++) {
        int e = eidx[i];
        int s = src[e];
        float a = alpha[i];
        float2 f = *reinterpret_cast<const float2*>(feat + (size_t)s * 64 + c0);
        acc.x = fmaf(a, f.x, acc.x);
        acc.y = fmaf(a, f.y, acc.y);
    }
    float2 b = *reinterpret_cast<const float2*>(bias + c0);
    float2 r = *reinterpret_cast<const float2*>(resid + (size_t)w * 64 + c0);
    acc.x += b.x + r.x;
    acc.y += b.y + r.y;
    *reinterpret_cast<float2*>(out + (size_t)w * 64 + c0) = acc;
}

// ---------------- host ----------------
extern "C" void kernel_launch(void* const* d_in, const int* in_sizes, int n_in,
                              void* d_out, int out_size) {
    const float* x    = (const float*)d_in[0];
    const int*   src  = (const int*)d_in[1];
    const int*   dst  = (const int*)d_in[2];
    const float* W0   = (const float*)d_in[3];
    const float* al0  = (const float*)d_in[4];
    const float* ar0  = (const float*)d_in[5];
    const float* b0   = (const float*)d_in[6];
    const float* W1   = (const float*)d_in[7];
    const float* al1  = (const float*)d_in[8];
    const float* ar1  = (const float*)d_in[9];
    const float* b1   = (const float*)d_in[10];
    const float* W2   = (const float*)d_in[11];
    const float* al2  = (const float*)d_in[12];
    const float* ar2  = (const float*)d_in[13];
    const float* b2   = (const float*)d_in[14];
    const float* rw2  = (const float*)d_in[15];
    float* out = (float*)d_out;

    float *feat, *h1, *h2, *res2, *el, *er, *alpha;
    int *rowptr, *cursor, *eidx;
    cudaGetSymbolAddress((void**)&feat,   g_feat);
    cudaGetSymbolAddress((void**)&h1,     g_h1);
    cudaGetSymbolAddress((void**)&h2,     g_h2);
    cudaGetSymbolAddress((void**)&res2,   g_res2);
    cudaGetSymbolAddress((void**)&el,     g_el);
    cudaGetSymbolAddress((void**)&er,     g_er);
    cudaGetSymbolAddress((void**)&alpha,  g_alpha);
    cudaGetSymbolAddress((void**)&rowptr, g_rowptr);
    cudaGetSymbolAddress((void**)&cursor, g_cursor);
    cudaGetSymbolAddress((void**)&eidx,   g_eidx);

    const int MTILES = (NN + 63) / 64;          // 782
    const int NODE_WARP_BLOCKS = (NN + 7) / 8;  // 6250

    // ---------- CSR build (dst shared by all layers) ----------
    zero_deg_kernel<<<(NN + 255) / 256, 256>>>(cursor);
    hist_kernel<<<(NE + 255) / 256, 256>>>(dst, cursor);
    scan_kernel<<<1, 1024>>>(cursor, rowptr);
    scatter_kernel<<<(NE + 255) / 256, 256>>>(dst, cursor, eidx);

    // ================= layer 0: x -> h1, H=4, no residual, ELU =================
    sgemm_tf32_kernel<<<dim3(4, MTILES), 256>>>(x, W0, feat, NN, 256);
    elr_kernel<4><<<(NN * 4 + 3) / 4, 128>>>(feat, al0, ar0, el, er);
    softmax_kernel<4, 2><<<NODE_WARP_BLOCKS, 256>>>(rowptr, eidx, src, el, er, alpha);
    aggregate4_kernel<1, 0><<<NODE_WARP_BLOCKS, 256>>>(rowptr, eidx, src, alpha, feat, b0, nullptr, h1);

    // ================= layer 1: h1 -> h2, H=4, identity residual, ELU =================
    sgemm_tf32_kernel<<<dim3(4, MTILES), 256>>>(h1, W1, feat, NN, 256);
    elr_kernel<4><<<(NN * 4 + 3) / 4, 128>>>(feat, al1, ar1, el, er);
    softmax_kernel<4, 2><<<NODE_WARP_BLOCKS, 256>>>(rowptr, eidx, src, el, er, alpha);
    aggregate4_kernel<1, 1><<<NODE_WARP_BLOCKS, 256>>>(rowptr, eidx, src, alpha, feat, b1, h1, h2);

    // ================= layer 2: h2 -> out, H=1, linear residual, no act =================
    sgemm_tf32_kernel<<<dim3(1, MTILES), 256>>>(h2, W2, feat, NN, 64);
    sgemm_tf32_kernel<<<dim3(1, MTILES), 256>>>(h2, rw2, res2, NN, 64);
    elr_kernel<1><<<(NN + 3) / 4, 128>>>(feat, al2, ar2, el, er);
    softmax_kernel<1, 0><<<NODE_WARP_BLOCKS, 256>>>(rowptr, eidx, src, el, er, alpha);
    aggregate1_kernel<<<NODE_WARP_BLOCKS, 256>>>(rowptr, eidx, src, alpha, feat, b2, res2, out);
}

// round 7
// speedup vs baseline: 2.9494x; 1.0307x over previous
#include <cuda_runtime.h>
#include <math_constants.h>

#define NN 50000
#define NE 800000

// ---------------- scratch (static device globals; no allocation) ----------------
__device__ float g_feat[NN * 256];
__device__ float g_h1[NN * 256];
__device__ float g_h2[NN * 256];
__device__ float g_res2[NN * 64];
__device__ float g_el[NN * 4];
__device__ float g_er[NN * 4];
__device__ int   g_rowptr[NN + 1];
__device__ int   g_cursor[NN];
__device__ int   g_eidx[NE];

__device__ __forceinline__ unsigned f2tf(float f) {
    unsigned u;
    asm("cvt.rna.tf32.f32 %0, %1;" : "=r"(u) : "f"(f));
    return u;
}

// ---------------- TF32 tensor-core GEMM: C[M,N] = A[M,256] @ B[256,N] ----------------
// BM=64, BN=64, BK=32; 8 warps (2m x 4n), warp tile 32x16.
// Double-buffered SMEM + register-staged global prefetch: 1 sync per K-step.
__device__ __forceinline__ void gemm_loadg(const float* __restrict__ A,
                                           const float* __restrict__ B,
                                           int N, int k0, int ar_g, bool avalid,
                                           int acol4, int tid, int col0,
                                           float4 ra[2], float4 rb[2]) {
    const int K = 256;
#pragma unroll
    for (int j = 0; j < 2; j++) {
        ra[j] = avalid
            ? *reinterpret_cast<const float4*>(A + (size_t)ar_g * K + k0 + acol4 + j * 16)
            : make_float4(0.f, 0.f, 0.f, 0.f);
    }
#pragma unroll
    for (int j = 0; j < 2; j++) {
        int idx  = tid + j * 256;
        int krow = idx >> 4;
        int ncol = (idx & 15) << 2;
        rb[j] = *reinterpret_cast<const float4*>(B + (size_t)(k0 + krow) * N + col0 + ncol);
    }
}

__device__ __forceinline__ void gemm_stores(unsigned* __restrict__ As,
                                            unsigned* __restrict__ Bs,
                                            int arow, int acol4, int tid,
                                            const float4 ra[2], const float4 rb[2]) {
#pragma unroll
    for (int j = 0; j < 2; j++) {
        int kk = acol4 + j * 16;
        As[(kk + 0) * 72 + arow] = f2tf(ra[j].x);
        As[(kk + 1) * 72 + arow] = f2tf(ra[j].y);
        As[(kk + 2) * 72 + arow] = f2tf(ra[j].z);
        As[(kk + 3) * 72 + arow] = f2tf(ra[j].w);
    }
#pragma unroll
    for (int j = 0; j < 2; j++) {
        int idx  = tid + j * 256;
        int krow = idx >> 4;
        int ncol = (idx & 15) << 2;
        uint4 u = make_uint4(f2tf(rb[j].x), f2tf(rb[j].y), f2tf(rb[j].z), f2tf(rb[j].w));
        *reinterpret_cast<uint4*>(&Bs[krow * 72 + ncol]) = u;
    }
}

__global__ void __launch_bounds__(256) sgemm_tf32_kernel(
        const float* __restrict__ A, const float* __restrict__ B,
        float* __restrict__ C, int M, int N) {
    const int K = 256;
    __shared__ unsigned As[2][32 * 72];
    __shared__ unsigned Bs[2][32 * 72];

    int tid  = threadIdx.x;
    int wid  = tid >> 5;
    int lane = tid & 31;
    int row0 = blockIdx.y * 64, col0 = blockIdx.x * 64;

    int wm = (wid & 1) * 32;
    int wn = (wid >> 1) * 16;

    int arow   = tid >> 2;
    int acol4  = (tid & 3) << 2;
    int ar_g   = row0 + arow;
    bool avalid = (ar_g < M);

    float acc[2][2][4];
#pragma unroll
    for (int i = 0; i < 2; i++)
#pragma unroll
        for (int j = 0; j < 2; j++)
#pragma unroll
            for (int v = 0; v < 4; v++) acc[i][j][v] = 0.f;

    int fr = lane >> 2;
    int fc = lane & 3;

    float4 ra[2], rb[2];
    gemm_loadg(A, B, N, 0, ar_g, avalid, acol4, tid, col0, ra, rb);
    gemm_stores(As[0], Bs[0], arow, acol4, tid, ra, rb);
    __syncthreads();

    int buf = 0;
    for (int k0 = 0; k0 < K; k0 += 32) {
        bool has_next = (k0 + 32 < K);
        if (has_next)
            gemm_loadg(A, B, N, k0 + 32, ar_g, avalid, acol4, tid, col0, ra, rb);

        const unsigned* Ab = As[buf];
        const unsigned* Bb = Bs[buf];
#pragma unroll
        for (int kt = 0; kt < 4; kt++) {
            int kb = kt * 8;
            unsigned a[2][4], b[2][2];
#pragma unroll
            for (int mt = 0; mt < 2; mt++) {
                int r = wm + mt * 16 + fr;
                a[mt][0] = Ab[(kb + fc) * 72 + r];
                a[mt][1] = Ab[(kb + fc) * 72 + r + 8];
                a[mt][2] = Ab[(kb + fc + 4) * 72 + r];
                a[mt][3] = Ab[(kb + fc + 4) * 72 + r + 8];
            }
#pragma unroll
            for (int nt = 0; nt < 2; nt++) {
                int c = wn + nt * 8 + fr;
                b[nt][0] = Bb[(kb + fc) * 72 + c];
                b[nt][1] = Bb[(kb + fc + 4) * 72 + c];
            }
#pragma unroll
            for (int mt = 0; mt < 2; mt++)
#pragma unroll
                for (int nt = 0; nt < 2; nt++) {
                    asm volatile(
                        "mma.sync.aligned.m16n8k8.row.col.f32.tf32.tf32.f32 "
                        "{%0,%1,%2,%3}, {%4,%5,%6,%7}, {%8,%9}, {%0,%1,%2,%3};\n"
                        : "+f"(acc[mt][nt][0]), "+f"(acc[mt][nt][1]),
                          "+f"(acc[mt][nt][2]), "+f"(acc[mt][nt][3])
                        : "r"(a[mt][0]), "r"(a[mt][1]), "r"(a[mt][2]), "r"(a[mt][3]),
                          "r"(b[nt][0]), "r"(b[nt][1]));
                }
        }

        if (has_next) {
            gemm_stores(As[buf ^ 1], Bs[buf ^ 1], arow, acol4, tid, ra, rb);
            __syncthreads();
            buf ^= 1;
        }
    }

#pragma unroll
    for (int mt = 0; mt < 2; mt++) {
#pragma unroll
        for (int nt = 0; nt < 2; nt++) {
            int crow = row0 + wm + mt * 16 + fr;
            int ccol = col0 + wn + nt * 8 + 2 * fc;
            if (crow < M)
                *reinterpret_cast<float2*>(C + (size_t)crow * N + ccol) =
                    make_float2(acc[mt][nt][0], acc[mt][nt][1]);
            if (crow + 8 < M)
                *reinterpret_cast<float2*>(C + (size_t)(crow + 8) * N + ccol) =
                    make_float2(acc[mt][nt][2], acc[mt][nt][3]);
        }
    }
}

// ---------------- el/er: one warp per (node, head) ----------------
template <int H>
__global__ void elr_kernel(const float* __restrict__ feat, const float* __restrict__ al,
                           const float* __restrict__ ar, float* __restrict__ el,
                           float* __restrict__ er) {
    int wid  = blockIdx.x * (blockDim.x >> 5) + (threadIdx.x >> 5);
    int lane = threadIdx.x & 31;
    if (wid >= NN * H) return;
    int node = wid / H, head = wid % H;
    const float* f  = feat + (size_t)node * (H * 64) + head * 64;
    const float* pl = al + head * 64;
    const float* pr = ar + head * 64;
    float f0 = f[lane], f1 = f[lane + 32];
    float sl = f0 * pl[lane] + f1 * pl[lane + 32];
    float sr = f0 * pr[lane] + f1 * pr[lane + 32];
#pragma unroll
    for (int o = 16; o; o >>= 1) {
        sl += __shfl_xor_sync(0xffffffffu, sl, o);
        sr += __shfl_xor_sync(0xffffffffu, sr, o);
    }
    if (lane == 0) { el[wid] = sl; er[wid] = sr; }
}

// ---------------- CSR build ----------------
__global__ void zero_deg_kernel(int* __restrict__ deg) {
    int i = blockIdx.x * blockDim.x + threadIdx.x;
    if (i < NN) deg[i] = 0;
}

__global__ void hist_kernel(const int* __restrict__ dst, int* __restrict__ deg) {
    int e = blockIdx.x * blockDim.x + threadIdx.x;
    if (e < NE) atomicAdd(&deg[dst[e]], 1);
}

__global__ void scan_kernel(int* __restrict__ deg_cursor, int* __restrict__ rowptr) {
    __shared__ int warp_sums[32];
    __shared__ int s_carry;
    int tid = threadIdx.x;  // 1024 threads
    if (tid == 0) s_carry = 0;
    __syncthreads();
    for (int base = 0; base < NN; base += 1024) {
        int i = base + tid;
        int v = (i < NN) ? deg_cursor[i] : 0;
        int x = v;
#pragma unroll
        for (int o = 1; o < 32; o <<= 1) {
            int y = __shfl_up_sync(0xffffffffu, x, o);
            if ((tid & 31) >= o) x += y;
        }
        if ((tid & 31) == 31) warp_sums[tid >> 5] = x;
        __syncthreads();
        if (tid < 32) {
            int s = warp_sums[tid];
#pragma unroll
            for (int o = 1; o < 32; o <<= 1) {
                int y = __shfl_up_sync(0xffffffffu, s, o);
                if (tid >= o) s += y;
            }
            warp_sums[tid] = s;
        }
        __syncthreads();
        int excl = x - v + ((tid >= 32) ? warp_sums[(tid >> 5) - 1] : 0);
        int val  = s_carry + excl;
        if (i < NN) { rowptr[i] = val; deg_cursor[i] = val; }
        int chunk_total = warp_sums[31];
        __syncthreads();
        if (tid == 0) s_carry += chunk_total;
        __syncthreads();
    }
    if (tid == 0) rowptr[NN] = NE;
}

__global__ void scatter_kernel(const int* __restrict__ dst, int* __restrict__ cursor,
                               int* __restrict__ eidx) {
    int e = blockIdx.x * blockDim.x + threadIdx.x;
    if (e < NE) {
        int p = atomicAdd(&cursor[dst[e]], 1);
        eidx[p] = e;
    }
}

// ---------------- fused softmax + aggregate, H=4: one warp per node ----------------
// Phase 1 lanes: h = lane&3, group g = lane>>2 strides edges (max, then sum).
// Phase 2 lanes: column layout; alpha recomputed inline per edge.
template <int ACT, int RES>
__global__ void gat_agg4_kernel(const int* __restrict__ rowptr, const int* __restrict__ eidx,
                                const int* __restrict__ src, const float* __restrict__ el,
                                const float* __restrict__ er, const float* __restrict__ feat,
                                const float* __restrict__ bias, const float* __restrict__ resid,
                                float* __restrict__ out) {
    int w = blockIdx.x * (blockDim.x >> 5) + (threadIdx.x >> 5);
    if (w >= NN) return;
    int lane = threadIdx.x & 31;
    int start = rowptr[w], end = rowptr[w + 1];

    int h = lane & 3;
    int g = lane >> 2;
    float erv = er[w * 4 + h];

    float m = -CUDART_INF_F;
    for (int i = start + g; i < end; i += 8) {
        int s = src[eidx[i]];
        float v = el[s * 4 + h] + erv;
        v = (v > 0.f) ? v : 0.2f * v;
        m = fmaxf(m, v);
    }
#pragma unroll
    for (int o = 4; o <= 16; o <<= 1) m = fmaxf(m, __shfl_xor_sync(0xffffffffu, m, o));

    float ssum = 0.f;
    for (int i = start + g; i < end; i += 8) {
        int s = src[eidx[i]];
        float v = el[s * 4 + h] + erv;
        v = (v > 0.f) ? v : 0.2f * v;
        ssum += __expf(v - m);
    }
#pragma unroll
    for (int o = 4; o <= 16; o <<= 1) ssum += __shfl_xor_sync(0xffffffffu, ssum, o);
    float inv = 1.f / ssum;

    // broadcast per-head stats into column layout
    int hA = lane >> 4;                 // head of first half (0/1); second half: 2+hA
    float mA = __shfl_sync(0xffffffffu, m,   hA);
    float iA = __shfl_sync(0xffffffffu, inv, hA);
    float eA = __shfl_sync(0xffffffffu, erv, hA);
    float mB = __shfl_sync(0xffffffffu, m,   2 + hA);
    float iB = __shfl_sync(0xffffffffu, inv, 2 + hA);
    float eB = __shfl_sync(0xffffffffu, erv, 2 + hA);

    int c0 = 4 * lane;
    float4 accA = make_float4(0.f, 0.f, 0.f, 0.f);
    float4 accB = make_float4(0.f, 0.f, 0.f, 0.f);

    for (int i = start; i < end; i++) {
        int e = eidx[i];
        int s = src[e];
        const float* ep = el + (size_t)s * 4;
        float vA = ep[hA] + eA;     vA = (vA > 0.f) ? vA : 0.2f * vA;
        float vB = ep[2 + hA] + eB; vB = (vB > 0.f) ? vB : 0.2f * vB;
        float aA = __expf(vA - mA) * iA;
        float aB = __expf(vB - mB) * iB;
        const float* fp = feat + (size_t)s * 256;
        float4 f0 = *reinterpret_cast<const float4*>(fp + c0);
        float4 f1 = *reinterpret_cast<const float4*>(fp + 128 + c0);
        accA.x = fmaf(aA, f0.x, accA.x); accA.y = fmaf(aA, f0.y, accA.y);
        accA.z = fmaf(aA, f0.z, accA.z); accA.w = fmaf(aA, f0.w, accA.w);
        accB.x = fmaf(aB, f1.x, accB.x); accB.y = fmaf(aB, f1.y, accB.y);
        accB.z = fmaf(aB, f1.z, accB.z); accB.w = fmaf(aB, f1.w, accB.w);
    }

    float4 bA = *reinterpret_cast<const float4*>(bias + c0);
    float4 bB = *reinterpret_cast<const float4*>(bias + 128 + c0);
    accA.x += bA.x; accA.y += bA.y; accA.z += bA.z; accA.w += bA.w;
    accB.x += bB.x; accB.y += bB.y; accB.z += bB.z; accB.w += bB.w;
    if (RES) {
        float4 rA = *reinterpret_cast<const float4*>(resid + (size_t)w * 256 + c0);
        float4 rB = *reinterpret_cast<const float4*>(resid + (size_t)w * 256 + 128 + c0);
        accA.x += rA.x; accA.y += rA.y; accA.z += rA.z; accA.w += rA.w;
        accB.x += rB.x; accB.y += rB.y; accB.z += rB.z; accB.w += rB.w;
    }
    if (ACT) {
        accA.x = (accA.x > 0.f) ? accA.x : expm1f(accA.x);
        accA.y = (accA.y > 0.f) ? accA.y : expm1f(accA.y);
        accA.z = (accA.z > 0.f) ? accA.z : expm1f(accA.z);
        accA.w = (accA.w > 0.f) ? accA.w : expm1f(accA.w);
        accB.x = (accB.x > 0.f) ? accB.x : expm1f(accB.x);
        accB.y = (accB.y > 0.f) ? accB.y : expm1f(accB.y);
        accB.z = (accB.z > 0.f) ? accB.z : expm1f(accB.z);
        accB.w = (accB.w > 0.f) ? accB.w : expm1f(accB.w);
    }
    *reinterpret_cast<float4*>(out + (size_t)w * 256 + c0)       = accA;
    *reinterpret_cast<float4*>(out + (size_t)w * 256 + 128 + c0) = accB;
}

// ---------------- fused softmax + aggregate, H=1: one warp per node ----------------
__global__ void gat_agg1_kernel(const int* __restrict__ rowptr, const int* __restrict__ eidx,
                                const int* __restrict__ src, const float* __restrict__ el,
                                const float* __restrict__ er, const float* __restrict__ feat,
                                const float* __restrict__ bias, const float* __restrict__ resid,
                                float* __restrict__ out) {
    int w = blockIdx.x * (blockDim.x >> 5) + (threadIdx.x >> 5);
    if (w >= NN) return;
    int lane = threadIdx.x & 31;
    int start = rowptr[w], end = rowptr[w + 1];
    float erv = er[w];

    float m = -CUDART_INF_F;
    for (int i = start + lane; i < end; i += 32) {
        int s = src[eidx[i]];
        float v = el[s] + erv;
        v = (v > 0.f) ? v : 0.2f * v;
        m = fmaxf(m, v);
    }
#pragma unroll
    for (int o = 1; o <= 16; o <<= 1) m = fmaxf(m, __shfl_xor_sync(0xffffffffu, m, o));

    float ssum = 0.f;
    for (int i = start + lane; i < end; i += 32) {
        int s = src[eidx[i]];
        float v = el[s] + erv;
        v = (v > 0.f) ? v : 0.2f * v;
        ssum += __expf(v - m);
    }
#pragma unroll
    for (int o = 1; o <= 16; o <<= 1) ssum += __shfl_xor_sync(0xffffffffu, ssum, o);
    float inv = 1.f / ssum;

    int c0 = 2 * lane;
    float2 acc = make_float2(0.f, 0.f);
    for (int i = start; i < end; i++) {
        int e = eidx[i];
        int s = src[e];
        float v = el[s] + erv;
        v = (v > 0.f) ? v : 0.2f * v;
        float a = __expf(v - m) * inv;
        float2 f = *reinterpret_cast<const float2*>(feat + (size_t)s * 64 + c0);
        acc.x = fmaf(a, f.x, acc.x);
        acc.y = fmaf(a, f.y, acc.y);
    }
    float2 b = *reinterpret_cast<const float2*>(bias + c0);
    float2 r = *reinterpret_cast<const float2*>(resid + (size_t)w * 64 + c0);
    acc.x += b.x + r.x;
    acc.y += b.y + r.y;
    *reinterpret_cast<float2*>(out + (size_t)w * 64 + c0) = acc;
}

// ---------------- host ----------------
extern "C" void kernel_launch(void* const* d_in, const int* in_sizes, int n_in,
                              void* d_out, int out_size) {
    const float* x    = (const float*)d_in[0];
    const int*   src  = (const int*)d_in[1];
    const int*   dst  = (const int*)d_in[2];
    const float* W0   = (const float*)d_in[3];
    const float* al0  = (const float*)d_in[4];
    const float* ar0  = (const float*)d_in[5];
    const float* b0   = (const float*)d_in[6];
    const float* W1   = (const float*)d_in[7];
    const float* al1  = (const float*)d_in[8];
    const float* ar1  = (const float*)d_in[9];
    const float* b1   = (const float*)d_in[10];
    const float* W2   = (const float*)d_in[11];
    const float* al2  = (const float*)d_in[12];
    const float* ar2  = (const float*)d_in[13];
    const float* b2   = (const float*)d_in[14];
    const float* rw2  = (const float*)d_in[15];
    float* out = (float*)d_out;

    float *feat, *h1, *h2, *res2, *el, *er;
    int *rowptr, *cursor, *eidx;
    cudaGetSymbolAddress((void**)&feat,   g_feat);
    cudaGetSymbolAddress((void**)&h1,     g_h1);
    cudaGetSymbolAddress((void**)&h2,     g_h2);
    cudaGetSymbolAddress((void**)&res2,   g_res2);
    cudaGetSymbolAddress((void**)&el,     g_el);
    cudaGetSymbolAddress((void**)&er,     g_er);
    cudaGetSymbolAddress((void**)&rowptr, g_rowptr);
    cudaGetSymbolAddress((void**)&cursor, g_cursor);
    cudaGetSymbolAddress((void**)&eidx,   g_eidx);

    const int MTILES = (NN + 63) / 64;          // 782
    const int NODE_WARP_BLOCKS = (NN + 7) / 8;  // 6250

    // ---------- CSR build (dst shared by all layers) ----------
    zero_deg_kernel<<<(NN + 255) / 256, 256>>>(cursor);
    hist_kernel<<<(NE + 255) / 256, 256>>>(dst, cursor);
    scan_kernel<<<1, 1024>>>(cursor, rowptr);
    scatter_kernel<<<(NE + 255) / 256, 256>>>(dst, cursor, eidx);

    // ================= layer 0: x -> h1, H=4, no residual, ELU =================
    sgemm_tf32_kernel<<<dim3(4, MTILES), 256>>>(x, W0, feat, NN, 256);
    elr_kernel<4><<<(NN * 4 + 3) / 4, 128>>>(feat, al0, ar0, el, er);
    gat_agg4_kernel<1, 0><<<NODE_WARP_BLOCKS, 256>>>(rowptr, eidx, src, el, er, feat, b0, nullptr, h1);

    // ================= layer 1: h1 -> h2, H=4, identity residual, ELU =================
    sgemm_tf32_kernel<<<dim3(4, MTILES), 256>>>(h1, W1, feat, NN, 256);
    elr_kernel<4><<<(NN * 4 + 3) / 4, 128>>>(feat, al1, ar1, el, er);
    gat_agg4_kernel<1, 1><<<NODE_WARP_BLOCKS, 256>>>(rowptr, eidx, src, el, er, feat, b1, h1, h2);

    // ================= layer 2: h2 -> out, H=1, linear residual, no act =================
    sgemm_tf32_kernel<<<dim3(1, MTILES), 256>>>(h2, W2, feat, NN, 64);
    sgemm_tf32_kernel<<<dim3(1, MTILES), 256>>>(h2, rw2, res2, NN, 64);
    elr_kernel<1><<<(NN + 3) / 4, 128>>>(feat, al2, ar2, el, er);
    gat_agg1_kernel<<<NODE_WARP_BLOCKS, 256>>>(rowptr, eidx, src, el, er, feat, b2, res2, out);
}

// round 9
// speedup vs baseline: 3.1340x; 1.0626x over previous
#include <cuda_runtime.h>
#include <math_constants.h>

#define NN 50000
#define NE 800000

// ---------------- scratch (static device globals; no allocation) ----------------
__device__ float g_feat[NN * 256];
__device__ float g_h1[NN * 256];
__device__ float g_h2[NN * 256];
__device__ float g_res2[NN * 64];
__device__ float g_el[NN * 4];
__device__ float g_er[NN * 4];
__device__ int   g_rowptr[NN + 1];
__device__ int   g_cursor[NN];
__device__ int   g_eidx[NE];

__device__ __forceinline__ unsigned f2tf(float f) {
    unsigned u;
    asm("cvt.rna.tf32.f32 %0, %1;" : "=r"(u) : "f"(f));
    return u;
}

// ---------------- TF32 tensor-core GEMM core ----------------
// BM=128, BN=64, BK=16, K=256. 256 threads = 8 warps (4m x 2n), warp tile 32x32.
// As[k][m] stride 136 (8 mod 32 -> conflict-free frag loads), Bs[k][n] stride 72.
#define AS_STRIDE 136
#define BS_STRIDE 72

__device__ __forceinline__ void gemm_body(const float* __restrict__ A,
                                          const float* __restrict__ B,
                                          float* __restrict__ C,
                                          int M, int N, int row0, int col0) {
    const int K = 256;
    __shared__ unsigned As[2][16 * AS_STRIDE];
    __shared__ unsigned Bs[2][16 * BS_STRIDE];

    int tid  = threadIdx.x;
    int wid  = tid >> 5;
    int lane = tid & 31;

    int wm = (wid & 3) * 32;
    int wn = (wid >> 2) * 32;

    // A loader: row = tid>>1 (128 rows), 2 float4 along k (fq = (tid&1)*2 + i)
    int arow  = tid >> 1;
    int afqb  = (tid & 1) * 2;
    int ar_g  = row0 + arow;
    bool avalid = (ar_g < M);

    // B loader: krow = tid>>4 (16 rows), ncol = (tid&15)*4
    int bkrow = tid >> 4;
    int bncol = (tid & 15) << 2;

    float acc[2][4][4];
#pragma unroll
    for (int i = 0; i < 2; i++)
#pragma unroll
        for (int j = 0; j < 4; j++)
#pragma unroll
            for (int v = 0; v < 4; v++) acc[i][j][v] = 0.f;

    int fr = lane >> 2;
    int fc = lane & 3;

    float4 ra[2], rb;
    // prologue load chunk 0
#pragma unroll
    for (int i = 0; i < 2; i++)
        ra[i] = avalid
            ? *reinterpret_cast<const float4*>(A + (size_t)ar_g * K + (afqb + i) * 4)
            : make_float4(0.f, 0.f, 0.f, 0.f);
    rb = *reinterpret_cast<const float4*>(B + (size_t)bkrow * N + col0 + bncol);

    // store chunk 0
#pragma unroll
    for (int i = 0; i < 2; i++) {
        int k = (afqb + i) * 4;
        As[0][(k + 0) * AS_STRIDE + arow] = f2tf(ra[i].x);
        As[0][(k + 1) * AS_STRIDE + arow] = f2tf(ra[i].y);
        As[0][(k + 2) * AS_STRIDE + arow] = f2tf(ra[i].z);
        As[0][(k + 3) * AS_STRIDE + arow] = f2tf(ra[i].w);
    }
    {
        uint4 u = make_uint4(f2tf(rb.x), f2tf(rb.y), f2tf(rb.z), f2tf(rb.w));
        *reinterpret_cast<uint4*>(&Bs[0][bkrow * BS_STRIDE + bncol]) = u;
    }
    __syncthreads();

    int buf = 0;
    for (int k0 = 0; k0 < K; k0 += 16) {
        bool has_next = (k0 + 16 < K);
        if (has_next) {
#pragma unroll
            for (int i = 0; i < 2; i++)
                ra[i] = avalid
                    ? *reinterpret_cast<const float4*>(
                          A + (size_t)ar_g * K + k0 + 16 + (afqb + i) * 4)
                    : make_float4(0.f, 0.f, 0.f, 0.f);
            rb = *reinterpret_cast<const float4*>(
                B + (size_t)(k0 + 16 + bkrow) * N + col0 + bncol);
        }

        const unsigned* Ab = As[buf];
        const unsigned* Bb = Bs[buf];
#pragma unroll
        for (int kt = 0; kt < 2; kt++) {
            int kb = kt * 8;
            unsigned a[2][4], b[4][2];
#pragma unroll
            for (int mt = 0; mt < 2; mt++) {
                int r = wm + mt * 16 + fr;
                a[mt][0] = Ab[(kb + fc) * AS_STRIDE + r];
                a[mt][1] = Ab[(kb + fc) * AS_STRIDE + r + 8];
                a[mt][2] = Ab[(kb + fc + 4) * AS_STRIDE + r];
                a[mt][3] = Ab[(kb + fc + 4) * AS_STRIDE + r + 8];
            }
#pragma unroll
            for (int nt = 0; nt < 4; nt++) {
                int c = wn + nt * 8 + fr;
                b[nt][0] = Bb[(kb + fc) * BS_STRIDE + c];
                b[nt][1] = Bb[(kb + fc + 4) * BS_STRIDE + c];
            }
#pragma unroll
            for (int mt = 0; mt < 2; mt++)
#pragma unroll
                for (int nt = 0; nt < 4; nt++) {
                    asm volatile(
                        "mma.sync.aligned.m16n8k8.row.col.f32.tf32.tf32.f32 "
                        "{%0,%1,%2,%3}, {%4,%5,%6,%7}, {%8,%9}, {%0,%1,%2,%3};\n"
                        : "+f"(acc[mt][nt][0]), "+f"(acc[mt][nt][1]),
                          "+f"(acc[mt][nt][2]), "+f"(acc[mt][nt][3])
                        : "r"(a[mt][0]), "r"(a[mt][1]), "r"(a[mt][2]), "r"(a[mt][3]),
                          "r"(b[nt][0]), "r"(b[nt][1]));
                }
        }

        if (has_next) {
#pragma unroll
            for (int i = 0; i < 2; i++) {
                int k = (afqb + i) * 4;
                As[buf ^ 1][(k + 0) * AS_STRIDE + arow] = f2tf(ra[i].x);
                As[buf ^ 1][(k + 1) * AS_STRIDE + arow] = f2tf(ra[i].y);
                As[buf ^ 1][(k + 2) * AS_STRIDE + arow] = f2tf(ra[i].z);
                As[buf ^ 1][(k + 3) * AS_STRIDE + arow] = f2tf(ra[i].w);
            }
            uint4 u = make_uint4(f2tf(rb.x), f2tf(rb.y), f2tf(rb.z), f2tf(rb.w));
            *reinterpret_cast<uint4*>(&Bs[buf ^ 1][bkrow * BS_STRIDE + bncol]) = u;
            __syncthreads();
            buf ^= 1;
        }
    }

#pragma unroll
    for (int mt = 0; mt < 2; mt++) {
#pragma unroll
        for (int nt = 0; nt < 4; nt++) {
            int crow = row0 + wm + mt * 16 + fr;
            int ccol = col0 + wn + nt * 8 + 2 * fc;
            if (crow < M)
                *reinterpret_cast<float2*>(C + (size_t)crow * N + ccol) =
                    make_float2(acc[mt][nt][0], acc[mt][nt][1]);
            if (crow + 8 < M)
                *reinterpret_cast<float2*>(C + (size_t)(crow + 8) * N + ccol) =
                    make_float2(acc[mt][nt][2], acc[mt][nt][3]);
        }
    }
}

__global__ void __launch_bounds__(256) sgemm_tf32_kernel(
        const float* __restrict__ A, const float* __restrict__ B,
        float* __restrict__ C, int M, int N) {
    gemm_body(A, B, C, M, N, blockIdx.y * 128, blockIdx.x * 64);
}

// layer-2 dual GEMM: same A, two B/C pairs (N=64), blockIdx.x selects.
__global__ void __launch_bounds__(256) sgemm_tf32_dual_kernel(
        const float* __restrict__ A, const float* __restrict__ B0,
        const float* __restrict__ B1, float* __restrict__ C0,
        float* __restrict__ C1, int M) {
    const float* B = blockIdx.x ? B1 : B0;
    float*       C = blockIdx.x ? C1 : C0;
    gemm_body(A, B, C, M, 64, blockIdx.y * 128, 0);
}

// ---------------- el/er: one warp per (node, head) ----------------
template <int H>
__global__ void elr_kernel(const float* __restrict__ feat, const float* __restrict__ al,
                           const float* __restrict__ ar, float* __restrict__ el,
                           float* __restrict__ er) {
    int wid  = blockIdx.x * (blockDim.x >> 5) + (threadIdx.x >> 5);
    int lane = threadIdx.x & 31;
    if (wid >= NN * H) return;
    int node = wid / H, head = wid % H;
    const float* f  = feat + (size_t)node * (H * 64) + head * 64;
    const float* pl = al + head * 64;
    const float* pr = ar + head * 64;
    float f0 = f[lane], f1 = f[lane + 32];
    float sl = f0 * pl[lane] + f1 * pl[lane + 32];
    float sr = f0 * pr[lane] + f1 * pr[lane + 32];
#pragma unroll
    for (int o = 16; o; o >>= 1) {
        sl += __shfl_xor_sync(0xffffffffu, sl, o);
        sr += __shfl_xor_sync(0xffffffffu, sr, o);
    }
    if (lane == 0) { el[wid] = sl; er[wid] = sr; }
}

// ---------------- CSR build ----------------
__global__ void zero_deg_kernel(int* __restrict__ deg) {
    int i = blockIdx.x * blockDim.x + threadIdx.x;
    if (i < NN) deg[i] = 0;
}

__global__ void hist_kernel(const int* __restrict__ dst, int* __restrict__ deg) {
    int e = blockIdx.x * blockDim.x + threadIdx.x;
    if (e < NE) atomicAdd(&deg[dst[e]], 1);
}

__global__ void scan_kernel(int* __restrict__ deg_cursor, int* __restrict__ rowptr) {
    __shared__ int warp_sums[32];
    __shared__ int s_carry;
    int tid = threadIdx.x;  // 1024 threads
    if (tid == 0) s_carry = 0;
    __syncthreads();
    for (int base = 0; base < NN; base += 1024) {
        int i = base + tid;
        int v = (i < NN) ? deg_cursor[i] : 0;
        int x = v;
#pragma unroll
        for (int o = 1; o < 32; o <<= 1) {
            int y = __shfl_up_sync(0xffffffffu, x, o);
            if ((tid & 31) >= o) x += y;
        }
        if ((tid & 31) == 31) warp_sums[tid >> 5] = x;
        __syncthreads();
        if (tid < 32) {
            int s = warp_sums[tid];
#pragma unroll
            for (int o = 1; o < 32; o <<= 1) {
                int y = __shfl_up_sync(0xffffffffu, s, o);
                if (tid >= o) s += y;
            }
            warp_sums[tid] = s;
        }
        __syncthreads();
        int excl = x - v + ((tid >= 32) ? warp_sums[(tid >> 5) - 1] : 0);
        int val  = s_carry + excl;
        if (i < NN) { rowptr[i] = val; deg_cursor[i] = val; }
        int chunk_total = warp_sums[31];
        __syncthreads();
        if (tid == 0) s_carry += chunk_total;
        __syncthreads();
    }
    if (tid == 0) rowptr[NN] = NE;
}

__global__ void scatter_kernel(const int* __restrict__ dst, int* __restrict__ cursor,
                               int* __restrict__ eidx) {
    int e = blockIdx.x * blockDim.x + threadIdx.x;
    if (e < NE) {
        int p = atomicAdd(&cursor[dst[e]], 1);
        eidx[p] = e;
    }
}

// ---------------- fused softmax + aggregate, H=4: one warp per node ----------------
template <int ACT, int RES>
__global__ void gat_agg4_kernel(const int* __restrict__ rowptr, const int* __restrict__ eidx,
                                const int* __restrict__ src, const float* __restrict__ el,
                                const float* __restrict__ er, const float* __restrict__ feat,
                                const float* __restrict__ bias, const float* __restrict__ resid,
                                float* __restrict__ out) {
    int w = blockIdx.x * (blockDim.x >> 5) + (threadIdx.x >> 5);
    if (w >= NN) return;
    int lane = threadIdx.x & 31;
    int start = rowptr[w], end = rowptr[w + 1];

    int h = lane & 3;
    int g = lane >> 2;
    float erv = er[w * 4 + h];

    float m = -CUDART_INF_F;
    for (int i = start + g; i < end; i += 8) {
        int s = src[eidx[i]];
        float v = el[s * 4 + h] + erv;
        v = (v > 0.f) ? v : 0.2f * v;
        m = fmaxf(m, v);
    }
#pragma unroll
    for (int o = 4; o <= 16; o <<= 1) m = fmaxf(m, __shfl_xor_sync(0xffffffffu, m, o));

    float ssum = 0.f;
    for (int i = start + g; i < end; i += 8) {
        int s = src[eidx[i]];
        float v = el[s * 4 + h] + erv;
        v = (v > 0.f) ? v : 0.2f * v;
        ssum += __expf(v - m);
    }
#pragma unroll
    for (int o = 4; o <= 16; o <<= 1) ssum += __shfl_xor_sync(0xffffffffu, ssum, o);
    float inv = 1.f / ssum;

    int hA = lane >> 4;
    float mA = __shfl_sync(0xffffffffu, m,   hA);
    float iA = __shfl_sync(0xffffffffu, inv, hA);
    float eA = __shfl_sync(0xffffffffu, erv, hA);
    float mB = __shfl_sync(0xffffffffu, m,   2 + hA);
    float iB = __shfl_sync(0xffffffffu, inv, 2 + hA);
    float eB = __shfl_sync(0xffffffffu, erv, 2 + hA);

    int c0 = 4 * lane;
    float4 accA = make_float4(0.f, 0.f, 0.f, 0.f);
    float4 accB = make_float4(0.f, 0.f, 0.f, 0.f);

    for (int i = start; i < end; i++) {
        int e = eidx[i];
        int s = src[e];
        const float* ep = el + (size_t)s * 4;
        float vA = ep[hA] + eA;     vA = (vA > 0.f) ? vA : 0.2f * vA;
        float vB = ep[2 + hA] + eB; vB = (vB > 0.f) ? vB : 0.2f * vB;
        float aA = __expf(vA - mA) * iA;
        float aB = __expf(vB - mB) * iB;
        const float* fp = feat + (size_t)s * 256;
        float4 f0 = *reinterpret_cast<const float4*>(fp + c0);
        float4 f1 = *reinterpret_cast<const float4*>(fp + 128 + c0);
        accA.x = fmaf(aA, f0.x, accA.x); accA.y = fmaf(aA, f0.y, accA.y);
        accA.z = fmaf(aA, f0.z, accA.z); accA.w = fmaf(aA, f0.w, accA.w);
        accB.x = fmaf(aB, f1.x, accB.x); accB.y = fmaf(aB, f1.y, accB.y);
        accB.z = fmaf(aB, f1.z, accB.z); accB.w = fmaf(aB, f1.w, accB.w);
    }

    float4 bA = *reinterpret_cast<const float4*>(bias + c0);
    float4 bB = *reinterpret_cast<const float4*>(bias + 128 + c0);
    accA.x += bA.x; accA.y += bA.y; accA.z += bA.z; accA.w += bA.w;
    accB.x += bB.x; accB.y += bB.y; accB.z += bB.z; accB.w += bB.w;
    if (RES) {
        float4 rA = *reinterpret_cast<const float4*>(resid + (size_t)w * 256 + c0);
        float4 rB = *reinterpret_cast<const float4*>(resid + (size_t)w * 256 + 128 + c0);
        accA.x += rA.x; accA.y += rA.y; accA.z += rA.z; accA.w += rA.w;
        accB.x += rB.x; accB.y += rB.y; accB.z += rB.z; accB.w += rB.w;
    }
    if (ACT) {
        accA.x = (accA.x > 0.f) ? accA.x : expm1f(accA.x);
        accA.y = (accA.y > 0.f) ? accA.y : expm1f(accA.y);
        accA.z = (accA.z > 0.f) ? accA.z : expm1f(accA.z);
        accA.w = (accA.w > 0.f) ? accA.w : expm1f(accA.w);
        accB.x = (accB.x > 0.f) ? accB.x : expm1f(accB.x);
        accB.y = (accB.y > 0.f) ? accB.y : expm1f(accB.y);
        accB.z = (accB.z > 0.f) ? accB.z : expm1f(accB.z);
        accB.w = (accB.w > 0.f) ? accB.w : expm1f(accB.w);
    }
    *reinterpret_cast<float4*>(out + (size_t)w * 256 + c0)       = accA;
    *reinterpret_cast<float4*>(out + (size_t)w * 256 + 128 + c0) = accB;
}

// ---------------- fused softmax + aggregate, H=1: one warp per node ----------------
__global__ void gat_agg1_kernel(const int* __restrict__ rowptr, const int* __restrict__ eidx,
                                const int* __restrict__ src, const float* __restrict__ el,
                                const float* __restrict__ er, const float* __restrict__ feat,
                                const float* __restrict__ bias, const float* __restrict__ resid,
                                float* __restrict__ out) {
    int w = blockIdx.x * (blockDim.x >> 5) + (threadIdx.x >> 5);
    if (w >= NN) return;
    int lane = threadIdx.x & 31;
    int start = rowptr[w], end = rowptr[w + 1];
    float erv = er[w];

    float m = -CUDART_INF_F;
    for (int i = start + lane; i < end; i += 32) {
        int s = src[eidx[i]];
        float v = el[s] + erv;
        v = (v > 0.f) ? v : 0.2f * v;
        m = fmaxf(m, v);
    }
#pragma unroll
    for (int o = 1; o <= 16; o <<= 1) m = fmaxf(m, __shfl_xor_sync(0xffffffffu, m, o));

    float ssum = 0.f;
    for (int i = start + lane; i < end; i += 32) {
        int s = src[eidx[i]];
        float v = el[s] + erv;
        v = (v > 0.f) ? v : 0.2f * v;
        ssum += __expf(v - m);
    }
#pragma unroll
    for (int o = 1; o <= 16; o <<= 1) ssum += __shfl_xor_sync(0xffffffffu, ssum, o);
    float inv = 1.f / ssum;

    int c0 = 2 * lane;
    float2 acc = make_float2(0.f, 0.f);
    for (int i = start; i < end; i++) {
        int e = eidx[i];
        int s = src[e];
        float v = el[s] + erv;
        v = (v > 0.f) ? v : 0.2f * v;
        float a = __expf(v - m) * inv;
        float2 f = *reinterpret_cast<const float2*>(feat + (size_t)s * 64 + c0);
        acc.x = fmaf(a, f.x, acc.x);
        acc.y = fmaf(a, f.y, acc.y);
    }
    float2 b = *reinterpret_cast<const float2*>(bias + c0);
    float2 r = *reinterpret_cast<const float2*>(resid + (size_t)w * 64 + c0);
    acc.x += b.x + r.x;
    acc.y += b.y + r.y;
    *reinterpret_cast<float2*>(out + (size_t)w * 64 + c0) = acc;
}

// ---------------- host ----------------
extern "C" void kernel_launch(void* const* d_in, const int* in_sizes, int n_in,
                              void* d_out, int out_size) {
    const float* x    = (const float*)d_in[0];
    const int*   src  = (const int*)d_in[1];
    const int*   dst  = (const int*)d_in[2];
    const float* W0   = (const float*)d_in[3];
    const float* al0  = (const float*)d_in[4];
    const float* ar0  = (const float*)d_in[5];
    const float* b0   = (const float*)d_in[6];
    const float* W1   = (const float*)d_in[7];
    const float* al1  = (const float*)d_in[8];
    const float* ar1  = (const float*)d_in[9];
    const float* b1   = (const float*)d_in[10];
    const float* W2   = (const float*)d_in[11];
    const float* al2  = (const float*)d_in[12];
    const float* ar2  = (const float*)d_in[13];
    const float* b2   = (const float*)d_in[14];
    const float* rw2  = (const float*)d_in[15];
    float* out = (float*)d_out;

    float *feat, *h1, *h2, *res2, *el, *er;
    int *rowptr, *cursor, *eidx;
    cudaGetSymbolAddress((void**)&feat,   g_feat);
    cudaGetSymbolAddress((void**)&h1,     g_h1);
    cudaGetSymbolAddress((void**)&h2,     g_h2);
    cudaGetSymbolAddress((void**)&res2,   g_res2);
    cudaGetSymbolAddress((void**)&el,     g_el);
    cudaGetSymbolAddress((void**)&er,     g_er);
    cudaGetSymbolAddress((void**)&rowptr, g_rowptr);
    cudaGetSymbolAddress((void**)&cursor, g_cursor);
    cudaGetSymbolAddress((void**)&eidx,   g_eidx);

    const int MTILES = (NN + 127) / 128;        // 391
    const int NODE_WARP_BLOCKS = (NN + 7) / 8;  // 6250

    // ---------- CSR build (dst shared by all layers) ----------
    zero_deg_kernel<<<(NN + 255) / 256, 256>>>(cursor);
    hist_kernel<<<(NE + 255) / 256, 256>>>(dst, cursor);
    scan_kernel<<<1, 1024>>>(cursor, rowptr);
    scatter_kernel<<<(NE + 255) / 256, 256>>>(dst, cursor, eidx);

    // ================= layer 0: x -> h1, H=4, no residual, ELU =================
    sgemm_tf32_kernel<<<dim3(4, MTILES), 256>>>(x, W0, feat, NN, 256);
    elr_kernel<4><<<(NN * 4 + 3) / 4, 128>>>(feat, al0, ar0, el, er);
    gat_agg4_kernel<1, 0><<<NODE_WARP_BLOCKS, 256>>>(rowptr, eidx, src, el, er, feat, b0, nullptr, h1);

    // ================= layer 1: h1 -> h2, H=4, identity residual, ELU =================
    sgemm_tf32_kernel<<<dim3(4, MTILES), 256>>>(h1, W1, feat, NN, 256);
    elr_kernel<4><<<(NN * 4 + 3) / 4, 128>>>(feat, al1, ar1, el, er);
    gat_agg4_kernel<1, 1><<<NODE_WARP_BLOCKS, 256>>>(rowptr, eidx, src, el, er, feat, b1, h1, h2);

    // ================= layer 2: h2 -> out, H=1, linear residual, no act =================
    sgemm_tf32_dual_kernel<<<dim3(2, MTILES), 256>>>(h2, W2, rw2, feat, res2, NN);
    elr_kernel<1><<<(NN + 3) / 4, 128>>>(feat, al2, ar2, el, er);
    gat_agg1_kernel<<<NODE_WARP_BLOCKS, 256>>>(rowptr, eidx, src, el, er, feat, b2, res2, out);
}

// round 11
// speedup vs baseline: 3.6529x; 1.1656x over previous
#include <cuda_runtime.h>
#include <math_constants.h>

#define NN 50000
#define NE 800000

// ---------------- scratch (static device globals; no allocation) ----------------
__device__ float g_feat[NN * 256];
__device__ float g_h1[NN * 256];
__device__ float g_h2[NN * 256];
__device__ float g_res2[NN * 64];
__device__ float g_el[NN * 4];
__device__ float g_er[NN * 4];
__device__ int   g_rowptr[NN + 1];
__device__ int   g_cursor[NN];
__device__ int   g_eidx[NE];

__device__ __forceinline__ unsigned f2tf(float f) {
    unsigned u;
    asm("cvt.rna.tf32.f32 %0, %1;" : "=r"(u) : "f"(f));
    return u;
}

// ---------------- TF32 tensor-core GEMM core ----------------
// BM=128, BN=64, BK=16, K=256. 256 threads = 8 warps (4m x 2n), warp tile 32x32.
// ELR=1: epilogue additionally computes el/er = C_head . al/ar for this block's head.
#define AS_STRIDE 136
#define BS_STRIDE 72

template <int ELR>
__device__ __forceinline__ void gemm_body(const float* __restrict__ A,
                                          const float* __restrict__ B,
                                          float* __restrict__ C,
                                          int M, int N, int row0, int col0,
                                          const float* __restrict__ alh,
                                          const float* __restrict__ arh,
                                          float* __restrict__ el,
                                          float* __restrict__ er,
                                          int Hs, int head, bool do_elr) {
    const int K = 256;
    __shared__ unsigned As[2][16 * AS_STRIDE];
    __shared__ unsigned Bs[2][16 * BS_STRIDE];
    __shared__ float s_elr[128][2];

    int tid  = threadIdx.x;
    int wid  = tid >> 5;
    int lane = tid & 31;

    int wm = (wid & 3) * 32;
    int wn = (wid >> 2) * 32;

    int arow  = tid >> 1;
    int afqb  = (tid & 1) * 2;
    int ar_g  = row0 + arow;
    bool avalid = (ar_g < M);

    int bkrow = tid >> 4;
    int bncol = (tid & 15) << 2;

    float acc[2][4][4];
#pragma unroll
    for (int i = 0; i < 2; i++)
#pragma unroll
        for (int j = 0; j < 4; j++)
#pragma unroll
            for (int v = 0; v < 4; v++) acc[i][j][v] = 0.f;

    int fr = lane >> 2;
    int fc = lane & 3;

    float4 ra[2], rb;
#pragma unroll
    for (int i = 0; i < 2; i++)
        ra[i] = avalid
            ? *reinterpret_cast<const float4*>(A + (size_t)ar_g * K + (afqb + i) * 4)
            : make_float4(0.f, 0.f, 0.f, 0.f);
    rb = *reinterpret_cast<const float4*>(B + (size_t)bkrow * N + col0 + bncol);

#pragma unroll
    for (int i = 0; i < 2; i++) {
        int k = (afqb + i) * 4;
        As[0][(k + 0) * AS_STRIDE + arow] = f2tf(ra[i].x);
        As[0][(k + 1) * AS_STRIDE + arow] = f2tf(ra[i].y);
        As[0][(k + 2) * AS_STRIDE + arow] = f2tf(ra[i].z);
        As[0][(k + 3) * AS_STRIDE + arow] = f2tf(ra[i].w);
    }
    {
        uint4 u = make_uint4(f2tf(rb.x), f2tf(rb.y), f2tf(rb.z), f2tf(rb.w));
        *reinterpret_cast<uint4*>(&Bs[0][bkrow * BS_STRIDE + bncol]) = u;
    }
    __syncthreads();

    int buf = 0;
    for (int k0 = 0; k0 < K; k0 += 16) {
        bool has_next = (k0 + 16 < K);
        if (has_next) {
#pragma unroll
            for (int i = 0; i < 2; i++)
                ra[i] = avalid
                    ? *reinterpret_cast<const float4*>(
                          A + (size_t)ar_g * K + k0 + 16 + (afqb + i) * 4)
                    : make_float4(0.f, 0.f, 0.f, 0.f);
            rb = *reinterpret_cast<const float4*>(
                B + (size_t)(k0 + 16 + bkrow) * N + col0 + bncol);
        }

        const unsigned* Ab = As[buf];
        const unsigned* Bb = Bs[buf];
#pragma unroll
        for (int kt = 0; kt < 2; kt++) {
            int kb = kt * 8;
            unsigned a[2][4], b[4][2];
#pragma unroll
            for (int mt = 0; mt < 2; mt++) {
                int r = wm + mt * 16 + fr;
                a[mt][0] = Ab[(kb + fc) * AS_STRIDE + r];
                a[mt][1] = Ab[(kb + fc) * AS_STRIDE + r + 8];
                a[mt][2] = Ab[(kb + fc + 4) * AS_STRIDE + r];
                a[mt][3] = Ab[(kb + fc + 4) * AS_STRIDE + r + 8];
            }
#pragma unroll
            for (int nt = 0; nt < 4; nt++) {
                int c = wn + nt * 8 + fr;
                b[nt][0] = Bb[(kb + fc) * BS_STRIDE + c];
                b[nt][1] = Bb[(kb + fc + 4) * BS_STRIDE + c];
            }
#pragma unroll
            for (int mt = 0; mt < 2; mt++)
#pragma unroll
                for (int nt = 0; nt < 4; nt++) {
                    asm volatile(
                        "mma.sync.aligned.m16n8k8.row.col.f32.tf32.tf32.f32 "
                        "{%0,%1,%2,%3}, {%4,%5,%6,%7}, {%8,%9}, {%0,%1,%2,%3};\n"
                        : "+f"(acc[mt][nt][0]), "+f"(acc[mt][nt][1]),
                          "+f"(acc[mt][nt][2]), "+f"(acc[mt][nt][3])
                        : "r"(a[mt][0]), "r"(a[mt][1]), "r"(a[mt][2]), "r"(a[mt][3]),
                          "r"(b[nt][0]), "r"(b[nt][1]));
                }
        }

        if (has_next) {
#pragma unroll
            for (int i = 0; i < 2; i++) {
                int k = (afqb + i) * 4;
                As[buf ^ 1][(k + 0) * AS_STRIDE + arow] = f2tf(ra[i].x);
                As[buf ^ 1][(k + 1) * AS_STRIDE + arow] = f2tf(ra[i].y);
                As[buf ^ 1][(k + 2) * AS_STRIDE + arow] = f2tf(ra[i].z);
                As[buf ^ 1][(k + 3) * AS_STRIDE + arow] = f2tf(ra[i].w);
            }
            uint4 u = make_uint4(f2tf(rb.x), f2tf(rb.y), f2tf(rb.z), f2tf(rb.w));
            *reinterpret_cast<uint4*>(&Bs[buf ^ 1][bkrow * BS_STRIDE + bncol]) = u;
            __syncthreads();
            buf ^= 1;
        }
    }

    // ---- C writeback ----
#pragma unroll
    for (int mt = 0; mt < 2; mt++) {
#pragma unroll
        for (int nt = 0; nt < 4; nt++) {
            int crow = row0 + wm + mt * 16 + fr;
            int ccol = col0 + wn + nt * 8 + 2 * fc;
            if (crow < M)
                *reinterpret_cast<float2*>(C + (size_t)crow * N + ccol) =
                    make_float2(acc[mt][nt][0], acc[mt][nt][1]);
            if (crow + 8 < M)
                *reinterpret_cast<float2*>(C + (size_t)(crow + 8) * N + ccol) =
                    make_float2(acc[mt][nt][2], acc[mt][nt][3]);
        }
    }

    // ---- fused el/er epilogue: this block's 64 cols == one full head ----
    if (ELR && do_elr) {
        float sl[4] = {0.f, 0.f, 0.f, 0.f}, sr[4] = {0.f, 0.f, 0.f, 0.f};
#pragma unroll
        for (int mt = 0; mt < 2; mt++)
#pragma unroll
            for (int nt = 0; nt < 4; nt++) {
                int c = wn + nt * 8 + 2 * fc;
                float a0 = alh[c], a1 = alh[c + 1];
                float r0 = arh[c], r1 = arh[c + 1];
                sl[mt * 2 + 0] += acc[mt][nt][0] * a0 + acc[mt][nt][1] * a1;
                sr[mt * 2 + 0] += acc[mt][nt][0] * r0 + acc[mt][nt][1] * r1;
                sl[mt * 2 + 1] += acc[mt][nt][2] * a0 + acc[mt][nt][3] * a1;
                sr[mt * 2 + 1] += acc[mt][nt][2] * r0 + acc[mt][nt][3] * r1;
            }
#pragma unroll
        for (int k = 0; k < 4; k++) {
            sl[k] += __shfl_xor_sync(0xffffffffu, sl[k], 1);
            sl[k] += __shfl_xor_sync(0xffffffffu, sl[k], 2);
            sr[k] += __shfl_xor_sync(0xffffffffu, sr[k], 1);
            sr[k] += __shfl_xor_sync(0xffffffffu, sr[k], 2);
        }
        int nhalf = wid >> 2;
        int rows[4] = {wm + fr, wm + fr + 8, wm + 16 + fr, wm + 16 + fr + 8};
        if (nhalf == 0 && fc == 0) {
#pragma unroll
            for (int k = 0; k < 4; k++) {
                s_elr[rows[k]][0] = sl[k];
                s_elr[rows[k]][1] = sr[k];
            }
        }
        __syncthreads();
        if (nhalf == 1 && fc == 0) {
#pragma unroll
            for (int k = 0; k < 4; k++) {
                int r = row0 + rows[k];
                if (r < M) {
                    el[(size_t)r * Hs + head] = s_elr[rows[k]][0] + sl[k];
                    er[(size_t)r * Hs + head] = s_elr[rows[k]][1] + sr[k];
                }
            }
        }
    }
}

// H=4 GEMM with fused el/er: blockIdx.x = head (N=256).
__global__ void __launch_bounds__(256) sgemm_tf32_elr_kernel(
        const float* __restrict__ A, const float* __restrict__ B,
        float* __restrict__ C, int M,
        const float* __restrict__ al, const float* __restrict__ ar,
        float* __restrict__ el, float* __restrict__ er) {
    int head = blockIdx.x;
    gemm_body<1>(A, B, C, M, 256, blockIdx.y * 128, head * 64,
                 al + head * 64, ar + head * 64, el, er, 4, head, true);
}

// layer-2 dual GEMM: same A; x=0 -> W2 product (with el/er), x=1 -> res_w2.
__global__ void __launch_bounds__(256) sgemm_tf32_dual_kernel(
        const float* __restrict__ A, const float* __restrict__ B0,
        const float* __restrict__ B1, float* __restrict__ C0,
        float* __restrict__ C1, int M,
        const float* __restrict__ al, const float* __restrict__ ar,
        float* __restrict__ el, float* __restrict__ er) {
    const float* B = blockIdx.x ? B1 : B0;
    float*       C = blockIdx.x ? C1 : C0;
    gemm_body<1>(A, B, C, M, 64, blockIdx.y * 128, 0,
                 al, ar, el, er, 1, 0, blockIdx.x == 0);
}

// ---------------- CSR build ----------------
__global__ void zero_deg_kernel(int* __restrict__ deg) {
    int i = blockIdx.x * blockDim.x + threadIdx.x;
    if (i < NN) deg[i] = 0;
}

__global__ void hist_kernel(const int* __restrict__ dst, int* __restrict__ deg) {
    int e = blockIdx.x * blockDim.x + threadIdx.x;
    if (e < NE) atomicAdd(&deg[dst[e]], 1);
}

__global__ void scan_kernel(int* __restrict__ deg_cursor, int* __restrict__ rowptr) {
    __shared__ int warp_sums[32];
    __shared__ int s_carry;
    int tid = threadIdx.x;  // 1024 threads
    if (tid == 0) s_carry = 0;
    __syncthreads();
    for (int base = 0; base < NN; base += 1024) {
        int i = base + tid;
        int v = (i < NN) ? deg_cursor[i] : 0;
        int x = v;
#pragma unroll
        for (int o = 1; o < 32; o <<= 1) {
            int y = __shfl_up_sync(0xffffffffu, x, o);
            if ((tid & 31) >= o) x += y;
        }
        if ((tid & 31) == 31) warp_sums[tid >> 5] = x;
        __syncthreads();
        if (tid < 32) {
            int s = warp_sums[tid];
#pragma unroll
            for (int o = 1; o < 32; o <<= 1) {
                int y = __shfl_up_sync(0xffffffffu, s, o);
                if (tid >= o) s += y;
            }
            warp_sums[tid] = s;
        }
        __syncthreads();
        int excl = x - v + ((tid >= 32) ? warp_sums[(tid >> 5) - 1] : 0);
        int val  = s_carry + excl;
        if (i < NN) { rowptr[i] = val; deg_cursor[i] = val; }
        int chunk_total = warp_sums[31];
        __syncthreads();
        if (tid == 0) s_carry += chunk_total;
        __syncthreads();
    }
    if (tid == 0) rowptr[NN] = NE;
}

__global__ void scatter_kernel(const int* __restrict__ dst, int* __restrict__ cursor,
                               int* __restrict__ eidx) {
    int e = blockIdx.x * blockDim.x + threadIdx.x;
    if (e < NE) {
        int p = atomicAdd(&cursor[dst[e]], 1);
        eidx[p] = e;
    }
}

// ---------------- fused softmax + aggregate, H=4: one warp per node ----------------
// Phase 1: lane-per-edge, float4 el load covers all 4 heads; no max subtraction
// (logits are O(10), far from exp overflow; alpha ratio is exact).
template <int ACT, int RES>
__global__ void gat_agg4_kernel(const int* __restrict__ rowptr, const int* __restrict__ eidx,
                                const int* __restrict__ src, const float* __restrict__ el,
                                const float* __restrict__ er, const float* __restrict__ feat,
                                const float* __restrict__ bias, const float* __restrict__ resid,
                                float* __restrict__ out) {
    int w = blockIdx.x * (blockDim.x >> 5) + (threadIdx.x >> 5);
    if (w >= NN) return;
    int lane = threadIdx.x & 31;
    int start = rowptr[w], end = rowptr[w + 1];

    float4 er4 = *reinterpret_cast<const float4*>(er + (size_t)w * 4);

    float4 ssum = make_float4(0.f, 0.f, 0.f, 0.f);
    for (int i = start + lane; i < end; i += 32) {
        int s = src[eidx[i]];
        float4 e4 = *reinterpret_cast<const float4*>(el + (size_t)s * 4);
        float v0 = e4.x + er4.x; v0 = (v0 > 0.f) ? v0 : 0.2f * v0;
        float v1 = e4.y + er4.y; v1 = (v1 > 0.f) ? v1 : 0.2f * v1;
        float v2 = e4.z + er4.z; v2 = (v2 > 0.f) ? v2 : 0.2f * v2;
        float v3 = e4.w + er4.w; v3 = (v3 > 0.f) ? v3 : 0.2f * v3;
        ssum.x += __expf(v0);
        ssum.y += __expf(v1);
        ssum.z += __expf(v2);
        ssum.w += __expf(v3);
    }
#pragma unroll
    for (int o = 16; o; o >>= 1) {
        ssum.x += __shfl_xor_sync(0xffffffffu, ssum.x, o);
        ssum.y += __shfl_xor_sync(0xffffffffu, ssum.y, o);
        ssum.z += __shfl_xor_sync(0xffffffffu, ssum.z, o);
        ssum.w += __shfl_xor_sync(0xffffffffu, ssum.w, o);
    }

    int hA = lane >> 4;  // head of first half (0/1); second half: 2+hA
    float invA = 1.f / (hA ? ssum.y : ssum.x);
    float invB = 1.f / (hA ? ssum.w : ssum.z);
    float erA  = hA ? er4.y : er4.x;
    float erB  = hA ? er4.w : er4.z;

    int c0 = 4 * lane;
    float4 accA = make_float4(0.f, 0.f, 0.f, 0.f);
    float4 accB = make_float4(0.f, 0.f, 0.f, 0.f);

    for (int i = start; i < end; i++) {
        int e = eidx[i];
        int s = src[e];
        float4 ee = *reinterpret_cast<const float4*>(el + (size_t)s * 4);
        float vA = (hA ? ee.y : ee.x) + erA; vA = (vA > 0.f) ? vA : 0.2f * vA;
        float vB = (hA ? ee.w : ee.z) + erB; vB = (vB > 0.f) ? vB : 0.2f * vB;
        float aA = __expf(vA) * invA;
        float aB = __expf(vB) * invB;
        const float* fp = feat + (size_t)s * 256;
        float4 f0 = *reinterpret_cast<const float4*>(fp + c0);
        float4 f1 = *reinterpret_cast<const float4*>(fp + 128 + c0);
        accA.x = fmaf(aA, f0.x, accA.x); accA.y = fmaf(aA, f0.y, accA.y);
        accA.z = fmaf(aA, f0.z, accA.z); accA.w = fmaf(aA, f0.w, accA.w);
        accB.x = fmaf(aB, f1.x, accB.x); accB.y = fmaf(aB, f1.y, accB.y);
        accB.z = fmaf(aB, f1.z, accB.z); accB.w = fmaf(aB, f1.w, accB.w);
    }

    float4 bA = *reinterpret_cast<const float4*>(bias + c0);
    float4 bB = *reinterpret_cast<const float4*>(bias + 128 + c0);
    accA.x += bA.x; accA.y += bA.y; accA.z += bA.z; accA.w += bA.w;
    accB.x += bB.x; accB.y += bB.y; accB.z += bB.z; accB.w += bB.w;
    if (RES) {
        float4 rA = *reinterpret_cast<const float4*>(resid + (size_t)w * 256 + c0);
        float4 rB = *reinterpret_cast<const float4*>(resid + (size_t)w * 256 + 128 + c0);
        accA.x += rA.x; accA.y += rA.y; accA.z += rA.z; accA.w += rA.w;
        accB.x += rB.x; accB.y += rB.y; accB.z += rB.z; accB.w += rB.w;
    }
    if (ACT) {
        accA.x = (accA.x > 0.f) ? accA.x : expm1f(accA.x);
        accA.y = (accA.y > 0.f) ? accA.y : expm1f(accA.y);
        accA.z = (accA.z > 0.f) ? accA.z : expm1f(accA.z);
        accA.w = (accA.w > 0.f) ? accA.w : expm1f(accA.w);
        accB.x = (accB.x > 0.f) ? accB.x : expm1f(accB.x);
        accB.y = (accB.y > 0.f) ? accB.y : expm1f(accB.y);
        accB.z = (accB.z > 0.f) ? accB.z : expm1f(accB.z);
        accB.w = (accB.w > 0.f) ? accB.w : expm1f(accB.w);
    }
    *reinterpret_cast<float4*>(out + (size_t)w * 256 + c0)       = accA;
    *reinterpret_cast<float4*>(out + (size_t)w * 256 + 128 + c0) = accB;
}

// ---------------- fused softmax + aggregate, H=1: one warp per node ----------------
__global__ void gat_agg1_kernel(const int* __restrict__ rowptr, const int* __restrict__ eidx,
                                const int* __restrict__ src, const float* __restrict__ el,
                                const float* __restrict__ er, const float* __restrict__ feat,
                                const float* __restrict__ bias, const float* __restrict__ resid,
                                float* __restrict__ out) {
    int w = blockIdx.x * (blockDim.x >> 5) + (threadIdx.x >> 5);
    if (w >= NN) return;
    int lane = threadIdx.x & 31;
    int start = rowptr[w], end = rowptr[w + 1];
    float erv = er[w];

    float ssum = 0.f;
    for (int i = start + lane; i < end; i += 32) {
        int s = src[eidx[i]];
        float v = el[s] + erv;
        v = (v > 0.f) ? v : 0.2f * v;
        ssum += __expf(v);
    }
#pragma unroll
    for (int o = 16; o; o >>= 1) ssum += __shfl_xor_sync(0xffffffffu, ssum, o);
    float inv = 1.f / ssum;

    int c0 = 2 * lane;
    float2 acc = make_float2(0.f, 0.f);
    for (int i = start; i < end; i++) {
        int e = eidx[i];
        int s = src[e];
        float v = el[s] + erv;
        v = (v > 0.f) ? v : 0.2f * v;
        float a = __expf(v) * inv;
        float2 f = *reinterpret_cast<const float2*>(feat + (size_t)s * 64 + c0);
        acc.x = fmaf(a, f.x, acc.x);
        acc.y = fmaf(a, f.y, acc.y);
    }
    float2 b = *reinterpret_cast<const float2*>(bias + c0);
    float2 r = *reinterpret_cast<const float2*>(resid + (size_t)w * 64 + c0);
    acc.x += b.x + r.x;
    acc.y += b.y + r.y;
    *reinterpret_cast<float2*>(out + (size_t)w * 64 + c0) = acc;
}

// ---------------- host ----------------
extern "C" void kernel_launch(void* const* d_in, const int* in_sizes, int n_in,
                              void* d_out, int out_size) {
    const float* x    = (const float*)d_in[0];
    const int*   src  = (const int*)d_in[1];
    const int*   dst  = (const int*)d_in[2];
    const float* W0   = (const float*)d_in[3];
    const float* al0  = (const float*)d_in[4];
    const float* ar0  = (const float*)d_in[5];
    const float* b0   = (const float*)d_in[6];
    const float* W1   = (const float*)d_in[7];
    const float* al1  = (const float*)d_in[8];
    const float* ar1  = (const float*)d_in[9];
    const float* b1   = (const float*)d_in[10];
    const float* W2   = (const float*)d_in[11];
    const float* al2  = (const float*)d_in[12];
    const float* ar2  = (const float*)d_in[13];
    const float* b2   = (const float*)d_in[14];
    const float* rw2  = (const float*)d_in[15];
    float* out = (float*)d_out;

    float *feat, *h1, *h2, *res2, *el, *er;
    int *rowptr, *cursor, *eidx;
    cudaGetSymbolAddress((void**)&feat,   g_feat);
    cudaGetSymbolAddress((void**)&h1,     g_h1);
    cudaGetSymbolAddress((void**)&h2,     g_h2);
    cudaGetSymbolAddress((void**)&res2,   g_res2);
    cudaGetSymbolAddress((void**)&el,     g_el);
    cudaGetSymbolAddress((void**)&er,     g_er);
    cudaGetSymbolAddress((void**)&rowptr, g_rowptr);
    cudaGetSymbolAddress((void**)&cursor, g_cursor);
    cudaGetSymbolAddress((void**)&eidx,   g_eidx);

    const int MTILES = (NN + 127) / 128;        // 391
    const int NODE_WARP_BLOCKS = (NN + 7) / 8;  // 6250

    // ---------- CSR build (dst shared by all layers) ----------
    zero_deg_kernel<<<(NN + 255) / 256, 256>>>(cursor);
    hist_kernel<<<(NE + 255) / 256, 256>>>(dst, cursor);
    scan_kernel<<<1, 1024>>>(cursor, rowptr);
    scatter_kernel<<<(NE + 255) / 256, 256>>>(dst, cursor, eidx);

    // ================= layer 0: x -> h1, H=4, no residual, ELU =================
    sgemm_tf32_elr_kernel<<<dim3(4, MTILES), 256>>>(x, W0, feat, NN, al0, ar0, el, er);
    gat_agg4_kernel<1, 0><<<NODE_WARP_BLOCKS, 256>>>(rowptr, eidx, src, el, er, feat, b0, nullptr, h1);

    // ================= layer 1: h1 -> h2, H=4, identity residual, ELU =================
    sgemm_tf32_elr_kernel<<<dim3(4, MTILES), 256>>>(h1, W1, feat, NN, al1, ar1, el, er);
    gat_agg4_kernel<1, 1><<<NODE_WARP_BLOCKS, 256>>>(rowptr, eidx, src, el, er, feat, b1, h1, h2);

    // ================= layer 2: h2 -> out, H=1, linear residual, no act =================
    sgemm_tf32_dual_kernel<<<dim3(2, MTILES), 256>>>(h2, W2, rw2, feat, res2, NN, al2, ar2, el, er);
    gat_agg1_kernel<<<NODE_WARP_BLOCKS, 256>>>(rowptr, eidx, src, el, er, feat, b2, res2, out);
}

// round 12
// speedup vs baseline: 3.8892x; 1.0647x over previous
#include <cuda_runtime.h>
#include <math_constants.h>

#define NN 50000
#define NE 800000

// ---------------- scratch (static device globals; no allocation) ----------------
__device__ float g_feat[NN * 256];
__device__ float g_h1[NN * 256];
__device__ float g_h2[NN * 256];
__device__ float g_res2[NN * 64];
__device__ float g_el[NN * 4];
__device__ float g_er[NN * 4];
__device__ int   g_rowptr[NN + 1];
__device__ int   g_cursor[NN];
__device__ int   g_srcs[NE];     // CSR payload: source node id per slot

__device__ __forceinline__ unsigned f2tf(float f) {
    unsigned u;
    asm("cvt.rna.tf32.f32 %0, %1;" : "=r"(u) : "f"(f));
    return u;
}

// ---------------- TF32 tensor-core GEMM core ----------------
// BM=128, BN=64, BK=16, K=256. 256 threads = 8 warps (4m x 2n), warp tile 32x32.
// ELR=1: epilogue additionally computes el/er = C_head . al/ar for this block's head.
#define AS_STRIDE 136
#define BS_STRIDE 72

template <int ELR>
__device__ __forceinline__ void gemm_body(const float* __restrict__ A,
                                          const float* __restrict__ B,
                                          float* __restrict__ C,
                                          int M, int N, int row0, int col0,
                                          const float* __restrict__ alh,
                                          const float* __restrict__ arh,
                                          float* __restrict__ el,
                                          float* __restrict__ er,
                                          int Hs, int head, bool do_elr) {
    const int K = 256;
    __shared__ unsigned As[2][16 * AS_STRIDE];
    __shared__ unsigned Bs[2][16 * BS_STRIDE];
    __shared__ float s_elr[128][2];

    int tid  = threadIdx.x;
    int wid  = tid >> 5;
    int lane = tid & 31;

    int wm = (wid & 3) * 32;
    int wn = (wid >> 2) * 32;

    int arow  = tid >> 1;
    int afqb  = (tid & 1) * 2;
    int ar_g  = row0 + arow;
    bool avalid = (ar_g < M);

    int bkrow = tid >> 4;
    int bncol = (tid & 15) << 2;

    float acc[2][4][4];
#pragma unroll
    for (int i = 0; i < 2; i++)
#pragma unroll
        for (int j = 0; j < 4; j++)
#pragma unroll
            for (int v = 0; v < 4; v++) acc[i][j][v] = 0.f;

    int fr = lane >> 2;
    int fc = lane & 3;

    float4 ra[2], rb;
#pragma unroll
    for (int i = 0; i < 2; i++)
        ra[i] = avalid
            ? *reinterpret_cast<const float4*>(A + (size_t)ar_g * K + (afqb + i) * 4)
            : make_float4(0.f, 0.f, 0.f, 0.f);
    rb = *reinterpret_cast<const float4*>(B + (size_t)bkrow * N + col0 + bncol);

#pragma unroll
    for (int i = 0; i < 2; i++) {
        int k = (afqb + i) * 4;
        As[0][(k + 0) * AS_STRIDE + arow] = f2tf(ra[i].x);
        As[0][(k + 1) * AS_STRIDE + arow] = f2tf(ra[i].y);
        As[0][(k + 2) * AS_STRIDE + arow] = f2tf(ra[i].z);
        As[0][(k + 3) * AS_STRIDE + arow] = f2tf(ra[i].w);
    }
    {
        uint4 u = make_uint4(f2tf(rb.x), f2tf(rb.y), f2tf(rb.z), f2tf(rb.w));
        *reinterpret_cast<uint4*>(&Bs[0][bkrow * BS_STRIDE + bncol]) = u;
    }
    __syncthreads();

    int buf = 0;
    for (int k0 = 0; k0 < K; k0 += 16) {
        bool has_next = (k0 + 16 < K);
        if (has_next) {
#pragma unroll
            for (int i = 0; i < 2; i++)
                ra[i] = avalid
                    ? *reinterpret_cast<const float4*>(
                          A + (size_t)ar_g * K + k0 + 16 + (afqb + i) * 4)
                    : make_float4(0.f, 0.f, 0.f, 0.f);
            rb = *reinterpret_cast<const float4*>(
                B + (size_t)(k0 + 16 + bkrow) * N + col0 + bncol);
        }

        const unsigned* Ab = As[buf];
        const unsigned* Bb = Bs[buf];
#pragma unroll
        for (int kt = 0; kt < 2; kt++) {
            int kb = kt * 8;
            unsigned a[2][4], b[4][2];
#pragma unroll
            for (int mt = 0; mt < 2; mt++) {
                int r = wm + mt * 16 + fr;
                a[mt][0] = Ab[(kb + fc) * AS_STRIDE + r];
                a[mt][1] = Ab[(kb + fc) * AS_STRIDE + r + 8];
                a[mt][2] = Ab[(kb + fc + 4) * AS_STRIDE + r];
                a[mt][3] = Ab[(kb + fc + 4) * AS_STRIDE + r + 8];
            }
#pragma unroll
            for (int nt = 0; nt < 4; nt++) {
                int c = wn + nt * 8 + fr;
                b[nt][0] = Bb[(kb + fc) * BS_STRIDE + c];
                b[nt][1] = Bb[(kb + fc + 4) * BS_STRIDE + c];
            }
#pragma unroll
            for (int mt = 0; mt < 2; mt++)
#pragma unroll
                for (int nt = 0; nt < 4; nt++) {
                    asm volatile(
                        "mma.sync.aligned.m16n8k8.row.col.f32.tf32.tf32.f32 "
                        "{%0,%1,%2,%3}, {%4,%5,%6,%7}, {%8,%9}, {%0,%1,%2,%3};\n"
                        : "+f"(acc[mt][nt][0]), "+f"(acc[mt][nt][1]),
                          "+f"(acc[mt][nt][2]), "+f"(acc[mt][nt][3])
                        : "r"(a[mt][0]), "r"(a[mt][1]), "r"(a[mt][2]), "r"(a[mt][3]),
                          "r"(b[nt][0]), "r"(b[nt][1]));
                }
        }

        if (has_next) {
#pragma unroll
            for (int i = 0; i < 2; i++) {
                int k = (afqb + i) * 4;
                As[buf ^ 1][(k + 0) * AS_STRIDE + arow] = f2tf(ra[i].x);
                As[buf ^ 1][(k + 1) * AS_STRIDE + arow] = f2tf(ra[i].y);
                As[buf ^ 1][(k + 2) * AS_STRIDE + arow] = f2tf(ra[i].z);
                As[buf ^ 1][(k + 3) * AS_STRIDE + arow] = f2tf(ra[i].w);
            }
            uint4 u = make_uint4(f2tf(rb.x), f2tf(rb.y), f2tf(rb.z), f2tf(rb.w));
            *reinterpret_cast<uint4*>(&Bs[buf ^ 1][bkrow * BS_STRIDE + bncol]) = u;
            __syncthreads();
            buf ^= 1;
        }
    }

    // ---- C writeback ----
#pragma unroll
    for (int mt = 0; mt < 2; mt++) {
#pragma unroll
        for (int nt = 0; nt < 4; nt++) {
            int crow = row0 + wm + mt * 16 + fr;
            int ccol = col0 + wn + nt * 8 + 2 * fc;
            if (crow < M)
                *reinterpret_cast<float2*>(C + (size_t)crow * N + ccol) =
                    make_float2(acc[mt][nt][0], acc[mt][nt][1]);
            if (crow + 8 < M)
                *reinterpret_cast<float2*>(C + (size_t)(crow + 8) * N + ccol) =
                    make_float2(acc[mt][nt][2], acc[mt][nt][3]);
        }
    }

    // ---- fused el/er epilogue: this block's 64 cols == one full head ----
    if (ELR && do_elr) {
        float sl[4] = {0.f, 0.f, 0.f, 0.f}, sr[4] = {0.f, 0.f, 0.f, 0.f};
#pragma unroll
        for (int mt = 0; mt < 2; mt++)
#pragma unroll
            for (int nt = 0; nt < 4; nt++) {
                int c = wn + nt * 8 + 2 * fc;
                float a0 = alh[c], a1 = alh[c + 1];
                float r0 = arh[c], r1 = arh[c + 1];
                sl[mt * 2 + 0] += acc[mt][nt][0] * a0 + acc[mt][nt][1] * a1;
                sr[mt * 2 + 0] += acc[mt][nt][0] * r0 + acc[mt][nt][1] * r1;
                sl[mt * 2 + 1] += acc[mt][nt][2] * a0 + acc[mt][nt][3] * a1;
                sr[mt * 2 + 1] += acc[mt][nt][2] * r0 + acc[mt][nt][3] * r1;
            }
#pragma unroll
        for (int k = 0; k < 4; k++) {
            sl[k] += __shfl_xor_sync(0xffffffffu, sl[k], 1);
            sl[k] += __shfl_xor_sync(0xffffffffu, sl[k], 2);
            sr[k] += __shfl_xor_sync(0xffffffffu, sr[k], 1);
            sr[k] += __shfl_xor_sync(0xffffffffu, sr[k], 2);
        }
        int nhalf = wid >> 2;
        int rows[4] = {wm + fr, wm + fr + 8, wm + 16 + fr, wm + 16 + fr + 8};
        if (nhalf == 0 && fc == 0) {
#pragma unroll
            for (int k = 0; k < 4; k++) {
                s_elr[rows[k]][0] = sl[k];
                s_elr[rows[k]][1] = sr[k];
            }
        }
        __syncthreads();
        if (nhalf == 1 && fc == 0) {
#pragma unroll
            for (int k = 0; k < 4; k++) {
                int r = row0 + rows[k];
                if (r < M) {
                    el[(size_t)r * Hs + head] = s_elr[rows[k]][0] + sl[k];
                    er[(size_t)r * Hs + head] = s_elr[rows[k]][1] + sr[k];
                }
            }
        }
    }
}

// H=4 GEMM with fused el/er: blockIdx.x = head (N=256).
__global__ void __launch_bounds__(256) sgemm_tf32_elr_kernel(
        const float* __restrict__ A, const float* __restrict__ B,
        float* __restrict__ C, int M,
        const float* __restrict__ al, const float* __restrict__ ar,
        float* __restrict__ el, float* __restrict__ er) {
    int head = blockIdx.x;
    gemm_body<1>(A, B, C, M, 256, blockIdx.y * 128, head * 64,
                 al + head * 64, ar + head * 64, el, er, 4, head, true);
}

// layer-2 dual GEMM: same A; x=0 -> W2 product (with el/er), x=1 -> res_w2.
__global__ void __launch_bounds__(256) sgemm_tf32_dual_kernel(
        const float* __restrict__ A, const float* __restrict__ B0,
        const float* __restrict__ B1, float* __restrict__ C0,
        float* __restrict__ C1, int M,
        const float* __restrict__ al, const float* __restrict__ ar,
        float* __restrict__ el, float* __restrict__ er) {
    const float* B = blockIdx.x ? B1 : B0;
    float*       C = blockIdx.x ? C1 : C0;
    gemm_body<1>(A, B, C, M, 64, blockIdx.y * 128, 0,
                 al, ar, el, er, 1, 0, blockIdx.x == 0);
}

// ---------------- CSR build ----------------
__global__ void zero_deg_kernel(int* __restrict__ deg) {
    int i = blockIdx.x * blockDim.x + threadIdx.x;
    if (i < NN) deg[i] = 0;
}

__global__ void hist_kernel(const int* __restrict__ dst, int* __restrict__ deg) {
    int e = blockIdx.x * blockDim.x + threadIdx.x;
    if (e < NE) atomicAdd(&deg[dst[e]], 1);
}

__global__ void scan_kernel(int* __restrict__ deg_cursor, int* __restrict__ rowptr) {
    __shared__ int warp_sums[32];
    __shared__ int s_carry;
    int tid = threadIdx.x;  // 1024 threads
    if (tid == 0) s_carry = 0;
    __syncthreads();
    for (int base = 0; base < NN; base += 1024) {
        int i = base + tid;
        int v = (i < NN) ? deg_cursor[i] : 0;
        int x = v;
#pragma unroll
        for (int o = 1; o < 32; o <<= 1) {
            int y = __shfl_up_sync(0xffffffffu, x, o);
            if ((tid & 31) >= o) x += y;
        }
        if ((tid & 31) == 31) warp_sums[tid >> 5] = x;
        __syncthreads();
        if (tid < 32) {
            int s = warp_sums[tid];
#pragma unroll
            for (int o = 1; o < 32; o <<= 1) {
                int y = __shfl_up_sync(0xffffffffu, s, o);
                if (tid >= o) s += y;
            }
            warp_sums[tid] = s;
        }
        __syncthreads();
        int excl = x - v + ((tid >= 32) ? warp_sums[(tid >> 5) - 1] : 0);
        int val  = s_carry + excl;
        if (i < NN) { rowptr[i] = val; deg_cursor[i] = val; }
        int chunk_total = warp_sums[31];
        __syncthreads();
        if (tid == 0) s_carry += chunk_total;
        __syncthreads();
    }
    if (tid == 0) rowptr[NN] = NE;
}

// scatter: store SOURCE NODE ID per CSR slot (agg kernels never need the edge id)
__global__ void scatter_kernel(const int* __restrict__ src, const int* __restrict__ dst,
                               int* __restrict__ cursor, int* __restrict__ srcs) {
    int e = blockIdx.x * blockDim.x + threadIdx.x;
    if (e < NE) {
        int p = atomicAdd(&cursor[dst[e]], 1);
        srcs[p] = src[e];
    }
}

// ---------------- single-pass softmax-aggregate, H=4: one warp per node ----------------
// out = (sum_i exp(v_i) * feat_i) / (sum_i exp(v_i)); every lane walks all edges
// (owns distinct columns) and carries the full denominator redundantly.
template <int ACT, int RES>
__global__ void gat_agg4_kernel(const int* __restrict__ rowptr, const int* __restrict__ srcs,
                                const float* __restrict__ el, const float* __restrict__ er,
                                const float* __restrict__ feat, const float* __restrict__ bias,
                                const float* __restrict__ resid, float* __restrict__ out) {
    int w = blockIdx.x * (blockDim.x >> 5) + (threadIdx.x >> 5);
    if (w >= NN) return;
    int lane = threadIdx.x & 31;
    int start = rowptr[w], end = rowptr[w + 1];

    float4 er4 = *reinterpret_cast<const float4*>(er + (size_t)w * 4);
    int hA = lane >> 4;  // head of first half (0/1); second half: 2+hA
    float erA = hA ? er4.y : er4.x;
    float erB = hA ? er4.w : er4.z;

    int c0 = 4 * lane;
    float4 accA = make_float4(0.f, 0.f, 0.f, 0.f);
    float4 accB = make_float4(0.f, 0.f, 0.f, 0.f);
    float sA = 0.f, sB = 0.f;

    int s = (start < end) ? srcs[start] : 0;
    for (int i = start; i < end; i++) {
        int s_next = (i + 1 < end) ? srcs[i + 1] : s;
        float4 ee = *reinterpret_cast<const float4*>(el + (size_t)s * 4);
        float vA = (hA ? ee.y : ee.x) + erA; vA = (vA > 0.f) ? vA : 0.2f * vA;
        float vB = (hA ? ee.w : ee.z) + erB; vB = (vB > 0.f) ? vB : 0.2f * vB;
        float aA = __expf(vA);
        float aB = __expf(vB);
        sA += aA;
        sB += aB;
        const float* fp = feat + (size_t)s * 256;
        float4 f0 = *reinterpret_cast<const float4*>(fp + c0);
        float4 f1 = *reinterpret_cast<const float4*>(fp + 128 + c0);
        accA.x = fmaf(aA, f0.x, accA.x); accA.y = fmaf(aA, f0.y, accA.y);
        accA.z = fmaf(aA, f0.z, accA.z); accA.w = fmaf(aA, f0.w, accA.w);
        accB.x = fmaf(aB, f1.x, accB.x); accB.y = fmaf(aB, f1.y, accB.y);
        accB.z = fmaf(aB, f1.z, accB.z); accB.w = fmaf(aB, f1.w, accB.w);
        s = s_next;
    }

    float invA = (sA > 0.f) ? 1.f / sA : 0.f;
    float invB = (sB > 0.f) ? 1.f / sB : 0.f;
    accA.x *= invA; accA.y *= invA; accA.z *= invA; accA.w *= invA;
    accB.x *= invB; accB.y *= invB; accB.z *= invB; accB.w *= invB;

    float4 bA = *reinterpret_cast<const float4*>(bias + c0);
    float4 bB = *reinterpret_cast<const float4*>(bias + 128 + c0);
    accA.x += bA.x; accA.y += bA.y; accA.z += bA.z; accA.w += bA.w;
    accB.x += bB.x; accB.y += bB.y; accB.z += bB.z; accB.w += bB.w;
    if (RES) {
        float4 rA = *reinterpret_cast<const float4*>(resid + (size_t)w * 256 + c0);
        float4 rB = *reinterpret_cast<const float4*>(resid + (size_t)w * 256 + 128 + c0);
        accA.x += rA.x; accA.y += rA.y; accA.z += rA.z; accA.w += rA.w;
        accB.x += rB.x; accB.y += rB.y; accB.z += rB.z; accB.w += rB.w;
    }
    if (ACT) {
        accA.x = (accA.x > 0.f) ? accA.x : expm1f(accA.x);
        accA.y = (accA.y > 0.f) ? accA.y : expm1f(accA.y);
        accA.z = (accA.z > 0.f) ? accA.z : expm1f(accA.z);
        accA.w = (accA.w > 0.f) ? accA.w : expm1f(accA.w);
        accB.x = (accB.x > 0.f) ? accB.x : expm1f(accB.x);
        accB.y = (accB.y > 0.f) ? accB.y : expm1f(accB.y);
        accB.z = (accB.z > 0.f) ? accB.z : expm1f(accB.z);
        accB.w = (accB.w > 0.f) ? accB.w : expm1f(accB.w);
    }
    *reinterpret_cast<float4*>(out + (size_t)w * 256 + c0)       = accA;
    *reinterpret_cast<float4*>(out + (size_t)w * 256 + 128 + c0) = accB;
}

// ---------------- single-pass softmax-aggregate, H=1: one warp per node ----------------
__global__ void gat_agg1_kernel(const int* __restrict__ rowptr, const int* __restrict__ srcs,
                                const float* __restrict__ el, const float* __restrict__ er,
                                const float* __restrict__ feat, const float* __restrict__ bias,
                                const float* __restrict__ resid, float* __restrict__ out) {
    int w = blockIdx.x * (blockDim.x >> 5) + (threadIdx.x >> 5);
    if (w >= NN) return;
    int lane = threadIdx.x & 31;
    int start = rowptr[w], end = rowptr[w + 1];
    float erv = er[w];

    int c0 = 2 * lane;
    float2 acc = make_float2(0.f, 0.f);
    float ssum = 0.f;

    int s = (start < end) ? srcs[start] : 0;
    for (int i = start; i < end; i++) {
        int s_next = (i + 1 < end) ? srcs[i + 1] : s;
        float v = el[s] + erv;
        v = (v > 0.f) ? v : 0.2f * v;
        float a = __expf(v);
        ssum += a;
        float2 f = *reinterpret_cast<const float2*>(feat + (size_t)s * 64 + c0);
        acc.x = fmaf(a, f.x, acc.x);
        acc.y = fmaf(a, f.y, acc.y);
        s = s_next;
    }
    float inv = (ssum > 0.f) ? 1.f / ssum : 0.f;
    acc.x *= inv;
    acc.y *= inv;

    float2 b = *reinterpret_cast<const float2*>(bias + c0);
    float2 r = *reinterpret_cast<const float2*>(resid + (size_t)w * 64 + c0);
    acc.x += b.x + r.x;
    acc.y += b.y + r.y;
    *reinterpret_cast<float2*>(out + (size_t)w * 64 + c0) = acc;
}

// ---------------- host ----------------
extern "C" void kernel_launch(void* const* d_in, const int* in_sizes, int n_in,
                              void* d_out, int out_size) {
    const float* x    = (const float*)d_in[0];
    const int*   src  = (const int*)d_in[1];
    const int*   dst  = (const int*)d_in[2];
    const float* W0   = (const float*)d_in[3];
    const float* al0  = (const float*)d_in[4];
    const float* ar0  = (const float*)d_in[5];
    const float* b0   = (const float*)d_in[6];
    const float* W1   = (const float*)d_in[7];
    const float* al1  = (const float*)d_in[8];
    const float* ar1  = (const float*)d_in[9];
    const float* b1   = (const float*)d_in[10];
    const float* W2   = (const float*)d_in[11];
    const float* al2  = (const float*)d_in[12];
    const float* ar2  = (const float*)d_in[13];
    const float* b2   = (const float*)d_in[14];
    const float* rw2  = (const float*)d_in[15];
    float* out = (float*)d_out;

    float *feat, *h1, *h2, *res2, *el, *er;
    int *rowptr, *cursor, *srcs;
    cudaGetSymbolAddress((void**)&feat,   g_feat);
    cudaGetSymbolAddress((void**)&h1,     g_h1);
    cudaGetSymbolAddress((void**)&h2,     g_h2);
    cudaGetSymbolAddress((void**)&res2,   g_res2);
    cudaGetSymbolAddress((void**)&el,     g_el);
    cudaGetSymbolAddress((void**)&er,     g_er);
    cudaGetSymbolAddress((void**)&rowptr, g_rowptr);
    cudaGetSymbolAddress((void**)&cursor, g_cursor);
    cudaGetSymbolAddress((void**)&srcs,   g_srcs);

    const int MTILES = (NN + 127) / 128;        // 391
    const int NODE_WARP_BLOCKS = (NN + 7) / 8;  // 6250

    // ---------- CSR build (dst shared by all layers) ----------
    zero_deg_kernel<<<(NN + 255) / 256, 256>>>(cursor);
    hist_kernel<<<(NE + 255) / 256, 256>>>(dst, cursor);
    scan_kernel<<<1, 1024>>>(cursor, rowptr);
    scatter_kernel<<<(NE + 255) / 256, 256>>>(src, dst, cursor, srcs);

    // ================= layer 0: x -> h1, H=4, no residual, ELU =================
    sgemm_tf32_elr_kernel<<<dim3(4, MTILES), 256>>>(x, W0, feat, NN, al0, ar0, el, er);
    gat_agg4_kernel<1, 0><<<NODE_WARP_BLOCKS, 256>>>(rowptr, srcs, el, er, feat, b0, nullptr, h1);

    // ================= layer 1: h1 -> h2, H=4, identity residual, ELU =================
    sgemm_tf32_elr_kernel<<<dim3(4, MTILES), 256>>>(h1, W1, feat, NN, al1, ar1, el, er);
    gat_agg4_kernel<1, 1><<<NODE_WARP_BLOCKS, 256>>>(rowptr, srcs, el, er, feat, b1, h1, h2);

    // ================= layer 2: h2 -> out, H=1, linear residual, no act =================
    sgemm_tf32_dual_kernel<<<dim3(2, MTILES), 256>>>(h2, W2, rw2, feat, res2, NN, al2, ar2, el, er);
    gat_agg1_kernel<<<NODE_WARP_BLOCKS, 256>>>(rowptr, srcs, el, er, feat, b2, res2, out);
}

// round 13
// speedup vs baseline: 4.2633x; 1.0962x over previous
#include <cuda_runtime.h>
#include <math_constants.h>

#define NN 50000
#define NE 800000

// ---------------- scratch (static device globals; no allocation) ----------------
__device__ float g_feat[NN * 256];
__device__ float g_h1[NN * 256];
__device__ float g_h2[NN * 256];
__device__ float g_res2[NN * 64];
__device__ float g_el[NN * 4];
__device__ float g_er[NN * 4];
__device__ int   g_rowptr[NN + 1];
__device__ int   g_cursor[NN];
__device__ int   g_srcs[NE];     // CSR payload: source node id per slot

__device__ __forceinline__ unsigned f2tf(float f) {
    unsigned u;
    asm("cvt.rna.tf32.f32 %0, %1;" : "=r"(u) : "f"(f));
    return u;
}

#define AS_STRIDE 136
#define BS_STRIDE 72
#define BS_STRIDE2 136

// ================= BN=128 GEMM for H=4 layers: BM=128,BN=128,BK=16 =================
// 8 warps (4m x 2n), warp tile 32x64. Each warp's 64-col n-half == one full head:
// el/er epilogue is warp-local (no smem combine).
__global__ void __launch_bounds__(256) sgemm_tf32_elr128_kernel(
        const float* __restrict__ A, const float* __restrict__ B,
        float* __restrict__ C, int M,
        const float* __restrict__ al, const float* __restrict__ ar,
        float* __restrict__ el, float* __restrict__ er) {
    const int K = 256, N = 256;
    __shared__ unsigned As[2][16 * AS_STRIDE];
    __shared__ unsigned Bs[2][16 * BS_STRIDE2];

    int tid  = threadIdx.x;
    int wid  = tid >> 5;
    int lane = tid & 31;
    int row0 = blockIdx.y * 128, col0 = blockIdx.x * 128;

    int wm = (wid & 3) * 32;
    int wn = (wid >> 2) * 64;
    int head = (col0 >> 6) + (wid >> 2);

    int arow  = tid >> 1;
    int afqb  = (tid & 1) * 2;
    int ar_g  = row0 + arow;
    bool avalid = (ar_g < M);

    float acc[2][8][4];
#pragma unroll
    for (int i = 0; i < 2; i++)
#pragma unroll
        for (int j = 0; j < 8; j++)
#pragma unroll
            for (int v = 0; v < 4; v++) acc[i][j][v] = 0.f;

    int fr = lane >> 2;
    int fc = lane & 3;

    float4 ra[2], rb[2];
    // prologue: load k-chunk 0
#pragma unroll
    for (int i = 0; i < 2; i++)
        ra[i] = avalid
            ? *reinterpret_cast<const float4*>(A + (size_t)ar_g * K + (afqb + i) * 4)
            : make_float4(0.f, 0.f, 0.f, 0.f);
#pragma unroll
    for (int j = 0; j < 2; j++) {
        int idx  = tid + j * 256;
        int krow = idx >> 5;
        int ncol = (idx & 31) << 2;
        rb[j] = *reinterpret_cast<const float4*>(B + (size_t)krow * N + col0 + ncol);
    }
#pragma unroll
    for (int i = 0; i < 2; i++) {
        int k = (afqb + i) * 4;
        As[0][(k + 0) * AS_STRIDE + arow] = f2tf(ra[i].x);
        As[0][(k + 1) * AS_STRIDE + arow] = f2tf(ra[i].y);
        As[0][(k + 2) * AS_STRIDE + arow] = f2tf(ra[i].z);
        As[0][(k + 3) * AS_STRIDE + arow] = f2tf(ra[i].w);
    }
#pragma unroll
    for (int j = 0; j < 2; j++) {
        int idx  = tid + j * 256;
        int krow = idx >> 5;
        int ncol = (idx & 31) << 2;
        uint4 u = make_uint4(f2tf(rb[j].x), f2tf(rb[j].y), f2tf(rb[j].z), f2tf(rb[j].w));
        *reinterpret_cast<uint4*>(&Bs[0][krow * BS_STRIDE2 + ncol]) = u;
    }
    __syncthreads();

    int buf = 0;
    for (int k0 = 0; k0 < K; k0 += 16) {
        bool has_next = (k0 + 16 < K);
        if (has_next) {
#pragma unroll
            for (int i = 0; i < 2; i++)
                ra[i] = avalid
                    ? *reinterpret_cast<const float4*>(
                          A + (size_t)ar_g * K + k0 + 16 + (afqb + i) * 4)
                    : make_float4(0.f, 0.f, 0.f, 0.f);
#pragma unroll
            for (int j = 0; j < 2; j++) {
                int idx  = tid + j * 256;
                int krow = idx >> 5;
                int ncol = (idx & 31) << 2;
                rb[j] = *reinterpret_cast<const float4*>(
                    B + (size_t)(k0 + 16 + krow) * N + col0 + ncol);
            }
        }

        const unsigned* Ab = As[buf];
        const unsigned* Bb = Bs[buf];
#pragma unroll
        for (int kt = 0; kt < 2; kt++) {
            int kb = kt * 8;
            unsigned a[2][4], b[8][2];
#pragma unroll
            for (int mt = 0; mt < 2; mt++) {
                int r = wm + mt * 16 + fr;
                a[mt][0] = Ab[(kb + fc) * AS_STRIDE + r];
                a[mt][1] = Ab[(kb + fc) * AS_STRIDE + r + 8];
                a[mt][2] = Ab[(kb + fc + 4) * AS_STRIDE + r];
                a[mt][3] = Ab[(kb + fc + 4) * AS_STRIDE + r + 8];
            }
#pragma unroll
            for (int nt = 0; nt < 8; nt++) {
                int c = wn + nt * 8 + fr;
                b[nt][0] = Bb[(kb + fc) * BS_STRIDE2 + c];
                b[nt][1] = Bb[(kb + fc + 4) * BS_STRIDE2 + c];
            }
#pragma unroll
            for (int mt = 0; mt < 2; mt++)
#pragma unroll
                for (int nt = 0; nt < 8; nt++) {
                    asm volatile(
                        "mma.sync.aligned.m16n8k8.row.col.f32.tf32.tf32.f32 "
                        "{%0,%1,%2,%3}, {%4,%5,%6,%7}, {%8,%9}, {%0,%1,%2,%3};\n"
                        : "+f"(acc[mt][nt][0]), "+f"(acc[mt][nt][1]),
                          "+f"(acc[mt][nt][2]), "+f"(acc[mt][nt][3])
                        : "r"(a[mt][0]), "r"(a[mt][1]), "r"(a[mt][2]), "r"(a[mt][3]),
                          "r"(b[nt][0]), "r"(b[nt][1]));
                }
        }

        if (has_next) {
#pragma unroll
            for (int i = 0; i < 2; i++) {
                int k = (afqb + i) * 4;
                As[buf ^ 1][(k + 0) * AS_STRIDE + arow] = f2tf(ra[i].x);
                As[buf ^ 1][(k + 1) * AS_STRIDE + arow] = f2tf(ra[i].y);
                As[buf ^ 1][(k + 2) * AS_STRIDE + arow] = f2tf(ra[i].z);
                As[buf ^ 1][(k + 3) * AS_STRIDE + arow] = f2tf(ra[i].w);
            }
#pragma unroll
            for (int j = 0; j < 2; j++) {
                int idx  = tid + j * 256;
                int krow = idx >> 5;
                int ncol = (idx & 31) << 2;
                uint4 u = make_uint4(f2tf(rb[j].x), f2tf(rb[j].y), f2tf(rb[j].z), f2tf(rb[j].w));
                *reinterpret_cast<uint4*>(&Bs[buf ^ 1][krow * BS_STRIDE2 + ncol]) = u;
            }
            __syncthreads();
            buf ^= 1;
        }
    }

    // ---- C writeback ----
#pragma unroll
    for (int mt = 0; mt < 2; mt++) {
#pragma unroll
        for (int nt = 0; nt < 8; nt++) {
            int crow = row0 + wm + mt * 16 + fr;
            int ccol = col0 + wn + nt * 8 + 2 * fc;
            if (crow < M)
                *reinterpret_cast<float2*>(C + (size_t)crow * N + ccol) =
                    make_float2(acc[mt][nt][0], acc[mt][nt][1]);
            if (crow + 8 < M)
                *reinterpret_cast<float2*>(C + (size_t)(crow + 8) * N + ccol) =
                    make_float2(acc[mt][nt][2], acc[mt][nt][3]);
        }
    }

    // ---- fused el/er: this warp's 64 cols == head; warp-local reduction ----
    {
        const float* alh = al + head * 64;
        const float* arh = ar + head * 64;
        float sl[4] = {0.f, 0.f, 0.f, 0.f}, sr[4] = {0.f, 0.f, 0.f, 0.f};
#pragma unroll
        for (int mt = 0; mt < 2; mt++)
#pragma unroll
            for (int nt = 0; nt < 8; nt++) {
                int c = nt * 8 + 2 * fc;
                float a0 = alh[c], a1 = alh[c + 1];
                float r0 = arh[c], r1 = arh[c + 1];
                sl[mt * 2 + 0] += acc[mt][nt][0] * a0 + acc[mt][nt][1] * a1;
                sr[mt * 2 + 0] += acc[mt][nt][0] * r0 + acc[mt][nt][1] * r1;
                sl[mt * 2 + 1] += acc[mt][nt][2] * a0 + acc[mt][nt][3] * a1;
                sr[mt * 2 + 1] += acc[mt][nt][2] * r0 + acc[mt][nt][3] * r1;
            }
#pragma unroll
        for (int k = 0; k < 4; k++) {
            sl[k] += __shfl_xor_sync(0xffffffffu, sl[k], 1);
            sl[k] += __shfl_xor_sync(0xffffffffu, sl[k], 2);
            sr[k] += __shfl_xor_sync(0xffffffffu, sr[k], 1);
            sr[k] += __shfl_xor_sync(0xffffffffu, sr[k], 2);
        }
        if (fc == 0) {
            int rows[4] = {wm + fr, wm + fr + 8, wm + 16 + fr, wm + 16 + fr + 8};
#pragma unroll
            for (int k = 0; k < 4; k++) {
                int r = row0 + rows[k];
                if (r < M) {
                    el[(size_t)r * 4 + head] = sl[k];
                    er[(size_t)r * 4 + head] = sr[k];
                }
            }
        }
    }
}

// ================= BN=64 GEMM body (layer 2 dual) =================
__device__ __forceinline__ void gemm_body64(const float* __restrict__ A,
                                            const float* __restrict__ B,
                                            float* __restrict__ C,
                                            int M, int N, int row0, int col0,
                                            const float* __restrict__ alh,
                                            const float* __restrict__ arh,
                                            float* __restrict__ el,
                                            float* __restrict__ er,
                                            bool do_elr) {
    const int K = 256;
    __shared__ unsigned As[2][16 * AS_STRIDE];
    __shared__ unsigned Bs[2][16 * BS_STRIDE];
    __shared__ float s_elr[128][2];

    int tid  = threadIdx.x;
    int wid  = tid >> 5;
    int lane = tid & 31;

    int wm = (wid & 3) * 32;
    int wn = (wid >> 2) * 32;

    int arow  = tid >> 1;
    int afqb  = (tid & 1) * 2;
    int ar_g  = row0 + arow;
    bool avalid = (ar_g < M);

    int bkrow = tid >> 4;
    int bncol = (tid & 15) << 2;

    float acc[2][4][4];
#pragma unroll
    for (int i = 0; i < 2; i++)
#pragma unroll
        for (int j = 0; j < 4; j++)
#pragma unroll
            for (int v = 0; v < 4; v++) acc[i][j][v] = 0.f;

    int fr = lane >> 2;
    int fc = lane & 3;

    float4 ra[2], rb;
#pragma unroll
    for (int i = 0; i < 2; i++)
        ra[i] = avalid
            ? *reinterpret_cast<const float4*>(A + (size_t)ar_g * K + (afqb + i) * 4)
            : make_float4(0.f, 0.f, 0.f, 0.f);
    rb = *reinterpret_cast<const float4*>(B + (size_t)bkrow * N + col0 + bncol);

#pragma unroll
    for (int i = 0; i < 2; i++) {
        int k = (afqb + i) * 4;
        As[0][(k + 0) * AS_STRIDE + arow] = f2tf(ra[i].x);
        As[0][(k + 1) * AS_STRIDE + arow] = f2tf(ra[i].y);
        As[0][(k + 2) * AS_STRIDE + arow] = f2tf(ra[i].z);
        As[0][(k + 3) * AS_STRIDE + arow] = f2tf(ra[i].w);
    }
    {
        uint4 u = make_uint4(f2tf(rb.x), f2tf(rb.y), f2tf(rb.z), f2tf(rb.w));
        *reinterpret_cast<uint4*>(&Bs[0][bkrow * BS_STRIDE + bncol]) = u;
    }
    __syncthreads();

    int buf = 0;
    for (int k0 = 0; k0 < K; k0 += 16) {
        bool has_next = (k0 + 16 < K);
        if (has_next) {
#pragma unroll
            for (int i = 0; i < 2; i++)
                ra[i] = avalid
                    ? *reinterpret_cast<const float4*>(
                          A + (size_t)ar_g * K + k0 + 16 + (afqb + i) * 4)
                    : make_float4(0.f, 0.f, 0.f, 0.f);
            rb = *reinterpret_cast<const float4*>(
                B + (size_t)(k0 + 16 + bkrow) * N + col0 + bncol);
        }

        const unsigned* Ab = As[buf];
        const unsigned* Bb = Bs[buf];
#pragma unroll
        for (int kt = 0; kt < 2; kt++) {
            int kb = kt * 8;
            unsigned a[2][4], b[4][2];
#pragma unroll
            for (int mt = 0; mt < 2; mt++) {
                int r = wm + mt * 16 + fr;
                a[mt][0] = Ab[(kb + fc) * AS_STRIDE + r];
                a[mt][1] = Ab[(kb + fc) * AS_STRIDE + r + 8];
                a[mt][2] = Ab[(kb + fc + 4) * AS_STRIDE + r];
                a[mt][3] = Ab[(kb + fc + 4) * AS_STRIDE + r + 8];
            }
#pragma unroll
            for (int nt = 0; nt < 4; nt++) {
                int c = wn + nt * 8 + fr;
                b[nt][0] = Bb[(kb + fc) * BS_STRIDE + c];
                b[nt][1] = Bb[(kb + fc + 4) * BS_STRIDE + c];
            }
#pragma unroll
            for (int mt = 0; mt < 2; mt++)
#pragma unroll
                for (int nt = 0; nt < 4; nt++) {
                    asm volatile(
                        "mma.sync.aligned.m16n8k8.row.col.f32.tf32.tf32.f32 "
                        "{%0,%1,%2,%3}, {%4,%5,%6,%7}, {%8,%9}, {%0,%1,%2,%3};\n"
                        : "+f"(acc[mt][nt][0]), "+f"(acc[mt][nt][1]),
                          "+f"(acc[mt][nt][2]), "+f"(acc[mt][nt][3])
                        : "r"(a[mt][0]), "r"(a[mt][1]), "r"(a[mt][2]), "r"(a[mt][3]),
                          "r"(b[nt][0]), "r"(b[nt][1]));
                }
        }

        if (has_next) {
#pragma unroll
            for (int i = 0; i < 2; i++) {
                int k = (afqb + i) * 4;
                As[buf ^ 1][(k + 0) * AS_STRIDE + arow] = f2tf(ra[i].x);
                As[buf ^ 1][(k + 1) * AS_STRIDE + arow] = f2tf(ra[i].y);
                As[buf ^ 1][(k + 2) * AS_STRIDE + arow] = f2tf(ra[i].z);
                As[buf ^ 1][(k + 3) * AS_STRIDE + arow] = f2tf(ra[i].w);
            }
            uint4 u = make_uint4(f2tf(rb.x), f2tf(rb.y), f2tf(rb.z), f2tf(rb.w));
            *reinterpret_cast<uint4*>(&Bs[buf ^ 1][bkrow * BS_STRIDE + bncol]) = u;
            __syncthreads();
            buf ^= 1;
        }
    }

#pragma unroll
    for (int mt = 0; mt < 2; mt++) {
#pragma unroll
        for (int nt = 0; nt < 4; nt++) {
            int crow = row0 + wm + mt * 16 + fr;
            int ccol = col0 + wn + nt * 8 + 2 * fc;
            if (crow < M)
                *reinterpret_cast<float2*>(C + (size_t)crow * N + ccol) =
                    make_float2(acc[mt][nt][0], acc[mt][nt][1]);
            if (crow + 8 < M)
                *reinterpret_cast<float2*>(C + (size_t)(crow + 8) * N + ccol) =
                    make_float2(acc[mt][nt][2], acc[mt][nt][3]);
        }
    }

    if (do_elr) {
        float sl[4] = {0.f, 0.f, 0.f, 0.f}, sr[4] = {0.f, 0.f, 0.f, 0.f};
#pragma unroll
        for (int mt = 0; mt < 2; mt++)
#pragma unroll
            for (int nt = 0; nt < 4; nt++) {
                int c = wn + nt * 8 + 2 * fc;
                float a0 = alh[c], a1 = alh[c + 1];
                float r0 = arh[c], r1 = arh[c + 1];
                sl[mt * 2 + 0] += acc[mt][nt][0] * a0 + acc[mt][nt][1] * a1;
                sr[mt * 2 + 0] += acc[mt][nt][0] * r0 + acc[mt][nt][1] * r1;
                sl[mt * 2 + 1] += acc[mt][nt][2] * a0 + acc[mt][nt][3] * a1;
                sr[mt * 2 + 1] += acc[mt][nt][2] * r0 + acc[mt][nt][3] * r1;
            }
#pragma unroll
        for (int k = 0; k < 4; k++) {
            sl[k] += __shfl_xor_sync(0xffffffffu, sl[k], 1);
            sl[k] += __shfl_xor_sync(0xffffffffu, sl[k], 2);
            sr[k] += __shfl_xor_sync(0xffffffffu, sr[k], 1);
            sr[k] += __shfl_xor_sync(0xffffffffu, sr[k], 2);
        }
        int nhalf = wid >> 2;
        int rows[4] = {wm + fr, wm + fr + 8, wm + 16 + fr, wm + 16 + fr + 8};
        if (nhalf == 0 && fc == 0) {
#pragma unroll
            for (int k = 0; k < 4; k++) {
                s_elr[rows[k]][0] = sl[k];
                s_elr[rows[k]][1] = sr[k];
            }
        }
        __syncthreads();
        if (nhalf == 1 && fc == 0) {
#pragma unroll
            for (int k = 0; k < 4; k++) {
                int r = row0 + rows[k];
                if (r < M) {
                    el[r] = s_elr[rows[k]][0] + sl[k];
                    er[r] = s_elr[rows[k]][1] + sr[k];
                }
            }
        }
    }
}

// layer-2 dual GEMM: same A; x=0 -> W2 product (with el/er), x=1 -> res_w2.
__global__ void __launch_bounds__(256) sgemm_tf32_dual_kernel(
        const float* __restrict__ A, const float* __restrict__ B0,
        const float* __restrict__ B1, float* __restrict__ C0,
        float* __restrict__ C1, int M,
        const float* __restrict__ al, const float* __restrict__ ar,
        float* __restrict__ el, float* __restrict__ er) {
    const float* B = blockIdx.x ? B1 : B0;
    float*       C = blockIdx.x ? C1 : C0;
    gemm_body64(A, B, C, M, 64, blockIdx.y * 128, 0, al, ar, el, er, blockIdx.x == 0);
}

// ---------------- CSR build ----------------
__global__ void zero_deg_kernel(int* __restrict__ deg) {
    int i = blockIdx.x * blockDim.x + threadIdx.x;
    if (i < NN) deg[i] = 0;
}

__global__ void hist_kernel(const int* __restrict__ dst, int* __restrict__ deg) {
    int e = blockIdx.x * blockDim.x + threadIdx.x;
    if (e < NE) atomicAdd(&deg[dst[e]], 1);
}

__global__ void scan_kernel(int* __restrict__ deg_cursor, int* __restrict__ rowptr) {
    __shared__ int warp_sums[32];
    __shared__ int s_carry;
    int tid = threadIdx.x;  // 1024 threads
    if (tid == 0) s_carry = 0;
    __syncthreads();
    for (int base = 0; base < NN; base += 1024) {
        int i = base + tid;
        int v = (i < NN) ? deg_cursor[i] : 0;
        int x = v;
#pragma unroll
        for (int o = 1; o < 32; o <<= 1) {
            int y = __shfl_up_sync(0xffffffffu, x, o);
            if ((tid & 31) >= o) x += y;
        }
        if ((tid & 31) == 31) warp_sums[tid >> 5] = x;
        __syncthreads();
        if (tid < 32) {
            int s = warp_sums[tid];
#pragma unroll
            for (int o = 1; o < 32; o <<= 1) {
                int y = __shfl_up_sync(0xffffffffu, s, o);
                if (tid >= o) s += y;
            }
            warp_sums[tid] = s;
        }
        __syncthreads();
        int excl = x - v + ((tid >= 32) ? warp_sums[(tid >> 5) - 1] : 0);
        int val  = s_carry + excl;
        if (i < NN) { rowptr[i] = val; deg_cursor[i] = val; }
        int chunk_total = warp_sums[31];
        __syncthreads();
        if (tid == 0) s_carry += chunk_total;
        __syncthreads();
    }
    if (tid == 0) rowptr[NN] = NE;
}

__global__ void scatter_kernel(const int* __restrict__ src, const int* __restrict__ dst,
                               int* __restrict__ cursor, int* __restrict__ srcs) {
    int e = blockIdx.x * blockDim.x + threadIdx.x;
    if (e < NE) {
        int p = atomicAdd(&cursor[dst[e]], 1);
        srcs[p] = src[e];
    }
}

// ---------------- single-pass softmax-aggregate, H=4: one warp per node ----------------
template <int ACT, int RES>
__global__ void gat_agg4_kernel(const int* __restrict__ rowptr, const int* __restrict__ srcs,
                                const float* __restrict__ el, const float* __restrict__ er,
                                const float* __restrict__ feat, const float* __restrict__ bias,
                                const float* __restrict__ resid, float* __restrict__ out) {
    int w = blockIdx.x * (blockDim.x >> 5) + (threadIdx.x >> 5);
    if (w >= NN) return;
    int lane = threadIdx.x & 31;
    int start = rowptr[w], end = rowptr[w + 1];

    float4 er4 = *reinterpret_cast<const float4*>(er + (size_t)w * 4);
    int hA = lane >> 4;
    float erA = hA ? er4.y : er4.x;
    float erB = hA ? er4.w : er4.z;

    int c0 = 4 * lane;
    float4 accA = make_float4(0.f, 0.f, 0.f, 0.f);
    float4 accB = make_float4(0.f, 0.f, 0.f, 0.f);
    float sA = 0.f, sB = 0.f;

    int s = (start < end) ? srcs[start] : 0;
    for (int i = start; i < end; i++) {
        int s_next = (i + 1 < end) ? srcs[i + 1] : s;
        float4 ee = *reinterpret_cast<const float4*>(el + (size_t)s * 4);
        float vA = (hA ? ee.y : ee.x) + erA; vA = (vA > 0.f) ? vA : 0.2f * vA;
        float vB = (hA ? ee.w : ee.z) + erB; vB = (vB > 0.f) ? vB : 0.2f * vB;
        float aA = __expf(vA);
        float aB = __expf(vB);
        sA += aA;
        sB += aB;
        const float* fp = feat + (size_t)s * 256;
        float4 f0 = *reinterpret_cast<const float4*>(fp + c0);
        float4 f1 = *reinterpret_cast<const float4*>(fp + 128 + c0);
        accA.x = fmaf(aA, f0.x, accA.x); accA.y = fmaf(aA, f0.y, accA.y);
        accA.z = fmaf(aA, f0.z, accA.z); accA.w = fmaf(aA, f0.w, accA.w);
        accB.x = fmaf(aB, f1.x, accB.x); accB.y = fmaf(aB, f1.y, accB.y);
        accB.z = fmaf(aB, f1.z, accB.z); accB.w = fmaf(aB, f1.w, accB.w);
        s = s_next;
    }

    float invA = (sA > 0.f) ? 1.f / sA : 0.f;
    float invB = (sB > 0.f) ? 1.f / sB : 0.f;
    accA.x *= invA; accA.y *= invA; accA.z *= invA; accA.w *= invA;
    accB.x *= invB; accB.y *= invB; accB.z *= invB; accB.w *= invB;

    float4 bA = *reinterpret_cast<const float4*>(bias + c0);
    float4 bB = *reinterpret_cast<const float4*>(bias + 128 + c0);
    accA.x += bA.x; accA.y += bA.y; accA.z += bA.z; accA.w += bA.w;
    accB.x += bB.x; accB.y += bB.y; accB.z += bB.z; accB.w += bB.w;
    if (RES) {
        float4 rA = *reinterpret_cast<const float4*>(resid + (size_t)w * 256 + c0);
        float4 rB = *reinterpret_cast<const float4*>(resid + (size_t)w * 256 + 128 + c0);
        accA.x += rA.x; accA.y += rA.y; accA.z += rA.z; accA.w += rA.w;
        accB.x += rB.x; accB.y += rB.y; accB.z += rB.z; accB.w += rB.w;
    }
    if (ACT) {
        accA.x = (accA.x > 0.f) ? accA.x : expm1f(accA.x);
        accA.y = (accA.y > 0.f) ? accA.y : expm1f(accA.y);
        accA.z = (accA.z > 0.f) ? accA.z : expm1f(accA.z);
        accA.w = (accA.w > 0.f) ? accA.w : expm1f(accA.w);
        accB.x = (accB.x > 0.f) ? accB.x : expm1f(accB.x);
        accB.y = (accB.y > 0.f) ? accB.y : expm1f(accB.y);
        accB.z = (accB.z > 0.f) ? accB.z : expm1f(accB.z);
        accB.w = (accB.w > 0.f) ? accB.w : expm1f(accB.w);
    }
    *reinterpret_cast<float4*>(out + (size_t)w * 256 + c0)       = accA;
    *reinterpret_cast<float4*>(out + (size_t)w * 256 + 128 + c0) = accB;
}

// ---------------- single-pass softmax-aggregate, H=1: one warp per node ----------------
__global__ void gat_agg1_kernel(const int* __restrict__ rowptr, const int* __restrict__ srcs,
                                const float* __restrict__ el, const float* __restrict__ er,
                                const float* __restrict__ feat, const float* __restrict__ bias,
                                const float* __restrict__ resid, float* __restrict__ out) {
    int w = blockIdx.x * (blockDim.x >> 5) + (threadIdx.x >> 5);
    if (w >= NN) return;
    int lane = threadIdx.x & 31;
    int start = rowptr[w], end = rowptr[w + 1];
    float erv = er[w];

    int c0 = 2 * lane;
    float2 acc = make_float2(0.f, 0.f);
    float ssum = 0.f;

    int s = (start < end) ? srcs[start] : 0;
    for (int i = start; i < end; i++) {
        int s_next = (i + 1 < end) ? srcs[i + 1] : s;
        float v = el[s] + erv;
        v = (v > 0.f) ? v : 0.2f * v;
        float a = __expf(v);
        ssum += a;
        float2 f = *reinterpret_cast<const float2*>(feat + (size_t)s * 64 + c0);
        acc.x = fmaf(a, f.x, acc.x);
        acc.y = fmaf(a, f.y, acc.y);
        s = s_next;
    }
    float inv = (ssum > 0.f) ? 1.f / ssum : 0.f;
    acc.x *= inv;
    acc.y *= inv;

    float2 b = *reinterpret_cast<const float2*>(bias + c0);
    float2 r = *reinterpret_cast<const float2*>(resid + (size_t)w * 64 + c0);
    acc.x += b.x + r.x;
    acc.y += b.y + r.y;
    *reinterpret_cast<float2*>(out + (size_t)w * 64 + c0) = acc;
}

// ---------------- host ----------------
extern "C" void kernel_launch(void* const* d_in, const int* in_sizes, int n_in,
                              void* d_out, int out_size) {
    const float* x    = (const float*)d_in[0];
    const int*   src  = (const int*)d_in[1];
    const int*   dst  = (const int*)d_in[2];
    const float* W0   = (const float*)d_in[3];
    const float* al0  = (const float*)d_in[4];
    const float* ar0  = (const float*)d_in[5];
    const float* b0   = (const float*)d_in[6];
    const float* W1   = (const float*)d_in[7];
    const float* al1  = (const float*)d_in[8];
    const float* ar1  = (const float*)d_in[9];
    const float* b1   = (const float*)d_in[10];
    const float* W2   = (const float*)d_in[11];
    const float* al2  = (const float*)d_in[12];
    const float* ar2  = (const float*)d_in[13];
    const float* b2   = (const float*)d_in[14];
    const float* rw2  = (const float*)d_in[15];
    float* out = (float*)d_out;

    float *feat, *h1, *h2, *res2, *el, *er;
    int *rowptr, *cursor, *srcs;
    cudaGetSymbolAddress((void**)&feat,   g_feat);
    cudaGetSymbolAddress((void**)&h1,     g_h1);
    cudaGetSymbolAddress((void**)&h2,     g_h2);
    cudaGetSymbolAddress((void**)&res2,   g_res2);
    cudaGetSymbolAddress((void**)&el,     g_el);
    cudaGetSymbolAddress((void**)&er,     g_er);
    cudaGetSymbolAddress((void**)&rowptr, g_rowptr);
    cudaGetSymbolAddress((void**)&cursor, g_cursor);
    cudaGetSymbolAddress((void**)&srcs,   g_srcs);

    // fork-join resources (created once, outside graph capture on first call)
    static cudaStream_t s2 = nullptr;
    static cudaEvent_t ev_fork = nullptr, ev_join = nullptr;
    if (s2 == nullptr) {
        cudaStreamCreate(&s2);
        cudaEventCreateWithFlags(&ev_fork, cudaEventDisableTiming);
        cudaEventCreateWithFlags(&ev_join, cudaEventDisableTiming);
    }

    const int MTILES = (NN + 127) / 128;        // 391
    const int NODE_WARP_BLOCKS = (NN + 7) / 8;  // 6250

    // ---------- fork: CSR build on s2, layer-0 GEMM on main stream ----------
    cudaEventRecord(ev_fork, 0);
    cudaStreamWaitEvent(s2, ev_fork, 0);

    zero_deg_kernel<<<(NN + 255) / 256, 256, 0, s2>>>(cursor);
    hist_kernel<<<(NE + 255) / 256, 256, 0, s2>>>(dst, cursor);
    scan_kernel<<<1, 1024, 0, s2>>>(cursor, rowptr);
    scatter_kernel<<<(NE + 255) / 256, 256, 0, s2>>>(src, dst, cursor, srcs);
    cudaEventRecord(ev_join, s2);

    sgemm_tf32_elr128_kernel<<<dim3(2, MTILES), 256>>>(x, W0, feat, NN, al0, ar0, el, er);

    cudaStreamWaitEvent(0, ev_join, 0);  // join before first aggregate

    // ================= layer 0 aggregate =================
    gat_agg4_kernel<1, 0><<<NODE_WARP_BLOCKS, 256>>>(rowptr, srcs, el, er, feat, b0, nullptr, h1);

    // ================= layer 1 =================
    sgemm_tf32_elr128_kernel<<<dim3(2, MTILES), 256>>>(h1, W1, feat, NN, al1, ar1, el, er);
    gat_agg4_kernel<1, 1><<<NODE_WARP_BLOCKS, 256>>>(rowptr, srcs, el, er, feat, b1, h1, h2);

    // ================= layer 2 =================
    sgemm_tf32_dual_kernel<<<dim3(2, MTILES), 256>>>(h2, W2, rw2, feat, res2, NN, al2, ar2, el, er);
    gat_agg1_kernel<<<NODE_WARP_BLOCKS, 256>>>(rowptr, srcs, el, er, feat, b2, res2, out);
}

// round 14
// speedup vs baseline: 4.3374x; 1.0174x over previous
#include <cuda_runtime.h>
#include <math_constants.h>

#define NN 50000
#define NE 800000

// ---------------- scratch (static device globals; no allocation) ----------------
__device__ float g_feat[NN * 256];
__device__ float g_h1[NN * 256];
__device__ float g_h2[NN * 256];
__device__ float g_res2[NN * 64];
__device__ float g_el[NN * 4];
__device__ float g_er[NN * 4];
__device__ int   g_rowptr[NN + 1];
__device__ int   g_cursor[NN];
__device__ int   g_srcs[NE];     // CSR payload: source node id per slot

__device__ __forceinline__ unsigned f2tf(float f) {
    unsigned u;
    asm("cvt.rna.tf32.f32 %0, %1;" : "=r"(u) : "f"(f));
    return u;
}

// A tile now ROW-major: As[m][k], stride 20 floats (80B rows, 16B-aligned STS.128;
// frag-load bank pattern fr*20+fc covers all 32 banks -> conflict-free).
#define ASR_STRIDE 20
#define BS_STRIDE 72
#define BS_STRIDE2 136

// ================= BN=128 GEMM for H=4 layers: BM=128,BN=128,BK=16 =================
// 8 warps (4m x 2n), warp tile 32x64. Each warp's 64-col n-half == one full head:
// el/er epilogue is warp-local (no smem combine).
__global__ void __launch_bounds__(256) sgemm_tf32_elr128_kernel(
        const float* __restrict__ A, const float* __restrict__ B,
        float* __restrict__ C, int M,
        const float* __restrict__ al, const float* __restrict__ ar,
        float* __restrict__ el, float* __restrict__ er) {
    const int K = 256, N = 256;
    __shared__ unsigned As[2][128 * ASR_STRIDE];
    __shared__ unsigned Bs[2][16 * BS_STRIDE2];

    int tid  = threadIdx.x;
    int wid  = tid >> 5;
    int lane = tid & 31;
    int row0 = blockIdx.y * 128, col0 = blockIdx.x * 128;

    int wm = (wid & 3) * 32;
    int wn = (wid >> 2) * 64;
    int head = (col0 >> 6) + (wid >> 2);

    int arow  = tid >> 1;
    int afqb  = (tid & 1) * 2;
    int ar_g  = row0 + arow;
    bool avalid = (ar_g < M);

    float acc[2][8][4];
#pragma unroll
    for (int i = 0; i < 2; i++)
#pragma unroll
        for (int j = 0; j < 8; j++)
#pragma unroll
            for (int v = 0; v < 4; v++) acc[i][j][v] = 0.f;

    int fr = lane >> 2;
    int fc = lane & 3;

    float4 ra[2], rb[2];
    // prologue: load k-chunk 0
#pragma unroll
    for (int i = 0; i < 2; i++)
        ra[i] = avalid
            ? *reinterpret_cast<const float4*>(A + (size_t)ar_g * K + (afqb + i) * 4)
            : make_float4(0.f, 0.f, 0.f, 0.f);
#pragma unroll
    for (int j = 0; j < 2; j++) {
        int idx  = tid + j * 256;
        int krow = idx >> 5;
        int ncol = (idx & 31) << 2;
        rb[j] = *reinterpret_cast<const float4*>(B + (size_t)krow * N + col0 + ncol);
    }
#pragma unroll
    for (int i = 0; i < 2; i++) {
        uint4 u = make_uint4(f2tf(ra[i].x), f2tf(ra[i].y), f2tf(ra[i].z), f2tf(ra[i].w));
        *reinterpret_cast<uint4*>(&As[0][arow * ASR_STRIDE + (afqb + i) * 4]) = u;
    }
#pragma unroll
    for (int j = 0; j < 2; j++) {
        int idx  = tid + j * 256;
        int krow = idx >> 5;
        int ncol = (idx & 31) << 2;
        uint4 u = make_uint4(f2tf(rb[j].x), f2tf(rb[j].y), f2tf(rb[j].z), f2tf(rb[j].w));
        *reinterpret_cast<uint4*>(&Bs[0][krow * BS_STRIDE2 + ncol]) = u;
    }
    __syncthreads();

    int buf = 0;
    for (int k0 = 0; k0 < K; k0 += 16) {
        bool has_next = (k0 + 16 < K);
        if (has_next) {
#pragma unroll
            for (int i = 0; i < 2; i++)
                ra[i] = avalid
                    ? *reinterpret_cast<const float4*>(
                          A + (size_t)ar_g * K + k0 + 16 + (afqb + i) * 4)
                    : make_float4(0.f, 0.f, 0.f, 0.f);
#pragma unroll
            for (int j = 0; j < 2; j++) {
                int idx  = tid + j * 256;
                int krow = idx >> 5;
                int ncol = (idx & 31) << 2;
                rb[j] = *reinterpret_cast<const float4*>(
                    B + (size_t)(k0 + 16 + krow) * N + col0 + ncol);
            }
        }

        const unsigned* Ab = As[buf];
        const unsigned* Bb = Bs[buf];
#pragma unroll
        for (int kt = 0; kt < 2; kt++) {
            int kb = kt * 8;
            unsigned a[2][4], b[8][2];
#pragma unroll
            for (int mt = 0; mt < 2; mt++) {
                int r = wm + mt * 16 + fr;
                a[mt][0] = Ab[r * ASR_STRIDE + kb + fc];
                a[mt][1] = Ab[(r + 8) * ASR_STRIDE + kb + fc];
                a[mt][2] = Ab[r * ASR_STRIDE + kb + fc + 4];
                a[mt][3] = Ab[(r + 8) * ASR_STRIDE + kb + fc + 4];
            }
#pragma unroll
            for (int nt = 0; nt < 8; nt++) {
                int c = wn + nt * 8 + fr;
                b[nt][0] = Bb[(kb + fc) * BS_STRIDE2 + c];
                b[nt][1] = Bb[(kb + fc + 4) * BS_STRIDE2 + c];
            }
#pragma unroll
            for (int mt = 0; mt < 2; mt++)
#pragma unroll
                for (int nt = 0; nt < 8; nt++) {
                    asm volatile(
                        "mma.sync.aligned.m16n8k8.row.col.f32.tf32.tf32.f32 "
                        "{%0,%1,%2,%3}, {%4,%5,%6,%7}, {%8,%9}, {%0,%1,%2,%3};\n"
                        : "+f"(acc[mt][nt][0]), "+f"(acc[mt][nt][1]),
                          "+f"(acc[mt][nt][2]), "+f"(acc[mt][nt][3])
                        : "r"(a[mt][0]), "r"(a[mt][1]), "r"(a[mt][2]), "r"(a[mt][3]),
                          "r"(b[nt][0]), "r"(b[nt][1]));
                }
        }

        if (has_next) {
#pragma unroll
            for (int i = 0; i < 2; i++) {
                uint4 u = make_uint4(f2tf(ra[i].x), f2tf(ra[i].y), f2tf(ra[i].z), f2tf(ra[i].w));
                *reinterpret_cast<uint4*>(&As[buf ^ 1][arow * ASR_STRIDE + (afqb + i) * 4]) = u;
            }
#pragma unroll
            for (int j = 0; j < 2; j++) {
                int idx  = tid + j * 256;
                int krow = idx >> 5;
                int ncol = (idx & 31) << 2;
                uint4 u = make_uint4(f2tf(rb[j].x), f2tf(rb[j].y), f2tf(rb[j].z), f2tf(rb[j].w));
                *reinterpret_cast<uint4*>(&Bs[buf ^ 1][krow * BS_STRIDE2 + ncol]) = u;
            }
            __syncthreads();
            buf ^= 1;
        }
    }

    // ---- C writeback ----
#pragma unroll
    for (int mt = 0; mt < 2; mt++) {
#pragma unroll
        for (int nt = 0; nt < 8; nt++) {
            int crow = row0 + wm + mt * 16 + fr;
            int ccol = col0 + wn + nt * 8 + 2 * fc;
            if (crow < M)
                *reinterpret_cast<float2*>(C + (size_t)crow * N + ccol) =
                    make_float2(acc[mt][nt][0], acc[mt][nt][1]);
            if (crow + 8 < M)
                *reinterpret_cast<float2*>(C + (size_t)(crow + 8) * N + ccol) =
                    make_float2(acc[mt][nt][2], acc[mt][nt][3]);
        }
    }

    // ---- fused el/er: this warp's 64 cols == head; warp-local reduction ----
    {
        const float* alh = al + head * 64;
        const float* arh = ar + head * 64;
        float sl[4] = {0.f, 0.f, 0.f, 0.f}, sr[4] = {0.f, 0.f, 0.f, 0.f};
#pragma unroll
        for (int mt = 0; mt < 2; mt++)
#pragma unroll
            for (int nt = 0; nt < 8; nt++) {
                int c = nt * 8 + 2 * fc;
                float a0 = alh[c], a1 = alh[c + 1];
                float r0 = arh[c], r1 = arh[c + 1];
                sl[mt * 2 + 0] += acc[mt][nt][0] * a0 + acc[mt][nt][1] * a1;
                sr[mt * 2 + 0] += acc[mt][nt][0] * r0 + acc[mt][nt][1] * r1;
                sl[mt * 2 + 1] += acc[mt][nt][2] * a0 + acc[mt][nt][3] * a1;
                sr[mt * 2 + 1] += acc[mt][nt][2] * r0 + acc[mt][nt][3] * r1;
            }
#pragma unroll
        for (int k = 0; k < 4; k++) {
            sl[k] += __shfl_xor_sync(0xffffffffu, sl[k], 1);
            sl[k] += __shfl_xor_sync(0xffffffffu, sl[k], 2);
            sr[k] += __shfl_xor_sync(0xffffffffu, sr[k], 1);
            sr[k] += __shfl_xor_sync(0xffffffffu, sr[k], 2);
        }
        if (fc == 0) {
            int rows[4] = {wm + fr, wm + fr + 8, wm + 16 + fr, wm + 16 + fr + 8};
#pragma unroll
            for (int k = 0; k < 4; k++) {
                int r = row0 + rows[k];
                if (r < M) {
                    el[(size_t)r * 4 + head] = sl[k];
                    er[(size_t)r * 4 + head] = sr[k];
                }
            }
        }
    }
}

// ================= BN=64 GEMM body (layer 2 dual) =================
__device__ __forceinline__ void gemm_body64(const float* __restrict__ A,
                                            const float* __restrict__ B,
                                            float* __restrict__ C,
                                            int M, int N, int row0, int col0,
                                            const float* __restrict__ alh,
                                            const float* __restrict__ arh,
                                            float* __restrict__ el,
                                            float* __restrict__ er,
                                            bool do_elr) {
    const int K = 256;
    __shared__ unsigned As[2][128 * ASR_STRIDE];
    __shared__ unsigned Bs[2][16 * BS_STRIDE];
    __shared__ float s_elr[128][2];

    int tid  = threadIdx.x;
    int wid  = tid >> 5;
    int lane = tid & 31;

    int wm = (wid & 3) * 32;
    int wn = (wid >> 2) * 32;

    int arow  = tid >> 1;
    int afqb  = (tid & 1) * 2;
    int ar_g  = row0 + arow;
    bool avalid = (ar_g < M);

    int bkrow = tid >> 4;
    int bncol = (tid & 15) << 2;

    float acc[2][4][4];
#pragma unroll
    for (int i = 0; i < 2; i++)
#pragma unroll
        for (int j = 0; j < 4; j++)
#pragma unroll
            for (int v = 0; v < 4; v++) acc[i][j][v] = 0.f;

    int fr = lane >> 2;
    int fc = lane & 3;

    float4 ra[2], rb;
#pragma unroll
    for (int i = 0; i < 2; i++)
        ra[i] = avalid
            ? *reinterpret_cast<const float4*>(A + (size_t)ar_g * K + (afqb + i) * 4)
            : make_float4(0.f, 0.f, 0.f, 0.f);
    rb = *reinterpret_cast<const float4*>(B + (size_t)bkrow * N + col0 + bncol);

#pragma unroll
    for (int i = 0; i < 2; i++) {
        uint4 u = make_uint4(f2tf(ra[i].x), f2tf(ra[i].y), f2tf(ra[i].z), f2tf(ra[i].w));
        *reinterpret_cast<uint4*>(&As[0][arow * ASR_STRIDE + (afqb + i) * 4]) = u;
    }
    {
        uint4 u = make_uint4(f2tf(rb.x), f2tf(rb.y), f2tf(rb.z), f2tf(rb.w));
        *reinterpret_cast<uint4*>(&Bs[0][bkrow * BS_STRIDE + bncol]) = u;
    }
    __syncthreads();

    int buf = 0;
    for (int k0 = 0; k0 < K; k0 += 16) {
        bool has_next = (k0 + 16 < K);
        if (has_next) {
#pragma unroll
            for (int i = 0; i < 2; i++)
                ra[i] = avalid
                    ? *reinterpret_cast<const float4*>(
                          A + (size_t)ar_g * K + k0 + 16 + (afqb + i) * 4)
                    : make_float4(0.f, 0.f, 0.f, 0.f);
            rb = *reinterpret_cast<const float4*>(
                B + (size_t)(k0 + 16 + bkrow) * N + col0 + bncol);
        }

        const unsigned* Ab = As[buf];
        const unsigned* Bb = Bs[buf];
#pragma unroll
        for (int kt = 0; kt < 2; kt++) {
            int kb = kt * 8;
            unsigned a[2][4], b[4][2];
#pragma unroll
            for (int mt = 0; mt < 2; mt++) {
                int r = wm + mt * 16 + fr;
                a[mt][0] = Ab[r * ASR_STRIDE + kb + fc];
                a[mt][1] = Ab[(r + 8) * ASR_STRIDE + kb + fc];
                a[mt][2] = Ab[r * ASR_STRIDE + kb + fc + 4];
                a[mt][3] = Ab[(r + 8) * ASR_STRIDE + kb + fc + 4];
            }
#pragma unroll
            for (int nt = 0; nt < 4; nt++) {
                int c = wn + nt * 8 + fr;
                b[nt][0] = Bb[(kb + fc) * BS_STRIDE + c];
                b[nt][1] = Bb[(kb + fc + 4) * BS_STRIDE + c];
            }
#pragma unroll
            for (int mt = 0; mt < 2; mt++)
#pragma unroll
                for (int nt = 0; nt < 4; nt++) {
                    asm volatile(
                        "mma.sync.aligned.m16n8k8.row.col.f32.tf32.tf32.f32 "
                        "{%0,%1,%2,%3}, {%4,%5,%6,%7}, {%8,%9}, {%0,%1,%2,%3};\n"
                        : "+f"(acc[mt][nt][0]), "+f"(acc[mt][nt][1]),
                          "+f"(acc[mt][nt][2]), "+f"(acc[mt][nt][3])
                        : "r"(a[mt][0]), "r"(a[mt][1]), "r"(a[mt][2]), "r"(a[mt][3]),
                          "r"(b[nt][0]), "r"(b[nt][1]));
                }
        }

        if (has_next) {
#pragma unroll
            for (int i = 0; i < 2; i++) {
                uint4 u = make_uint4(f2tf(ra[i].x), f2tf(ra[i].y), f2tf(ra[i].z), f2tf(ra[i].w));
                *reinterpret_cast<uint4*>(&As[buf ^ 1][arow * ASR_STRIDE + (afqb + i) * 4]) = u;
            }
            uint4 u = make_uint4(f2tf(rb.x), f2tf(rb.y), f2tf(rb.z), f2tf(rb.w));
            *reinterpret_cast<uint4*>(&Bs[buf ^ 1][bkrow * BS_STRIDE + bncol]) = u;
            __syncthreads();
            buf ^= 1;
        }
    }

#pragma unroll
    for (int mt = 0; mt < 2; mt++) {
#pragma unroll
        for (int nt = 0; nt < 4; nt++) {
            int crow = row0 + wm + mt * 16 + fr;
            int ccol = col0 + wn + nt * 8 + 2 * fc;
            if (crow < M)
                *reinterpret_cast<float2*>(C + (size_t)crow * N + ccol) =
                    make_float2(acc[mt][nt][0], acc[mt][nt][1]);
            if (crow + 8 < M)
                *reinterpret_cast<float2*>(C + (size_t)(crow + 8) * N + ccol) =
                    make_float2(acc[mt][nt][2], acc[mt][nt][3]);
        }
    }

    if (do_elr) {
        float sl[4] = {0.f, 0.f, 0.f, 0.f}, sr[4] = {0.f, 0.f, 0.f, 0.f};
#pragma unroll
        for (int mt = 0; mt < 2; mt++)
#pragma unroll
            for (int nt = 0; nt < 4; nt++) {
                int c = wn + nt * 8 + 2 * fc;
                float a0 = alh[c], a1 = alh[c + 1];
                float r0 = arh[c], r1 = arh[c + 1];
                sl[mt * 2 + 0] += acc[mt][nt][0] * a0 + acc[mt][nt][1] * a1;
                sr[mt * 2 + 0] += acc[mt][nt][0] * r0 + acc[mt][nt][1] * r1;
                sl[mt * 2 + 1] += acc[mt][nt][2] * a0 + acc[mt][nt][3] * a1;
                sr[mt * 2 + 1] += acc[mt][nt][2] * r0 + acc[mt][nt][3] * r1;
            }
#pragma unroll
        for (int k = 0; k < 4; k++) {
            sl[k] += __shfl_xor_sync(0xffffffffu, sl[k], 1);
            sl[k] += __shfl_xor_sync(0xffffffffu, sl[k], 2);
            sr[k] += __shfl_xor_sync(0xffffffffu, sr[k], 1);
            sr[k] += __shfl_xor_sync(0xffffffffu, sr[k], 2);
        }
        int nhalf = wid >> 2;
        int rows[4] = {wm + fr, wm + fr + 8, wm + 16 + fr, wm + 16 + fr + 8};
        if (nhalf == 0 && fc == 0) {
#pragma unroll
            for (int k = 0; k < 4; k++) {
                s_elr[rows[k]][0] = sl[k];
                s_elr[rows[k]][1] = sr[k];
            }
        }
        __syncthreads();
        if (nhalf == 1 && fc == 0) {
#pragma unroll
            for (int k = 0; k < 4; k++) {
                int r = row0 + rows[k];
                if (r < M) {
                    el[r] = s_elr[rows[k]][0] + sl[k];
                    er[r] = s_elr[rows[k]][1] + sr[k];
                }
            }
        }
    }
}

// layer-2 dual GEMM: same A; x=0 -> W2 product (with el/er), x=1 -> res_w2.
__global__ void __launch_bounds__(256) sgemm_tf32_dual_kernel(
        const float* __restrict__ A, const float* __restrict__ B0,
        const float* __restrict__ B1, float* __restrict__ C0,
        float* __restrict__ C1, int M,
        const float* __restrict__ al, const float* __restrict__ ar,
        float* __restrict__ el, float* __restrict__ er) {
    const float* B = blockIdx.x ? B1 : B0;
    float*       C = blockIdx.x ? C1 : C0;
    gemm_body64(A, B, C, M, 64, blockIdx.y * 128, 0, al, ar, el, er, blockIdx.x == 0);
}

// ---------------- CSR build ----------------
__global__ void zero_deg_kernel(int* __restrict__ deg) {
    int i = blockIdx.x * blockDim.x + threadIdx.x;
    if (i < NN) deg[i] = 0;
}

__global__ void hist_kernel(const int* __restrict__ dst, int* __restrict__ deg) {
    int e = blockIdx.x * blockDim.x + threadIdx.x;
    if (e < NE) atomicAdd(&deg[dst[e]], 1);
}

__global__ void scan_kernel(int* __restrict__ deg_cursor, int* __restrict__ rowptr) {
    __shared__ int warp_sums[32];
    __shared__ int s_carry;
    int tid = threadIdx.x;  // 1024 threads
    if (tid == 0) s_carry = 0;
    __syncthreads();
    for (int base = 0; base < NN; base += 1024) {
        int i = base + tid;
        int v = (i < NN) ? deg_cursor[i] : 0;
        int x = v;
#pragma unroll
        for (int o = 1; o < 32; o <<= 1) {
            int y = __shfl_up_sync(0xffffffffu, x, o);
            if ((tid & 31) >= o) x += y;
        }
        if ((tid & 31) == 31) warp_sums[tid >> 5] = x;
        __syncthreads();
        if (tid < 32) {
            int s = warp_sums[tid];
#pragma unroll
            for (int o = 1; o < 32; o <<= 1) {
                int y = __shfl_up_sync(0xffffffffu, s, o);
                if (tid >= o) s += y;
            }
            warp_sums[tid] = s;
        }
        __syncthreads();
        int excl = x - v + ((tid >= 32) ? warp_sums[(tid >> 5) - 1] : 0);
        int val  = s_carry + excl;
        if (i < NN) { rowptr[i] = val; deg_cursor[i] = val; }
        int chunk_total = warp_sums[31];
        __syncthreads();
        if (tid == 0) s_carry += chunk_total;
        __syncthreads();
    }
    if (tid == 0) rowptr[NN] = NE;
}

__global__ void scatter_kernel(const int* __restrict__ src, const int* __restrict__ dst,
                               int* __restrict__ cursor, int* __restrict__ srcs) {
    int e = blockIdx.x * blockDim.x + threadIdx.x;
    if (e < NE) {
        int p = atomicAdd(&cursor[dst[e]], 1);
        srcs[p] = src[e];
    }
}

// ---------------- single-pass softmax-aggregate, H=4: one warp per node ----------------
// Prefetch srcs two ahead + el one ahead to break the srcs->el->feat chain.
template <int ACT, int RES>
__global__ void __launch_bounds__(256) gat_agg4_kernel(
        const int* __restrict__ rowptr, const int* __restrict__ srcs,
        const float* __restrict__ el, const float* __restrict__ er,
        const float* __restrict__ feat, const float* __restrict__ bias,
        const float* __restrict__ resid, float* __restrict__ out) {
    int w = blockIdx.x * (blockDim.x >> 5) + (threadIdx.x >> 5);
    if (w >= NN) return;
    int lane = threadIdx.x & 31;
    int start = rowptr[w], end = rowptr[w + 1];

    float4 er4 = *reinterpret_cast<const float4*>(er + (size_t)w * 4);
    int hA = lane >> 4;
    float erA = hA ? er4.y : er4.x;
    float erB = hA ? er4.w : er4.z;

    int c0 = 4 * lane;
    float4 accA = make_float4(0.f, 0.f, 0.f, 0.f);
    float4 accB = make_float4(0.f, 0.f, 0.f, 0.f);
    float sdA = 0.f, sdB = 0.f;

    int sa = (start < end) ? srcs[start] : 0;
    int sb = (start + 1 < end) ? srcs[start + 1] : sa;
    float4 ee = (start < end)
        ? *reinterpret_cast<const float4*>(el + (size_t)sa * 4)
        : make_float4(0.f, 0.f, 0.f, 0.f);

#pragma unroll 2
    for (int i = start; i < end; i++) {
        int sc = (i + 2 < end) ? srcs[i + 2] : sb;
        float4 eeN = (i + 1 < end)
            ? *reinterpret_cast<const float4*>(el + (size_t)sb * 4)
            : ee;

        float vA = (hA ? ee.y : ee.x) + erA; vA = (vA > 0.f) ? vA : 0.2f * vA;
        float vB = (hA ? ee.w : ee.z) + erB; vB = (vB > 0.f) ? vB : 0.2f * vB;
        float aA = __expf(vA);
        float aB = __expf(vB);
        sdA += aA;
        sdB += aB;
        const float* fp = feat + (size_t)sa * 256;
        float4 f0 = *reinterpret_cast<const float4*>(fp + c0);
        float4 f1 = *reinterpret_cast<const float4*>(fp + 128 + c0);
        accA.x = fmaf(aA, f0.x, accA.x); accA.y = fmaf(aA, f0.y, accA.y);
        accA.z = fmaf(aA, f0.z, accA.z); accA.w = fmaf(aA, f0.w, accA.w);
        accB.x = fmaf(aB, f1.x, accB.x); accB.y = fmaf(aB, f1.y, accB.y);
        accB.z = fmaf(aB, f1.z, accB.z); accB.w = fmaf(aB, f1.w, accB.w);

        sa = sb; sb = sc; ee = eeN;
    }

    float invA = (sdA > 0.f) ? 1.f / sdA : 0.f;
    float invB = (sdB > 0.f) ? 1.f / sdB : 0.f;
    accA.x *= invA; accA.y *= invA; accA.z *= invA; accA.w *= invA;
    accB.x *= invB; accB.y *= invB; accB.z *= invB; accB.w *= invB;

    float4 bA = *reinterpret_cast<const float4*>(bias + c0);
    float4 bB = *reinterpret_cast<const float4*>(bias + 128 + c0);
    accA.x += bA.x; accA.y += bA.y; accA.z += bA.z; accA.w += bA.w;
    accB.x += bB.x; accB.y += bB.y; accB.z += bB.z; accB.w += bB.w;
    if (RES) {
        float4 rA = *reinterpret_cast<const float4*>(resid + (size_t)w * 256 + c0);
        float4 rB = *reinterpret_cast<const float4*>(resid + (size_t)w * 256 + 128 + c0);
        accA.x += rA.x; accA.y += rA.y; accA.z += rA.z; accA.w += rA.w;
        accB.x += rB.x; accB.y += rB.y; accB.z += rB.z; accB.w += rB.w;
    }
    if (ACT) {
        accA.x = (accA.x > 0.f) ? accA.x : expm1f(accA.x);
        accA.y = (accA.y > 0.f) ? accA.y : expm1f(accA.y);
        accA.z = (accA.z > 0.f) ? accA.z : expm1f(accA.z);
        accA.w = (accA.w > 0.f) ? accA.w : expm1f(accA.w);
        accB.x = (accB.x > 0.f) ? accB.x : expm1f(accB.x);
        accB.y = (accB.y > 0.f) ? accB.y : expm1f(accB.y);
        accB.z = (accB.z > 0.f) ? accB.z : expm1f(accB.z);
        accB.w = (accB.w > 0.f) ? accB.w : expm1f(accB.w);
    }
    *reinterpret_cast<float4*>(out + (size_t)w * 256 + c0)       = accA;
    *reinterpret_cast<float4*>(out + (size_t)w * 256 + 128 + c0) = accB;
}

// ---------------- single-pass softmax-aggregate, H=1: one warp per node ----------------
__global__ void __launch_bounds__(256) gat_agg1_kernel(
        const int* __restrict__ rowptr, const int* __restrict__ srcs,
        const float* __restrict__ el, const float* __restrict__ er,
        const float* __restrict__ feat, const float* __restrict__ bias,
        const float* __restrict__ resid, float* __restrict__ out) {
    int w = blockIdx.x * (blockDim.x >> 5) + (threadIdx.x >> 5);
    if (w >= NN) return;
    int lane = threadIdx.x & 31;
    int start = rowptr[w], end = rowptr[w + 1];
    float erv = er[w];

    int c0 = 2 * lane;
    float2 acc = make_float2(0.f, 0.f);
    float ssum = 0.f;

    int sa = (start < end) ? srcs[start] : 0;
    int sb = (start + 1 < end) ? srcs[start + 1] : sa;
    float eev = (start < end) ? el[sa] : 0.f;

#pragma unroll 2
    for (int i = start; i < end; i++) {
        int sc = (i + 2 < end) ? srcs[i + 2] : sb;
        float eeN = (i + 1 < end) ? el[sb] : eev;

        float v = eev + erv;
        v = (v > 0.f) ? v : 0.2f * v;
        float a = __expf(v);
        ssum += a;
        float2 f = *reinterpret_cast<const float2*>(feat + (size_t)sa * 64 + c0);
        acc.x = fmaf(a, f.x, acc.x);
        acc.y = fmaf(a, f.y, acc.y);

        sa = sb; sb = sc; eev = eeN;
    }
    float inv = (ssum > 0.f) ? 1.f / ssum : 0.f;
    acc.x *= inv;
    acc.y *= inv;

    float2 b = *reinterpret_cast<const float2*>(bias + c0);
    float2 r = *reinterpret_cast<const float2*>(resid + (size_t)w * 64 + c0);
    acc.x += b.x + r.x;
    acc.y += b.y + r.y;
    *reinterpret_cast<float2*>(out + (size_t)w * 64 + c0) = acc;
}

// ---------------- host ----------------
extern "C" void kernel_launch(void* const* d_in, const int* in_sizes, int n_in,
                              void* d_out, int out_size) {
    const float* x    = (const float*)d_in[0];
    const int*   src  = (const int*)d_in[1];
    const int*   dst  = (const int*)d_in[2];
    const float* W0   = (const float*)d_in[3];
    const float* al0  = (const float*)d_in[4];
    const float* ar0  = (const float*)d_in[5];
    const float* b0   = (const float*)d_in[6];
    const float* W1   = (const float*)d_in[7];
    const float* al1  = (const float*)d_in[8];
    const float* ar1  = (const float*)d_in[9];
    const float* b1   = (const float*)d_in[10];
    const float* W2   = (const float*)d_in[11];
    const float* al2  = (const float*)d_in[12];
    const float* ar2  = (const float*)d_in[13];
    const float* b2   = (const float*)d_in[14];
    const float* rw2  = (const float*)d_in[15];
    float* out = (float*)d_out;

    float *feat, *h1, *h2, *res2, *el, *er;
    int *rowptr, *cursor, *srcs;
    cudaGetSymbolAddress((void**)&feat,   g_feat);
    cudaGetSymbolAddress((void**)&h1,     g_h1);
    cudaGetSymbolAddress((void**)&h2,     g_h2);
    cudaGetSymbolAddress((void**)&res2,   g_res2);
    cudaGetSymbolAddress((void**)&el,     g_el);
    cudaGetSymbolAddress((void**)&er,     g_er);
    cudaGetSymbolAddress((void**)&rowptr, g_rowptr);
    cudaGetSymbolAddress((void**)&cursor, g_cursor);
    cudaGetSymbolAddress((void**)&srcs,   g_srcs);

    // fork-join resources (created once, outside graph capture on first call)
    static cudaStream_t s2 = nullptr;
    static cudaEvent_t ev_fork = nullptr, ev_join = nullptr;
    if (s2 == nullptr) {
        cudaStreamCreate(&s2);
        cudaEventCreateWithFlags(&ev_fork, cudaEventDisableTiming);
        cudaEventCreateWithFlags(&ev_join, cudaEventDisableTiming);
    }

    const int MTILES = (NN + 127) / 128;        // 391
    const int NODE_WARP_BLOCKS = (NN + 7) / 8;  // 6250

    // ---------- fork: CSR build on s2, layer-0 GEMM on main stream ----------
    cudaEventRecord(ev_fork, 0);
    cudaStreamWaitEvent(s2, ev_fork, 0);

    zero_deg_kernel<<<(NN + 255) / 256, 256, 0, s2>>>(cursor);
    hist_kernel<<<(NE + 255) / 256, 256, 0, s2>>>(dst, cursor);
    scan_kernel<<<1, 1024, 0, s2>>>(cursor, rowptr);
    scatter_kernel<<<(NE + 255) / 256, 256, 0, s2>>>(src, dst, cursor, srcs);
    cudaEventRecord(ev_join, s2);

    sgemm_tf32_elr128_kernel<<<dim3(2, MTILES), 256>>>(x, W0, feat, NN, al0, ar0, el, er);

    cudaStreamWaitEvent(0, ev_join, 0);  // join before first aggregate

    // ================= layer 0 aggregate =================
    gat_agg4_kernel<1, 0><<<NODE_WARP_BLOCKS, 256>>>(rowptr, srcs, el, er, feat, b0, nullptr, h1);

    // ================= layer 1 =================
    sgemm_tf32_elr128_kernel<<<dim3(2, MTILES), 256>>>(h1, W1, feat, NN, al1, ar1, el, er);
    gat_agg4_kernel<1, 1><<<NODE_WARP_BLOCKS, 256>>>(rowptr, srcs, el, er, feat, b1, h1, h2);

    // ================= layer 2 =================
    sgemm_tf32_dual_kernel<<<dim3(2, MTILES), 256>>>(h2, W2, rw2, feat, res2, NN, al2, ar2, el, er);
    gat_agg1_kernel<<<NODE_WARP_BLOCKS, 256>>>(rowptr, srcs, el, er, feat, b2, res2, out);
}

// round 15
// speedup vs baseline: 4.6246x; 1.0662x over previous
#include <cuda_runtime.h>
#include <cuda_fp16.h>
#include <math_constants.h>

#define NN 50000
#define NE 800000

// ---------------- scratch (static device globals; no allocation) ----------------
__device__ __half g_feat16[NN * 256];   // fp16 features (gather payload)
__device__ float  g_h1[NN * 256];
__device__ float  g_h2[NN * 256];
__device__ float  g_res2[NN * 64];
__device__ float  g_el[NN * 4];
__device__ float  g_er[NN * 4];
__device__ int    g_rowptr[NN + 1];
__device__ int    g_cursor[NN];
__device__ int    g_srcs[NE];

__device__ __forceinline__ unsigned f2tf(float f) {
    unsigned u;
    asm("cvt.rna.tf32.f32 %0, %1;" : "=r"(u) : "f"(f));
    return u;
}

#define ASR_STRIDE 20
#define BS_STRIDE 72
#define BS_STRIDE2 136

// ================= BN=128 GEMM for H=4 layers: BM=128,BN=128,BK=16 =================
// Writes C in fp16 (row stride 256 halfs). el/er epilogue warp-local per head.
__global__ void __launch_bounds__(256) sgemm_tf32_elr128_kernel(
        const float* __restrict__ A, const float* __restrict__ B,
        __half* __restrict__ C, int M,
        const float* __restrict__ al, const float* __restrict__ ar,
        float* __restrict__ el, float* __restrict__ er) {
    const int K = 256, N = 256;
    __shared__ unsigned As[2][128 * ASR_STRIDE];
    __shared__ unsigned Bs[2][16 * BS_STRIDE2];

    int tid  = threadIdx.x;
    int wid  = tid >> 5;
    int lane = tid & 31;
    int row0 = blockIdx.y * 128, col0 = blockIdx.x * 128;

    int wm = (wid & 3) * 32;
    int wn = (wid >> 2) * 64;
    int head = (col0 >> 6) + (wid >> 2);

    int arow  = tid >> 1;
    int afqb  = (tid & 1) * 2;
    int ar_g  = row0 + arow;
    bool avalid = (ar_g < M);

    float acc[2][8][4];
#pragma unroll
    for (int i = 0; i < 2; i++)
#pragma unroll
        for (int j = 0; j < 8; j++)
#pragma unroll
            for (int v = 0; v < 4; v++) acc[i][j][v] = 0.f;

    int fr = lane >> 2;
    int fc = lane & 3;

    float4 ra[2], rb[2];
#pragma unroll
    for (int i = 0; i < 2; i++)
        ra[i] = avalid
            ? *reinterpret_cast<const float4*>(A + (size_t)ar_g * K + (afqb + i) * 4)
            : make_float4(0.f, 0.f, 0.f, 0.f);
#pragma unroll
    for (int j = 0; j < 2; j++) {
        int idx  = tid + j * 256;
        int krow = idx >> 5;
        int ncol = (idx & 31) << 2;
        rb[j] = *reinterpret_cast<const float4*>(B + (size_t)krow * N + col0 + ncol);
    }
#pragma unroll
    for (int i = 0; i < 2; i++) {
        uint4 u = make_uint4(f2tf(ra[i].x), f2tf(ra[i].y), f2tf(ra[i].z), f2tf(ra[i].w));
        *reinterpret_cast<uint4*>(&As[0][arow * ASR_STRIDE + (afqb + i) * 4]) = u;
    }
#pragma unroll
    for (int j = 0; j < 2; j++) {
        int idx  = tid + j * 256;
        int krow = idx >> 5;
        int ncol = (idx & 31) << 2;
        uint4 u = make_uint4(f2tf(rb[j].x), f2tf(rb[j].y), f2tf(rb[j].z), f2tf(rb[j].w));
        *reinterpret_cast<uint4*>(&Bs[0][krow * BS_STRIDE2 + ncol]) = u;
    }
    __syncthreads();

    int buf = 0;
    for (int k0 = 0; k0 < K; k0 += 16) {
        bool has_next = (k0 + 16 < K);
        if (has_next) {
#pragma unroll
            for (int i = 0; i < 2; i++)
                ra[i] = avalid
                    ? *reinterpret_cast<const float4*>(
                          A + (size_t)ar_g * K + k0 + 16 + (afqb + i) * 4)
                    : make_float4(0.f, 0.f, 0.f, 0.f);
#pragma unroll
            for (int j = 0; j < 2; j++) {
                int idx  = tid + j * 256;
                int krow = idx >> 5;
                int ncol = (idx & 31) << 2;
                rb[j] = *reinterpret_cast<const float4*>(
                    B + (size_t)(k0 + 16 + krow) * N + col0 + ncol);
            }
        }

        const unsigned* Ab = As[buf];
        const unsigned* Bb = Bs[buf];
#pragma unroll
        for (int kt = 0; kt < 2; kt++) {
            int kb = kt * 8;
            unsigned a[2][4], b[8][2];
#pragma unroll
            for (int mt = 0; mt < 2; mt++) {
                int r = wm + mt * 16 + fr;
                a[mt][0] = Ab[r * ASR_STRIDE + kb + fc];
                a[mt][1] = Ab[(r + 8) * ASR_STRIDE + kb + fc];
                a[mt][2] = Ab[r * ASR_STRIDE + kb + fc + 4];
                a[mt][3] = Ab[(r + 8) * ASR_STRIDE + kb + fc + 4];
            }
#pragma unroll
            for (int nt = 0; nt < 8; nt++) {
                int c = wn + nt * 8 + fr;
                b[nt][0] = Bb[(kb + fc) * BS_STRIDE2 + c];
                b[nt][1] = Bb[(kb + fc + 4) * BS_STRIDE2 + c];
            }
#pragma unroll
            for (int mt = 0; mt < 2; mt++)
#pragma unroll
                for (int nt = 0; nt < 8; nt++) {
                    asm volatile(
                        "mma.sync.aligned.m16n8k8.row.col.f32.tf32.tf32.f32 "
                        "{%0,%1,%2,%3}, {%4,%5,%6,%7}, {%8,%9}, {%0,%1,%2,%3};\n"
                        : "+f"(acc[mt][nt][0]), "+f"(acc[mt][nt][1]),
                          "+f"(acc[mt][nt][2]), "+f"(acc[mt][nt][3])
                        : "r"(a[mt][0]), "r"(a[mt][1]), "r"(a[mt][2]), "r"(a[mt][3]),
                          "r"(b[nt][0]), "r"(b[nt][1]));
                }
        }

        if (has_next) {
#pragma unroll
            for (int i = 0; i < 2; i++) {
                uint4 u = make_uint4(f2tf(ra[i].x), f2tf(ra[i].y), f2tf(ra[i].z), f2tf(ra[i].w));
                *reinterpret_cast<uint4*>(&As[buf ^ 1][arow * ASR_STRIDE + (afqb + i) * 4]) = u;
            }
#pragma unroll
            for (int j = 0; j < 2; j++) {
                int idx  = tid + j * 256;
                int krow = idx >> 5;
                int ncol = (idx & 31) << 2;
                uint4 u = make_uint4(f2tf(rb[j].x), f2tf(rb[j].y), f2tf(rb[j].z), f2tf(rb[j].w));
                *reinterpret_cast<uint4*>(&Bs[buf ^ 1][krow * BS_STRIDE2 + ncol]) = u;
            }
            __syncthreads();
            buf ^= 1;
        }
    }

    // ---- C writeback (fp16 half2 pairs) ----
#pragma unroll
    for (int mt = 0; mt < 2; mt++) {
#pragma unroll
        for (int nt = 0; nt < 8; nt++) {
            int crow = row0 + wm + mt * 16 + fr;
            int ccol = col0 + wn + nt * 8 + 2 * fc;
            if (crow < M)
                *reinterpret_cast<__half2*>(C + (size_t)crow * N + ccol) =
                    __floats2half2_rn(acc[mt][nt][0], acc[mt][nt][1]);
            if (crow + 8 < M)
                *reinterpret_cast<__half2*>(C + (size_t)(crow + 8) * N + ccol) =
                    __floats2half2_rn(acc[mt][nt][2], acc[mt][nt][3]);
        }
    }

    // ---- fused el/er: warp-local per-head reduction (fp32 accumulators) ----
    {
        const float* alh = al + head * 64;
        const float* arh = ar + head * 64;
        float sl[4] = {0.f, 0.f, 0.f, 0.f}, sr[4] = {0.f, 0.f, 0.f, 0.f};
#pragma unroll
        for (int mt = 0; mt < 2; mt++)
#pragma unroll
            for (int nt = 0; nt < 8; nt++) {
                int c = nt * 8 + 2 * fc;
                float a0 = alh[c], a1 = alh[c + 1];
                float r0 = arh[c], r1 = arh[c + 1];
                sl[mt * 2 + 0] += acc[mt][nt][0] * a0 + acc[mt][nt][1] * a1;
                sr[mt * 2 + 0] += acc[mt][nt][0] * r0 + acc[mt][nt][1] * r1;
                sl[mt * 2 + 1] += acc[mt][nt][2] * a0 + acc[mt][nt][3] * a1;
                sr[mt * 2 + 1] += acc[mt][nt][2] * r0 + acc[mt][nt][3] * r1;
            }
#pragma unroll
        for (int k = 0; k < 4; k++) {
            sl[k] += __shfl_xor_sync(0xffffffffu, sl[k], 1);
            sl[k] += __shfl_xor_sync(0xffffffffu, sl[k], 2);
            sr[k] += __shfl_xor_sync(0xffffffffu, sr[k], 1);
            sr[k] += __shfl_xor_sync(0xffffffffu, sr[k], 2);
        }
        if (fc == 0) {
            int rows[4] = {wm + fr, wm + fr + 8, wm + 16 + fr, wm + 16 + fr + 8};
#pragma unroll
            for (int k = 0; k < 4; k++) {
                int r = row0 + rows[k];
                if (r < M) {
                    el[(size_t)r * 4 + head] = sl[k];
                    er[(size_t)r * 4 + head] = sr[k];
                }
            }
        }
    }
}

// ================= BN=64 GEMM body (layer 2 dual) =================
// OUTH=1: write fp16 C (feat path). OUTH=0: fp32 C (residual path).
template <int OUTH>
__device__ __forceinline__ void gemm_body64(const float* __restrict__ A,
                                            const float* __restrict__ B,
                                            void* __restrict__ Cv,
                                            int M, int N, int row0, int col0,
                                            const float* __restrict__ alh,
                                            const float* __restrict__ arh,
                                            float* __restrict__ el,
                                            float* __restrict__ er,
                                            bool do_elr) {
    const int K = 256;
    __shared__ unsigned As[2][128 * ASR_STRIDE];
    __shared__ unsigned Bs[2][16 * BS_STRIDE];
    __shared__ float s_elr[128][2];

    int tid  = threadIdx.x;
    int wid  = tid >> 5;
    int lane = tid & 31;

    int wm = (wid & 3) * 32;
    int wn = (wid >> 2) * 32;

    int arow  = tid >> 1;
    int afqb  = (tid & 1) * 2;
    int ar_g  = row0 + arow;
    bool avalid = (ar_g < M);

    int bkrow = tid >> 4;
    int bncol = (tid & 15) << 2;

    float acc[2][4][4];
#pragma unroll
    for (int i = 0; i < 2; i++)
#pragma unroll
        for (int j = 0; j < 4; j++)
#pragma unroll
            for (int v = 0; v < 4; v++) acc[i][j][v] = 0.f;

    int fr = lane >> 2;
    int fc = lane & 3;

    float4 ra[2], rb;
#pragma unroll
    for (int i = 0; i < 2; i++)
        ra[i] = avalid
            ? *reinterpret_cast<const float4*>(A + (size_t)ar_g * K + (afqb + i) * 4)
            : make_float4(0.f, 0.f, 0.f, 0.f);
    rb = *reinterpret_cast<const float4*>(B + (size_t)bkrow * N + col0 + bncol);

#pragma unroll
    for (int i = 0; i < 2; i++) {
        uint4 u = make_uint4(f2tf(ra[i].x), f2tf(ra[i].y), f2tf(ra[i].z), f2tf(ra[i].w));
        *reinterpret_cast<uint4*>(&As[0][arow * ASR_STRIDE + (afqb + i) * 4]) = u;
    }
    {
        uint4 u = make_uint4(f2tf(rb.x), f2tf(rb.y), f2tf(rb.z), f2tf(rb.w));
        *reinterpret_cast<uint4*>(&Bs[0][bkrow * BS_STRIDE + bncol]) = u;
    }
    __syncthreads();

    int buf = 0;
    for (int k0 = 0; k0 < K; k0 += 16) {
        bool has_next = (k0 + 16 < K);
        if (has_next) {
#pragma unroll
            for (int i = 0; i < 2; i++)
                ra[i] = avalid
                    ? *reinterpret_cast<const float4*>(
                          A + (size_t)ar_g * K + k0 + 16 + (afqb + i) * 4)
                    : make_float4(0.f, 0.f, 0.f, 0.f);
            rb = *reinterpret_cast<const float4*>(
                B + (size_t)(k0 + 16 + bkrow) * N + col0 + bncol);
        }

        const unsigned* Ab = As[buf];
        const unsigned* Bb = Bs[buf];
#pragma unroll
        for (int kt = 0; kt < 2; kt++) {
            int kb = kt * 8;
            unsigned a[2][4], b[4][2];
#pragma unroll
            for (int mt = 0; mt < 2; mt++) {
                int r = wm + mt * 16 + fr;
                a[mt][0] = Ab[r * ASR_STRIDE + kb + fc];
                a[mt][1] = Ab[(r + 8) * ASR_STRIDE + kb + fc];
                a[mt][2] = Ab[r * ASR_STRIDE + kb + fc + 4];
                a[mt][3] = Ab[(r + 8) * ASR_STRIDE + kb + fc + 4];
            }
#pragma unroll
            for (int nt = 0; nt < 4; nt++) {
                int c = wn + nt * 8 + fr;
                b[nt][0] = Bb[(kb + fc) * BS_STRIDE + c];
                b[nt][1] = Bb[(kb + fc + 4) * BS_STRIDE + c];
            }
#pragma unroll
            for (int mt = 0; mt < 2; mt++)
#pragma unroll
                for (int nt = 0; nt < 4; nt++) {
                    asm volatile(
                        "mma.sync.aligned.m16n8k8.row.col.f32.tf32.tf32.f32 "
                        "{%0,%1,%2,%3}, {%4,%5,%6,%7}, {%8,%9}, {%0,%1,%2,%3};\n"
                        : "+f"(acc[mt][nt][0]), "+f"(acc[mt][nt][1]),
                          "+f"(acc[mt][nt][2]), "+f"(acc[mt][nt][3])
                        : "r"(a[mt][0]), "r"(a[mt][1]), "r"(a[mt][2]), "r"(a[mt][3]),
                          "r"(b[nt][0]), "r"(b[nt][1]));
                }
        }

        if (has_next) {
#pragma unroll
            for (int i = 0; i < 2; i++) {
                uint4 u = make_uint4(f2tf(ra[i].x), f2tf(ra[i].y), f2tf(ra[i].z), f2tf(ra[i].w));
                *reinterpret_cast<uint4*>(&As[buf ^ 1][arow * ASR_STRIDE + (afqb + i) * 4]) = u;
            }
            uint4 u = make_uint4(f2tf(rb.x), f2tf(rb.y), f2tf(rb.z), f2tf(rb.w));
            *reinterpret_cast<uint4*>(&Bs[buf ^ 1][bkrow * BS_STRIDE + bncol]) = u;
            __syncthreads();
            buf ^= 1;
        }
    }

#pragma unroll
    for (int mt = 0; mt < 2; mt++) {
#pragma unroll
        for (int nt = 0; nt < 4; nt++) {
            int crow = row0 + wm + mt * 16 + fr;
            int ccol = col0 + wn + nt * 8 + 2 * fc;
            if (OUTH) {
                __half* C = (__half*)Cv;
                if (crow < M)
                    *reinterpret_cast<__half2*>(C + (size_t)crow * N + ccol) =
                        __floats2half2_rn(acc[mt][nt][0], acc[mt][nt][1]);
                if (crow + 8 < M)
                    *reinterpret_cast<__half2*>(C + (size_t)(crow + 8) * N + ccol) =
                        __floats2half2_rn(acc[mt][nt][2], acc[mt][nt][3]);
            } else {
                float* C = (float*)Cv;
                if (crow < M)
                    *reinterpret_cast<float2*>(C + (size_t)crow * N + ccol) =
                        make_float2(acc[mt][nt][0], acc[mt][nt][1]);
                if (crow + 8 < M)
                    *reinterpret_cast<float2*>(C + (size_t)(crow + 8) * N + ccol) =
                        make_float2(acc[mt][nt][2], acc[mt][nt][3]);
            }
        }
    }

    if (do_elr) {
        float sl[4] = {0.f, 0.f, 0.f, 0.f}, sr[4] = {0.f, 0.f, 0.f, 0.f};
#pragma unroll
        for (int mt = 0; mt < 2; mt++)
#pragma unroll
            for (int nt = 0; nt < 4; nt++) {
                int c = wn + nt * 8 + 2 * fc;
                float a0 = alh[c], a1 = alh[c + 1];
                float r0 = arh[c], r1 = arh[c + 1];
                sl[mt * 2 + 0] += acc[mt][nt][0] * a0 + acc[mt][nt][1] * a1;
                sr[mt * 2 + 0] += acc[mt][nt][0] * r0 + acc[mt][nt][1] * r1;
                sl[mt * 2 + 1] += acc[mt][nt][2] * a0 + acc[mt][nt][3] * a1;
                sr[mt * 2 + 1] += acc[mt][nt][2] * r0 + acc[mt][nt][3] * r1;
            }
#pragma unroll
        for (int k = 0; k < 4; k++) {
            sl[k] += __shfl_xor_sync(0xffffffffu, sl[k], 1);
            sl[k] += __shfl_xor_sync(0xffffffffu, sl[k], 2);
            sr[k] += __shfl_xor_sync(0xffffffffu, sr[k], 1);
            sr[k] += __shfl_xor_sync(0xffffffffu, sr[k], 2);
        }
        int nhalf = wid >> 2;
        int rows[4] = {wm + fr, wm + fr + 8, wm + 16 + fr, wm + 16 + fr + 8};
        if (nhalf == 0 && fc == 0) {
#pragma unroll
            for (int k = 0; k < 4; k++) {
                s_elr[rows[k]][0] = sl[k];
                s_elr[rows[k]][1] = sr[k];
            }
        }
        __syncthreads();
        if (nhalf == 1 && fc == 0) {
#pragma unroll
            for (int k = 0; k < 4; k++) {
                int r = row0 + rows[k];
                if (r < M) {
                    el[r] = s_elr[rows[k]][0] + sl[k];
                    er[r] = s_elr[rows[k]][1] + sr[k];
                }
            }
        }
    }
}

// layer-2 dual GEMM: x=0 -> W2 product (fp16 + el/er), x=1 -> res_w2 (fp32).
__global__ void __launch_bounds__(256) sgemm_tf32_dual_kernel(
        const float* __restrict__ A, const float* __restrict__ B0,
        const float* __restrict__ B1, __half* __restrict__ C0,
        float* __restrict__ C1, int M,
        const float* __restrict__ al, const float* __restrict__ ar,
        float* __restrict__ el, float* __restrict__ er) {
    if (blockIdx.x == 0)
        gemm_body64<1>(A, B0, C0, M, 64, blockIdx.y * 128, 0, al, ar, el, er, true);
    else
        gemm_body64<0>(A, B1, C1, M, 64, blockIdx.y * 128, 0, al, ar, el, er, false);
}

// ---------------- CSR build ----------------
__global__ void zero_deg_kernel(int* __restrict__ deg) {
    int i = blockIdx.x * blockDim.x + threadIdx.x;
    if (i < NN) deg[i] = 0;
}

__global__ void hist_kernel(const int* __restrict__ dst, int* __restrict__ deg) {
    int e = blockIdx.x * blockDim.x + threadIdx.x;
    if (e < NE) atomicAdd(&deg[dst[e]], 1);
}

__global__ void scan_kernel(int* __restrict__ deg_cursor, int* __restrict__ rowptr) {
    __shared__ int warp_sums[32];
    __shared__ int s_carry;
    int tid = threadIdx.x;  // 1024 threads
    if (tid == 0) s_carry = 0;
    __syncthreads();
    for (int base = 0; base < NN; base += 1024) {
        int i = base + tid;
        int v = (i < NN) ? deg_cursor[i] : 0;
        int x = v;
#pragma unroll
        for (int o = 1; o < 32; o <<= 1) {
            int y = __shfl_up_sync(0xffffffffu, x, o);
            if ((tid & 31) >= o) x += y;
        }
        if ((tid & 31) == 31) warp_sums[tid >> 5] = x;
        __syncthreads();
        if (tid < 32) {
            int s = warp_sums[tid];
#pragma unroll
            for (int o = 1; o < 32; o <<= 1) {
                int y = __shfl_up_sync(0xffffffffu, s, o);
                if (tid >= o) s += y;
            }
            warp_sums[tid] = s;
        }
        __syncthreads();
        int excl = x - v + ((tid >= 32) ? warp_sums[(tid >> 5) - 1] : 0);
        int val  = s_carry + excl;
        if (i < NN) { rowptr[i] = val; deg_cursor[i] = val; }
        int chunk_total = warp_sums[31];
        __syncthreads();
        if (tid == 0) s_carry += chunk_total;
        __syncthreads();
    }
    if (tid == 0) rowptr[NN] = NE;
}

__global__ void scatter_kernel(const int* __restrict__ src, const int* __restrict__ dst,
                               int* __restrict__ cursor, int* __restrict__ srcs) {
    int e = blockIdx.x * blockDim.x + threadIdx.x;
    if (e < NE) {
        int p = atomicAdd(&cursor[dst[e]], 1);
        srcs[p] = src[e];
    }
}

// ---------------- single-pass softmax-aggregate, H=4, fp16 feat ----------------
// Lane owns 8 consecutive cols (one uint4 of halfs), all within head lane>>3.
template <int ACT, int RES>
__global__ void __launch_bounds__(256) gat_agg4_kernel(
        const int* __restrict__ rowptr, const int* __restrict__ srcs,
        const float* __restrict__ el, const float* __restrict__ er,
        const __half* __restrict__ feat, const float* __restrict__ bias,
        const float* __restrict__ resid, float* __restrict__ out) {
    int w = blockIdx.x * (blockDim.x >> 5) + (threadIdx.x >> 5);
    if (w >= NN) return;
    int lane = threadIdx.x & 31;
    int start = rowptr[w], end = rowptr[w + 1];

    int h  = lane >> 3;          // head for this lane's 8 cols
    int c0 = 8 * lane;           // column base (halfs)
    float erv = er[(size_t)w * 4 + h];

    float acc[8] = {0.f, 0.f, 0.f, 0.f, 0.f, 0.f, 0.f, 0.f};
    float sd = 0.f;

    int sa = (start < end) ? srcs[start] : 0;
    int sb = (start + 1 < end) ? srcs[start + 1] : sa;
    float ev = (start < end) ? el[(size_t)sa * 4 + h] : 0.f;

    for (int i = start; i < end; i++) {
        int sc = (i + 2 < end) ? srcs[i + 2] : sb;
        float evN = (i + 1 < end) ? el[(size_t)sb * 4 + h] : ev;

        float v = ev + erv;
        v = (v > 0.f) ? v : 0.2f * v;
        float a = __expf(v);
        sd += a;

        uint4 u = *reinterpret_cast<const uint4*>(feat + (size_t)sa * 256 + c0);
        const __half2* hp = reinterpret_cast<const __half2*>(&u);
#pragma unroll
        for (int j = 0; j < 4; j++) {
            float2 f = __half22float2(hp[j]);
            acc[2 * j + 0] = fmaf(a, f.x, acc[2 * j + 0]);
            acc[2 * j + 1] = fmaf(a, f.y, acc[2 * j + 1]);
        }
        sa = sb; sb = sc; ev = evN;
    }

    float inv = (sd > 0.f) ? 1.f / sd : 0.f;
    float4 o0, o1;
    {
        float4 b0 = *reinterpret_cast<const float4*>(bias + c0);
        float4 b1 = *reinterpret_cast<const float4*>(bias + c0 + 4);
        o0 = make_float4(acc[0] * inv + b0.x, acc[1] * inv + b0.y,
                         acc[2] * inv + b0.z, acc[3] * inv + b0.w);
        o1 = make_float4(acc[4] * inv + b1.x, acc[5] * inv + b1.y,
                         acc[6] * inv + b1.z, acc[7] * inv + b1.w);
    }
    if (RES) {
        float4 r0 = *reinterpret_cast<const float4*>(resid + (size_t)w * 256 + c0);
        float4 r1 = *reinterpret_cast<const float4*>(resid + (size_t)w * 256 + c0 + 4);
        o0.x += r0.x; o0.y += r0.y; o0.z += r0.z; o0.w += r0.w;
        o1.x += r1.x; o1.y += r1.y; o1.z += r1.z; o1.w += r1.w;
    }
    if (ACT) {
        o0.x = (o0.x > 0.f) ? o0.x : expm1f(o0.x);
        o0.y = (o0.y > 0.f) ? o0.y : expm1f(o0.y);
        o0.z = (o0.z > 0.f) ? o0.z : expm1f(o0.z);
        o0.w = (o0.w > 0.f) ? o0.w : expm1f(o0.w);
        o1.x = (o1.x > 0.f) ? o1.x : expm1f(o1.x);
        o1.y = (o1.y > 0.f) ? o1.y : expm1f(o1.y);
        o1.z = (o1.z > 0.f) ? o1.z : expm1f(o1.z);
        o1.w = (o1.w > 0.f) ? o1.w : expm1f(o1.w);
    }
    *reinterpret_cast<float4*>(out + (size_t)w * 256 + c0)     = o0;
    *reinterpret_cast<float4*>(out + (size_t)w * 256 + c0 + 4) = o1;
}

// ---------------- single-pass softmax-aggregate, H=1, fp16 feat ----------------
__global__ void __launch_bounds__(256) gat_agg1_kernel(
        const int* __restrict__ rowptr, const int* __restrict__ srcs,
        const float* __restrict__ el, const float* __restrict__ er,
        const __half* __restrict__ feat, const float* __restrict__ bias,
        const float* __restrict__ resid, float* __restrict__ out) {
    int w = blockIdx.x * (blockDim.x >> 5) + (threadIdx.x >> 5);
    if (w >= NN) return;
    int lane = threadIdx.x & 31;
    int start = rowptr[w], end = rowptr[w + 1];
    float erv = er[w];

    int c0 = 2 * lane;
    float2 acc = make_float2(0.f, 0.f);
    float ssum = 0.f;

    int sa = (start < end) ? srcs[start] : 0;
    int sb = (start + 1 < end) ? srcs[start + 1] : sa;
    float eev = (start < end) ? el[sa] : 0.f;

    for (int i = start; i < end; i++) {
        int sc = (i + 2 < end) ? srcs[i + 2] : sb;
        float eeN = (i + 1 < end) ? el[sb] : eev;

        float v = eev + erv;
        v = (v > 0.f) ? v : 0.2f * v;
        float a = __expf(v);
        ssum += a;
        float2 f = __half22float2(*reinterpret_cast<const __half2*>(feat + (size_t)sa * 64 + c0));
        acc.x = fmaf(a, f.x, acc.x);
        acc.y = fmaf(a, f.y, acc.y);

        sa = sb; sb = sc; eev = eeN;
    }
    float inv = (ssum > 0.f) ? 1.f / ssum : 0.f;
    acc.x *= inv;
    acc.y *= inv;

    float2 b = *reinterpret_cast<const float2*>(bias + c0);
    float2 r = *reinterpret_cast<const float2*>(resid + (size_t)w * 64 + c0);
    acc.x += b.x + r.x;
    acc.y += b.y + r.y;
    *reinterpret_cast<float2*>(out + (size_t)w * 64 + c0) = acc;
}

// ---------------- host ----------------
extern "C" void kernel_launch(void* const* d_in, const int* in_sizes, int n_in,
                              void* d_out, int out_size) {
    const float* x    = (const float*)d_in[0];
    const int*   src  = (const int*)d_in[1];
    const int*   dst  = (const int*)d_in[2];
    const float* W0   = (const float*)d_in[3];
    const float* al0  = (const float*)d_in[4];
    const float* ar0  = (const float*)d_in[5];
    const float* b0   = (const float*)d_in[6];
    const float* W1   = (const float*)d_in[7];
    const float* al1  = (const float*)d_in[8];
    const float* ar1  = (const float*)d_in[9];
    const float* b1   = (const float*)d_in[10];
    const float* W2   = (const float*)d_in[11];
    const float* al2  = (const float*)d_in[12];
    const float* ar2  = (const float*)d_in[13];
    const float* b2   = (const float*)d_in[14];
    const float* rw2  = (const float*)d_in[15];
    float* out = (float*)d_out;

    __half* feat16;
    float *h1, *h2, *res2, *el, *er;
    int *rowptr, *cursor, *srcs;
    cudaGetSymbolAddress((void**)&feat16, g_feat16);
    cudaGetSymbolAddress((void**)&h1,     g_h1);
    cudaGetSymbolAddress((void**)&h2,     g_h2);
    cudaGetSymbolAddress((void**)&res2,   g_res2);
    cudaGetSymbolAddress((void**)&el,     g_el);
    cudaGetSymbolAddress((void**)&er,     g_er);
    cudaGetSymbolAddress((void**)&rowptr, g_rowptr);
    cudaGetSymbolAddress((void**)&cursor, g_cursor);
    cudaGetSymbolAddress((void**)&srcs,   g_srcs);

    static cudaStream_t s2 = nullptr;
    static cudaEvent_t ev_fork = nullptr, ev_join = nullptr;
    if (s2 == nullptr) {
        cudaStreamCreate(&s2);
        cudaEventCreateWithFlags(&ev_fork, cudaEventDisableTiming);
        cudaEventCreateWithFlags(&ev_join, cudaEventDisableTiming);
    }

    const int MTILES = (NN + 127) / 128;        // 391
    const int NODE_WARP_BLOCKS = (NN + 7) / 8;  // 6250

    // ---------- fork: CSR build on s2, layer-0 GEMM on main stream ----------
    cudaEventRecord(ev_fork, 0);
    cudaStreamWaitEvent(s2, ev_fork, 0);

    zero_deg_kernel<<<(NN + 255) / 256, 256, 0, s2>>>(cursor);
    hist_kernel<<<(NE + 255) / 256, 256, 0, s2>>>(dst, cursor);
    scan_kernel<<<1, 1024, 0, s2>>>(cursor, rowptr);
    scatter_kernel<<<(NE + 255) / 256, 256, 0, s2>>>(src, dst, cursor, srcs);
    cudaEventRecord(ev_join, s2);

    sgemm_tf32_elr128_kernel<<<dim3(2, MTILES), 256>>>(x, W0, feat16, NN, al0, ar0, el, er);

    cudaStreamWaitEvent(0, ev_join, 0);

    // ================= layer 0 aggregate =================
    gat_agg4_kernel<1, 0><<<NODE_WARP_BLOCKS, 256>>>(rowptr, srcs, el, er, feat16, b0, nullptr, h1);

    // ================= layer 1 =================
    sgemm_tf32_elr128_kernel<<<dim3(2, MTILES), 256>>>(h1, W1, feat16, NN, al1, ar1, el, er);
    gat_agg4_kernel<1, 1><<<NODE_WARP_BLOCKS, 256>>>(rowptr, srcs, el, er, feat16, b1, h1, h2);

    // ================= layer 2 =================
    sgemm_tf32_dual_kernel<<<dim3(2, MTILES), 256>>>(h2, W2, rw2, feat16, res2, NN, al2, ar2, el, er);
    gat_agg1_kernel<<<NODE_WARP_BLOCKS, 256>>>(rowptr, srcs, el, er, feat16, b2, res2, out);
}

// round 16
// speedup vs baseline: 5.2297x; 1.1308x over previous
#include <cuda_runtime.h>
#include <cuda_fp16.h>
#include <math_constants.h>

#define NN 50000
#define NE 800000

// ---------------- scratch (static device globals; no allocation) ----------------
__device__ __half g_feat16[NN * 256];   // fp16 features (gather payload)
__device__ __half g_h1[NN * 256];       // fp16 hidden state 1
__device__ __half g_h2[NN * 256];       // fp16 hidden state 2
__device__ float  g_res2[NN * 64];
__device__ float  g_el[NN * 4];
__device__ float  g_er[NN * 4];
__device__ int    g_rowptr[NN + 1];
__device__ int    g_cursor[NN];
__device__ int    g_srcs[NE];

__device__ __forceinline__ unsigned f2tf(float f) {
    unsigned u;
    asm("cvt.rna.tf32.f32 %0, %1;" : "=r"(u) : "f"(f));
    return u;
}

#define ASR_STRIDE 20
#define BS_STRIDE 72
#define BS_STRIDE2 136

// Convert 8 halfs (uint4) -> 8 tf32 words
__device__ __forceinline__ void h8_to_tf32(const uint4& u, unsigned o[8]) {
    const __half2* hp = reinterpret_cast<const __half2*>(&u);
#pragma unroll
    for (int j = 0; j < 4; j++) {
        float2 f = __half22float2(hp[j]);
        o[2 * j + 0] = f2tf(f.x);
        o[2 * j + 1] = f2tf(f.y);
    }
}

// ================= BN=128 GEMM for H=4 layers: BM=128,BN=128,BK=16 =================
// AHALF: A operand is fp16 (h1) vs fp32 (x). Writes C fp16. el/er warp-local per head.
template <int AHALF>
__global__ void __launch_bounds__(256) sgemm_tf32_elr128_kernel(
        const void* __restrict__ Av, const float* __restrict__ B,
        __half* __restrict__ C, int M,
        const float* __restrict__ al, const float* __restrict__ ar,
        float* __restrict__ el, float* __restrict__ er) {
    const int K = 256, N = 256;
    __shared__ unsigned As[2][128 * ASR_STRIDE];
    __shared__ unsigned Bs[2][16 * BS_STRIDE2];

    int tid  = threadIdx.x;
    int wid  = tid >> 5;
    int lane = tid & 31;
    int row0 = blockIdx.y * 128, col0 = blockIdx.x * 128;

    int wm = (wid & 3) * 32;
    int wn = (wid >> 2) * 64;
    int head = (col0 >> 6) + (wid >> 2);

    int arow  = tid >> 1;
    int ahalf = tid & 1;           // which 8-k half of the 16-k chunk
    int ar_g  = row0 + arow;
    bool avalid = (ar_g < M);

    const float*  Af = (const float*)Av;
    const __half* Ah = (const __half*)Av;

    float acc[2][8][4];
#pragma unroll
    for (int i = 0; i < 2; i++)
#pragma unroll
        for (int j = 0; j < 8; j++)
#pragma unroll
            for (int v = 0; v < 4; v++) acc[i][j][v] = 0.f;

    int fr = lane >> 2;
    int fc = lane & 3;

    float4 ra[2];
    uint4  rah;
    float4 rb[2];

    // ---- prologue: load k-chunk 0 ----
    if (AHALF) {
        rah = avalid
            ? *reinterpret_cast<const uint4*>(Ah + (size_t)ar_g * K + ahalf * 8)
            : make_uint4(0u, 0u, 0u, 0u);
    } else {
#pragma unroll
        for (int i = 0; i < 2; i++)
            ra[i] = avalid
                ? *reinterpret_cast<const float4*>(Af + (size_t)ar_g * K + (ahalf * 2 + i) * 4)
                : make_float4(0.f, 0.f, 0.f, 0.f);
    }
#pragma unroll
    for (int j = 0; j < 2; j++) {
        int idx  = tid + j * 256;
        int krow = idx >> 5;
        int ncol = (idx & 31) << 2;
        rb[j] = *reinterpret_cast<const float4*>(B + (size_t)krow * N + col0 + ncol);
    }
    // store chunk 0
    if (AHALF) {
        unsigned o[8];
        h8_to_tf32(rah, o);
#pragma unroll
        for (int i = 0; i < 2; i++) {
            uint4 u = make_uint4(o[4 * i + 0], o[4 * i + 1], o[4 * i + 2], o[4 * i + 3]);
            *reinterpret_cast<uint4*>(&As[0][arow * ASR_STRIDE + ahalf * 8 + i * 4]) = u;
        }
    } else {
#pragma unroll
        for (int i = 0; i < 2; i++) {
            uint4 u = make_uint4(f2tf(ra[i].x), f2tf(ra[i].y), f2tf(ra[i].z), f2tf(ra[i].w));
            *reinterpret_cast<uint4*>(&As[0][arow * ASR_STRIDE + (ahalf * 2 + i) * 4]) = u;
        }
    }
#pragma unroll
    for (int j = 0; j < 2; j++) {
        int idx  = tid + j * 256;
        int krow = idx >> 5;
        int ncol = (idx & 31) << 2;
        uint4 u = make_uint4(f2tf(rb[j].x), f2tf(rb[j].y), f2tf(rb[j].z), f2tf(rb[j].w));
        *reinterpret_cast<uint4*>(&Bs[0][krow * BS_STRIDE2 + ncol]) = u;
    }
    __syncthreads();

    int buf = 0;
    for (int k0 = 0; k0 < K; k0 += 16) {
        bool has_next = (k0 + 16 < K);
        if (has_next) {
            if (AHALF) {
                rah = avalid
                    ? *reinterpret_cast<const uint4*>(Ah + (size_t)ar_g * K + k0 + 16 + ahalf * 8)
                    : make_uint4(0u, 0u, 0u, 0u);
            } else {
#pragma unroll
                for (int i = 0; i < 2; i++)
                    ra[i] = avalid
                        ? *reinterpret_cast<const float4*>(
                              Af + (size_t)ar_g * K + k0 + 16 + (ahalf * 2 + i) * 4)
                        : make_float4(0.f, 0.f, 0.f, 0.f);
            }
#pragma unroll
            for (int j = 0; j < 2; j++) {
                int idx  = tid + j * 256;
                int krow = idx >> 5;
                int ncol = (idx & 31) << 2;
                rb[j] = *reinterpret_cast<const float4*>(
                    B + (size_t)(k0 + 16 + krow) * N + col0 + ncol);
            }
        }

        const unsigned* Ab = As[buf];
        const unsigned* Bb = Bs[buf];
#pragma unroll
        for (int kt = 0; kt < 2; kt++) {
            int kb = kt * 8;
            unsigned a[2][4], b[8][2];
#pragma unroll
            for (int mt = 0; mt < 2; mt++) {
                int r = wm + mt * 16 + fr;
                a[mt][0] = Ab[r * ASR_STRIDE + kb + fc];
                a[mt][1] = Ab[(r + 8) * ASR_STRIDE + kb + fc];
                a[mt][2] = Ab[r * ASR_STRIDE + kb + fc + 4];
                a[mt][3] = Ab[(r + 8) * ASR_STRIDE + kb + fc + 4];
            }
#pragma unroll
            for (int nt = 0; nt < 8; nt++) {
                int c = wn + nt * 8 + fr;
                b[nt][0] = Bb[(kb + fc) * BS_STRIDE2 + c];
                b[nt][1] = Bb[(kb + fc + 4) * BS_STRIDE2 + c];
            }
#pragma unroll
            for (int mt = 0; mt < 2; mt++)
#pragma unroll
                for (int nt = 0; nt < 8; nt++) {
                    asm volatile(
                        "mma.sync.aligned.m16n8k8.row.col.f32.tf32.tf32.f32 "
                        "{%0,%1,%2,%3}, {%4,%5,%6,%7}, {%8,%9}, {%0,%1,%2,%3};\n"
                        : "+f"(acc[mt][nt][0]), "+f"(acc[mt][nt][1]),
                          "+f"(acc[mt][nt][2]), "+f"(acc[mt][nt][3])
                        : "r"(a[mt][0]), "r"(a[mt][1]), "r"(a[mt][2]), "r"(a[mt][3]),
                          "r"(b[nt][0]), "r"(b[nt][1]));
                }
        }

        if (has_next) {
            if (AHALF) {
                unsigned o[8];
                h8_to_tf32(rah, o);
#pragma unroll
                for (int i = 0; i < 2; i++) {
                    uint4 u = make_uint4(o[4 * i + 0], o[4 * i + 1], o[4 * i + 2], o[4 * i + 3]);
                    *reinterpret_cast<uint4*>(&As[buf ^ 1][arow * ASR_STRIDE + ahalf * 8 + i * 4]) = u;
                }
            } else {
#pragma unroll
                for (int i = 0; i < 2; i++) {
                    uint4 u = make_uint4(f2tf(ra[i].x), f2tf(ra[i].y), f2tf(ra[i].z), f2tf(ra[i].w));
                    *reinterpret_cast<uint4*>(&As[buf ^ 1][arow * ASR_STRIDE + (ahalf * 2 + i) * 4]) = u;
                }
            }
#pragma unroll
            for (int j = 0; j < 2; j++) {
                int idx  = tid + j * 256;
                int krow = idx >> 5;
                int ncol = (idx & 31) << 2;
                uint4 u = make_uint4(f2tf(rb[j].x), f2tf(rb[j].y), f2tf(rb[j].z), f2tf(rb[j].w));
                *reinterpret_cast<uint4*>(&Bs[buf ^ 1][krow * BS_STRIDE2 + ncol]) = u;
            }
            __syncthreads();
            buf ^= 1;
        }
    }

    // ---- C writeback (fp16) ----
#pragma unroll
    for (int mt = 0; mt < 2; mt++) {
#pragma unroll
        for (int nt = 0; nt < 8; nt++) {
            int crow = row0 + wm + mt * 16 + fr;
            int ccol = col0 + wn + nt * 8 + 2 * fc;
            if (crow < M)
                *reinterpret_cast<__half2*>(C + (size_t)crow * N + ccol) =
                    __floats2half2_rn(acc[mt][nt][0], acc[mt][nt][1]);
            if (crow + 8 < M)
                *reinterpret_cast<__half2*>(C + (size_t)(crow + 8) * N + ccol) =
                    __floats2half2_rn(acc[mt][nt][2], acc[mt][nt][3]);
        }
    }

    // ---- fused el/er (fp32 accumulators, warp-local) ----
    {
        const float* alh = al + head * 64;
        const float* arh = ar + head * 64;
        float sl[4] = {0.f, 0.f, 0.f, 0.f}, sr[4] = {0.f, 0.f, 0.f, 0.f};
#pragma unroll
        for (int mt = 0; mt < 2; mt++)
#pragma unroll
            for (int nt = 0; nt < 8; nt++) {
                int c = nt * 8 + 2 * fc;
                float a0 = alh[c], a1 = alh[c + 1];
                float r0 = arh[c], r1 = arh[c + 1];
                sl[mt * 2 + 0] += acc[mt][nt][0] * a0 + acc[mt][nt][1] * a1;
                sr[mt * 2 + 0] += acc[mt][nt][0] * r0 + acc[mt][nt][1] * r1;
                sl[mt * 2 + 1] += acc[mt][nt][2] * a0 + acc[mt][nt][3] * a1;
                sr[mt * 2 + 1] += acc[mt][nt][2] * r0 + acc[mt][nt][3] * r1;
            }
#pragma unroll
        for (int k = 0; k < 4; k++) {
            sl[k] += __shfl_xor_sync(0xffffffffu, sl[k], 1);
            sl[k] += __shfl_xor_sync(0xffffffffu, sl[k], 2);
            sr[k] += __shfl_xor_sync(0xffffffffu, sr[k], 1);
            sr[k] += __shfl_xor_sync(0xffffffffu, sr[k], 2);
        }
        if (fc == 0) {
            int rows[4] = {wm + fr, wm + fr + 8, wm + 16 + fr, wm + 16 + fr + 8};
#pragma unroll
            for (int k = 0; k < 4; k++) {
                int r = row0 + rows[k];
                if (r < M) {
                    el[(size_t)r * 4 + head] = sl[k];
                    er[(size_t)r * 4 + head] = sr[k];
                }
            }
        }
    }
}

// ================= BN=64 GEMM body (layer 2 dual): A fp16 =================
// OUTH=1: C fp16 (feat path, + el/er). OUTH=0: C fp32 (residual path).
template <int OUTH>
__device__ __forceinline__ void gemm_body64(const __half* __restrict__ A,
                                            const float* __restrict__ B,
                                            void* __restrict__ Cv,
                                            int M, int N, int row0,
                                            const float* __restrict__ alh,
                                            const float* __restrict__ arh,
                                            float* __restrict__ el,
                                            float* __restrict__ er,
                                            bool do_elr) {
    const int K = 256;
    __shared__ unsigned As[2][128 * ASR_STRIDE];
    __shared__ unsigned Bs[2][16 * BS_STRIDE];
    __shared__ float s_elr[128][2];

    int tid  = threadIdx.x;
    int wid  = tid >> 5;
    int lane = tid & 31;

    int wm = (wid & 3) * 32;
    int wn = (wid >> 2) * 32;

    int arow  = tid >> 1;
    int ahalf = tid & 1;
    int ar_g  = row0 + arow;
    bool avalid = (ar_g < M);

    int bkrow = tid >> 4;
    int bncol = (tid & 15) << 2;

    float acc[2][4][4];
#pragma unroll
    for (int i = 0; i < 2; i++)
#pragma unroll
        for (int j = 0; j < 4; j++)
#pragma unroll
            for (int v = 0; v < 4; v++) acc[i][j][v] = 0.f;

    int fr = lane >> 2;
    int fc = lane & 3;

    uint4 rah;
    float4 rb;
    rah = avalid
        ? *reinterpret_cast<const uint4*>(A + (size_t)ar_g * K + ahalf * 8)
        : make_uint4(0u, 0u, 0u, 0u);
    rb = *reinterpret_cast<const float4*>(B + (size_t)bkrow * N + bncol);

    {
        unsigned o[8];
        h8_to_tf32(rah, o);
#pragma unroll
        for (int i = 0; i < 2; i++) {
            uint4 u = make_uint4(o[4 * i + 0], o[4 * i + 1], o[4 * i + 2], o[4 * i + 3]);
            *reinterpret_cast<uint4*>(&As[0][arow * ASR_STRIDE + ahalf * 8 + i * 4]) = u;
        }
        uint4 ub = make_uint4(f2tf(rb.x), f2tf(rb.y), f2tf(rb.z), f2tf(rb.w));
        *reinterpret_cast<uint4*>(&Bs[0][bkrow * BS_STRIDE + bncol]) = ub;
    }
    __syncthreads();

    int buf = 0;
    for (int k0 = 0; k0 < K; k0 += 16) {
        bool has_next = (k0 + 16 < K);
        if (has_next) {
            rah = avalid
                ? *reinterpret_cast<const uint4*>(A + (size_t)ar_g * K + k0 + 16 + ahalf * 8)
                : make_uint4(0u, 0u, 0u, 0u);
            rb = *reinterpret_cast<const float4*>(B + (size_t)(k0 + 16 + bkrow) * N + bncol);
        }

        const unsigned* Ab = As[buf];
        const unsigned* Bb = Bs[buf];
#pragma unroll
        for (int kt = 0; kt < 2; kt++) {
            int kb = kt * 8;
            unsigned a[2][4], b[4][2];
#pragma unroll
            for (int mt = 0; mt < 2; mt++) {
                int r = wm + mt * 16 + fr;
                a[mt][0] = Ab[r * ASR_STRIDE + kb + fc];
                a[mt][1] = Ab[(r + 8) * ASR_STRIDE + kb + fc];
                a[mt][2] = Ab[r * ASR_STRIDE + kb + fc + 4];
                a[mt][3] = Ab[(r + 8) * ASR_STRIDE + kb + fc + 4];
            }
#pragma unroll
            for (int nt = 0; nt < 4; nt++) {
                int c = wn + nt * 8 + fr;
                b[nt][0] = Bb[(kb + fc) * BS_STRIDE + c];
                b[nt][1] = Bb[(kb + fc + 4) * BS_STRIDE + c];
            }
#pragma unroll
            for (int mt = 0; mt < 2; mt++)
#pragma unroll
                for (int nt = 0; nt < 4; nt++) {
                    asm volatile(
                        "mma.sync.aligned.m16n8k8.row.col.f32.tf32.tf32.f32 "
                        "{%0,%1,%2,%3}, {%4,%5,%6,%7}, {%8,%9}, {%0,%1,%2,%3};\n"
                        : "+f"(acc[mt][nt][0]), "+f"(acc[mt][nt][1]),
                          "+f"(acc[mt][nt][2]), "+f"(acc[mt][nt][3])
                        : "r"(a[mt][0]), "r"(a[mt][1]), "r"(a[mt][2]), "r"(a[mt][3]),
                          "r"(b[nt][0]), "r"(b[nt][1]));
                }
        }

        if (has_next) {
            unsigned o[8];
            h8_to_tf32(rah, o);
#pragma unroll
            for (int i = 0; i < 2; i++) {
                uint4 u = make_uint4(o[4 * i + 0], o[4 * i + 1], o[4 * i + 2], o[4 * i + 3]);
                *reinterpret_cast<uint4*>(&As[buf ^ 1][arow * ASR_STRIDE + ahalf * 8 + i * 4]) = u;
            }
            uint4 ub = make_uint4(f2tf(rb.x), f2tf(rb.y), f2tf(rb.z), f2tf(rb.w));
            *reinterpret_cast<uint4*>(&Bs[buf ^ 1][bkrow * BS_STRIDE + bncol]) = ub;
            __syncthreads();
            buf ^= 1;
        }
    }

#pragma unroll
    for (int mt = 0; mt < 2; mt++) {
#pragma unroll
        for (int nt = 0; nt < 4; nt++) {
            int crow = row0 + wm + mt * 16 + fr;
            int ccol = wn + nt * 8 + 2 * fc;
            if (OUTH) {
                __half* C = (__half*)Cv;
                if (crow < M)
                    *reinterpret_cast<__half2*>(C + (size_t)crow * N + ccol) =
                        __floats2half2_rn(acc[mt][nt][0], acc[mt][nt][1]);
                if (crow + 8 < M)
                    *reinterpret_cast<__half2*>(C + (size_t)(crow + 8) * N + ccol) =
                        __floats2half2_rn(acc[mt][nt][2], acc[mt][nt][3]);
            } else {
                float* C = (float*)Cv;
                if (crow < M)
                    *reinterpret_cast<float2*>(C + (size_t)crow * N + ccol) =
                        make_float2(acc[mt][nt][0], acc[mt][nt][1]);
                if (crow + 8 < M)
                    *reinterpret_cast<float2*>(C + (size_t)(crow + 8) * N + ccol) =
                        make_float2(acc[mt][nt][2], acc[mt][nt][3]);
            }
        }
    }

    if (do_elr) {
        float sl[4] = {0.f, 0.f, 0.f, 0.f}, sr[4] = {0.f, 0.f, 0.f, 0.f};
#pragma unroll
        for (int mt = 0; mt < 2; mt++)
#pragma unroll
            for (int nt = 0; nt < 4; nt++) {
                int c = wn + nt * 8 + 2 * fc;
                float a0 = alh[c], a1 = alh[c + 1];
                float r0 = arh[c], r1 = arh[c + 1];
                sl[mt * 2 + 0] += acc[mt][nt][0] * a0 + acc[mt][nt][1] * a1;
                sr[mt * 2 + 0] += acc[mt][nt][0] * r0 + acc[mt][nt][1] * r1;
                sl[mt * 2 + 1] += acc[mt][nt][2] * a0 + acc[mt][nt][3] * a1;
                sr[mt * 2 + 1] += acc[mt][nt][2] * r0 + acc[mt][nt][3] * r1;
            }
#pragma unroll
        for (int k = 0; k < 4; k++) {
            sl[k] += __shfl_xor_sync(0xffffffffu, sl[k], 1);
            sl[k] += __shfl_xor_sync(0xffffffffu, sl[k], 2);
            sr[k] += __shfl_xor_sync(0xffffffffu, sr[k], 1);
            sr[k] += __shfl_xor_sync(0xffffffffu, sr[k], 2);
        }
        int nhalf = wid >> 2;
        int rows[4] = {wm + fr, wm + fr + 8, wm + 16 + fr, wm + 16 + fr + 8};
        if (nhalf == 0 && fc == 0) {
#pragma unroll
            for (int k = 0; k < 4; k++) {
                s_elr[rows[k]][0] = sl[k];
                s_elr[rows[k]][1] = sr[k];
            }
        }
        __syncthreads();
        if (nhalf == 1 && fc == 0) {
#pragma unroll
            for (int k = 0; k < 4; k++) {
                int r = row0 + rows[k];
                if (r < M) {
                    el[r] = s_elr[rows[k]][0] + sl[k];
                    er[r] = s_elr[rows[k]][1] + sr[k];
                }
            }
        }
    }
}

__global__ void __launch_bounds__(256) sgemm_tf32_dual_kernel(
        const __half* __restrict__ A, const float* __restrict__ B0,
        const float* __restrict__ B1, __half* __restrict__ C0,
        float* __restrict__ C1, int M,
        const float* __restrict__ al, const float* __restrict__ ar,
        float* __restrict__ el, float* __restrict__ er) {
    if (blockIdx.x == 0)
        gemm_body64<1>(A, B0, C0, M, 64, blockIdx.y * 128, al, ar, el, er, true);
    else
        gemm_body64<0>(A, B1, C1, M, 64, blockIdx.y * 128, al, ar, el, er, false);
}

// ---------------- CSR build ----------------
__global__ void zero_deg_kernel(int* __restrict__ deg) {
    int i = blockIdx.x * blockDim.x + threadIdx.x;
    if (i < NN) deg[i] = 0;
}

__global__ void hist_kernel(const int* __restrict__ dst, int* __restrict__ deg) {
    int e = blockIdx.x * blockDim.x + threadIdx.x;
    if (e < NE) atomicAdd(&deg[dst[e]], 1);
}

__global__ void scan_kernel(int* __restrict__ deg_cursor, int* __restrict__ rowptr) {
    __shared__ int warp_sums[32];
    __shared__ int s_carry;
    int tid = threadIdx.x;  // 1024 threads
    if (tid == 0) s_carry = 0;
    __syncthreads();
    for (int base = 0; base < NN; base += 1024) {
        int i = base + tid;
        int v = (i < NN) ? deg_cursor[i] : 0;
        int x = v;
#pragma unroll
        for (int o = 1; o < 32; o <<= 1) {
            int y = __shfl_up_sync(0xffffffffu, x, o);
            if ((tid & 31) >= o) x += y;
        }
        if ((tid & 31) == 31) warp_sums[tid >> 5] = x;
        __syncthreads();
        if (tid < 32) {
            int s = warp_sums[tid];
#pragma unroll
            for (int o = 1; o < 32; o <<= 1) {
                int y = __shfl_up_sync(0xffffffffu, s, o);
                if (tid >= o) s += y;
            }
            warp_sums[tid] = s;
        }
        __syncthreads();
        int excl = x - v + ((tid >= 32) ? warp_sums[(tid >> 5) - 1] : 0);
        int val  = s_carry + excl;
        if (i < NN) { rowptr[i] = val; deg_cursor[i] = val; }
        int chunk_total = warp_sums[31];
        __syncthreads();
        if (tid == 0) s_carry += chunk_total;
        __syncthreads();
    }
    if (tid == 0) rowptr[NN] = NE;
}

__global__ void scatter_kernel(const int* __restrict__ src, const int* __restrict__ dst,
                               int* __restrict__ cursor, int* __restrict__ srcs) {
    int e = blockIdx.x * blockDim.x + threadIdx.x;
    if (e < NE) {
        int p = atomicAdd(&cursor[dst[e]], 1);
        srcs[p] = src[e];
    }
}

// ---------------- single-pass softmax-aggregate, H=4, fp16 feat, unroll-2 ----------------
// Lane owns 8 consecutive cols (one uint4 of halfs), all within head lane>>3.
// RESH: residual is fp16 (h1). OUT fp16 (h1/h2).
template <int ACT, int RES>
__global__ void __launch_bounds__(256) gat_agg4_kernel(
        const int* __restrict__ rowptr, const int* __restrict__ srcs,
        const float* __restrict__ el, const float* __restrict__ er,
        const __half* __restrict__ feat, const float* __restrict__ bias,
        const __half* __restrict__ resid, __half* __restrict__ out) {
    int w = blockIdx.x * (blockDim.x >> 5) + (threadIdx.x >> 5);
    if (w >= NN) return;
    int lane = threadIdx.x & 31;
    int start = rowptr[w], end = rowptr[w + 1];

    int h  = lane >> 3;
    int c0 = 8 * lane;
    float erv = er[(size_t)w * 4 + h];

    float acc[8] = {0.f, 0.f, 0.f, 0.f, 0.f, 0.f, 0.f, 0.f};
    float sd = 0.f;

    int i = start;
    for (; i + 1 < end; i += 2) {
        int s0 = srcs[i];
        int s1 = srcs[i + 1];
        float ev0 = el[(size_t)s0 * 4 + h];
        float ev1 = el[(size_t)s1 * 4 + h];
        uint4 u0 = *reinterpret_cast<const uint4*>(feat + (size_t)s0 * 256 + c0);
        uint4 u1 = *reinterpret_cast<const uint4*>(feat + (size_t)s1 * 256 + c0);

        float v0 = ev0 + erv; v0 = (v0 > 0.f) ? v0 : 0.2f * v0;
        float v1 = ev1 + erv; v1 = (v1 > 0.f) ? v1 : 0.2f * v1;
        float a0 = __expf(v0);
        float a1 = __expf(v1);
        sd += a0 + a1;

        const __half2* h0 = reinterpret_cast<const __half2*>(&u0);
        const __half2* h1p = reinterpret_cast<const __half2*>(&u1);
#pragma unroll
        for (int j = 0; j < 4; j++) {
            float2 f0 = __half22float2(h0[j]);
            float2 f1 = __half22float2(h1p[j]);
            acc[2 * j + 0] = fmaf(a0, f0.x, fmaf(a1, f1.x, acc[2 * j + 0]));
            acc[2 * j + 1] = fmaf(a0, f0.y, fmaf(a1, f1.y, acc[2 * j + 1]));
        }
    }
    if (i < end) {
        int s0 = srcs[i];
        float ev0 = el[(size_t)s0 * 4 + h];
        float v0 = ev0 + erv; v0 = (v0 > 0.f) ? v0 : 0.2f * v0;
        float a0 = __expf(v0);
        sd += a0;
        uint4 u0 = *reinterpret_cast<const uint4*>(feat + (size_t)s0 * 256 + c0);
        const __half2* h0 = reinterpret_cast<const __half2*>(&u0);
#pragma unroll
        for (int j = 0; j < 4; j++) {
            float2 f0 = __half22float2(h0[j]);
            acc[2 * j + 0] = fmaf(a0, f0.x, acc[2 * j + 0]);
            acc[2 * j + 1] = fmaf(a0, f0.y, acc[2 * j + 1]);
        }
    }

    float inv = (sd > 0.f) ? 1.f / sd : 0.f;
    float o[8];
    {
        float4 b0 = *reinterpret_cast<const float4*>(bias + c0);
        float4 b1 = *reinterpret_cast<const float4*>(bias + c0 + 4);
        o[0] = acc[0] * inv + b0.x; o[1] = acc[1] * inv + b0.y;
        o[2] = acc[2] * inv + b0.z; o[3] = acc[3] * inv + b0.w;
        o[4] = acc[4] * inv + b1.x; o[5] = acc[5] * inv + b1.y;
        o[6] = acc[6] * inv + b1.z; o[7] = acc[7] * inv + b1.w;
    }
    if (RES) {
        uint4 ur = *reinterpret_cast<const uint4*>(resid + (size_t)w * 256 + c0);
        const __half2* hr = reinterpret_cast<const __half2*>(&ur);
#pragma unroll
        for (int j = 0; j < 4; j++) {
            float2 f = __half22float2(hr[j]);
            o[2 * j + 0] += f.x;
            o[2 * j + 1] += f.y;
        }
    }
    if (ACT) {
#pragma unroll
        for (int j = 0; j < 8; j++)
            o[j] = (o[j] > 0.f) ? o[j] : expm1f(o[j]);
    }
    __half2 packed[4];
#pragma unroll
    for (int j = 0; j < 4; j++)
        packed[j] = __floats2half2_rn(o[2 * j], o[2 * j + 1]);
    *reinterpret_cast<uint4*>(out + (size_t)w * 256 + c0) =
        *reinterpret_cast<const uint4*>(packed);
}

// ---------------- single-pass softmax-aggregate, H=1, fp16 feat, unroll-2 ----------------
__global__ void __launch_bounds__(256) gat_agg1_kernel(
        const int* __restrict__ rowptr, const int* __restrict__ srcs,
        const float* __restrict__ el, const float* __restrict__ er,
        const __half* __restrict__ feat, const float* __restrict__ bias,
        const float* __restrict__ resid, float* __restrict__ out) {
    int w = blockIdx.x * (blockDim.x >> 5) + (threadIdx.x >> 5);
    if (w >= NN) return;
    int lane = threadIdx.x & 31;
    int start = rowptr[w], end = rowptr[w + 1];
    float erv = er[w];

    int c0 = 2 * lane;
    float2 acc = make_float2(0.f, 0.f);
    float ssum = 0.f;

    int i = start;
    for (; i + 1 < end; i += 2) {
        int s0 = srcs[i];
        int s1 = srcs[i + 1];
        float e0 = el[s0];
        float e1 = el[s1];
        __half2 q0 = *reinterpret_cast<const __half2*>(feat + (size_t)s0 * 64 + c0);
        __half2 q1 = *reinterpret_cast<const __half2*>(feat + (size_t)s1 * 64 + c0);

        float v0 = e0 + erv; v0 = (v0 > 0.f) ? v0 : 0.2f * v0;
        float v1 = e1 + erv; v1 = (v1 > 0.f) ? v1 : 0.2f * v1;
        float a0 = __expf(v0);
        float a1 = __expf(v1);
        ssum += a0 + a1;
        float2 f0 = __half22float2(q0);
        float2 f1 = __half22float2(q1);
        acc.x = fmaf(a0, f0.x, fmaf(a1, f1.x, acc.x));
        acc.y = fmaf(a0, f0.y, fmaf(a1, f1.y, acc.y));
    }
    if (i < end) {
        int s0 = srcs[i];
        float e0 = el[s0];
        float v0 = e0 + erv; v0 = (v0 > 0.f) ? v0 : 0.2f * v0;
        float a0 = __expf(v0);
        ssum += a0;
        float2 f0 = __half22float2(*reinterpret_cast<const __half2*>(feat + (size_t)s0 * 64 + c0));
        acc.x = fmaf(a0, f0.x, acc.x);
        acc.y = fmaf(a0, f0.y, acc.y);
    }
    float inv = (ssum > 0.f) ? 1.f / ssum : 0.f;
    acc.x *= inv;
    acc.y *= inv;

    float2 b = *reinterpret_cast<const float2*>(bias + c0);
    float2 r = *reinterpret_cast<const float2*>(resid + (size_t)w * 64 + c0);
    acc.x += b.x + r.x;
    acc.y += b.y + r.y;
    *reinterpret_cast<float2*>(out + (size_t)w * 64 + c0) = acc;
}

// ---------------- host ----------------
extern "C" void kernel_launch(void* const* d_in, const int* in_sizes, int n_in,
                              void* d_out, int out_size) {
    const float* x    = (const float*)d_in[0];
    const int*   src  = (const int*)d_in[1];
    const int*   dst  = (const int*)d_in[2];
    const float* W0   = (const float*)d_in[3];
    const float* al0  = (const float*)d_in[4];
    const float* ar0  = (const float*)d_in[5];
    const float* b0   = (const float*)d_in[6];
    const float* W1   = (const float*)d_in[7];
    const float* al1  = (const float*)d_in[8];
    const float* ar1  = (const float*)d_in[9];
    const float* b1   = (const float*)d_in[10];
    const float* W2   = (const float*)d_in[11];
    const float* al2  = (const float*)d_in[12];
    const float* ar2  = (const float*)d_in[13];
    const float* b2   = (const float*)d_in[14];
    const float* rw2  = (const float*)d_in[15];
    float* out = (float*)d_out;

    __half *feat16, *h1, *h2;
    float *res2, *el, *er;
    int *rowptr, *cursor, *srcs;
    cudaGetSymbolAddress((void**)&feat16, g_feat16);
    cudaGetSymbolAddress((void**)&h1,     g_h1);
    cudaGetSymbolAddress((void**)&h2,     g_h2);
    cudaGetSymbolAddress((void**)&res2,   g_res2);
    cudaGetSymbolAddress((void**)&el,     g_el);
    cudaGetSymbolAddress((void**)&er,     g_er);
    cudaGetSymbolAddress((void**)&rowptr, g_rowptr);
    cudaGetSymbolAddress((void**)&cursor, g_cursor);
    cudaGetSymbolAddress((void**)&srcs,   g_srcs);

    static cudaStream_t s2 = nullptr;
    static cudaEvent_t ev_fork = nullptr, ev_join = nullptr;
    if (s2 == nullptr) {
        cudaStreamCreate(&s2);
        cudaEventCreateWithFlags(&ev_fork, cudaEventDisableTiming);
        cudaEventCreateWithFlags(&ev_join, cudaEventDisableTiming);
    }

    const int MTILES = (NN + 127) / 128;        // 391
    const int NODE_WARP_BLOCKS = (NN + 7) / 8;  // 6250

    // ---------- fork: CSR build on s2, layer-0 GEMM on main stream ----------
    cudaEventRecord(ev_fork, 0);
    cudaStreamWaitEvent(s2, ev_fork, 0);

    zero_deg_kernel<<<(NN + 255) / 256, 256, 0, s2>>>(cursor);
    hist_kernel<<<(NE + 255) / 256, 256, 0, s2>>>(dst, cursor);
    scan_kernel<<<1, 1024, 0, s2>>>(cursor, rowptr);
    scatter_kernel<<<(NE + 255) / 256, 256, 0, s2>>>(src, dst, cursor, srcs);
    cudaEventRecord(ev_join, s2);

    sgemm_tf32_elr128_kernel<0><<<dim3(2, MTILES), 256>>>(x, W0, feat16, NN, al0, ar0, el, er);

    cudaStreamWaitEvent(0, ev_join, 0);

    // ================= layer 0 aggregate =================
    gat_agg4_kernel<1, 0><<<NODE_WARP_BLOCKS, 256>>>(rowptr, srcs, el, er, feat16, b0, nullptr, h1);

    // ================= layer 1 =================
    sgemm_tf32_elr128_kernel<1><<<dim3(2, MTILES), 256>>>(h1, W1, feat16, NN, al1, ar1, el, er);
    gat_agg4_kernel<1, 1><<<NODE_WARP_BLOCKS, 256>>>(rowptr, srcs, el, er, feat16, b1, h1, h2);

    // ================= layer 2 =================
    sgemm_tf32_dual_kernel<<<dim3(2, MTILES), 256>>>(h2, W2, rw2, feat16, res2, NN, al2, ar2, el, er);
    gat_agg1_kernel<<<NODE_WARP_BLOCKS, 256>>>(rowptr, srcs, el, er, feat16, b2, res2, out);
}

// round 17
// speedup vs baseline: 5.7983x; 1.1087x over previous
#include <cuda_runtime.h>
#include <cuda_fp16.h>
#include <math_constants.h>

#define NN 50000
#define NE 800000

// ---------------- scratch (static device globals; no allocation) ----------------
__device__ __half g_feat16[NN * 256];
__device__ __half g_h1[NN * 256];
__device__ __half g_h2[NN * 256];
__device__ float  g_res2[NN * 64];
__device__ float  g_el[NN * 4];
__device__ float  g_er[NN * 4];
__device__ int    g_rowptr[NN + 1];
__device__ int    g_cursor[NN];
__device__ int    g_srcs[NE];
__device__ __half g_w0t[256 * 256];   // W0^T fp16 [n][k]
__device__ __half g_w1t[256 * 256];   // W1^T fp16
__device__ __half g_w2t[64 * 256];    // W2^T fp16
__device__ __half g_rw2t[64 * 256];   // res_w2^T fp16

#define AS_H 40   // halfs per SMEM row (80B, 16B-aligned, conflict-free frags)

// ---------------- weight transpose+convert: [K][N] f32 -> [N][K] f16 ----------------
__global__ void transpose_w_kernel(const float* __restrict__ in, __half* __restrict__ out,
                                   int K, int N) {
    __shared__ float t[32][33];
    int n0 = blockIdx.x * 32, k0 = blockIdx.y * 32;
    int tx = threadIdx.x, ty = threadIdx.y;   // 32 x 8
#pragma unroll
    for (int j = 0; j < 4; j++)
        t[ty + 8 * j][tx] = in[(size_t)(k0 + ty + 8 * j) * N + n0 + tx];
    __syncthreads();
#pragma unroll
    for (int j = 0; j < 4; j++)
        out[(size_t)(n0 + ty + 8 * j) * K + k0 + tx] = __float2half_rn(t[tx][ty + 8 * j]);
}

// ================= fp16 MMA GEMM, BN=128 (H=4 layers): BM=128,BN=128,BK=32 =================
// 8 warps (4m x 2n), warp tile 32x64; mma m16n8k16.f16. Each warp's 64 cols == one head.
// AHALF: A operand fp16 (h1) vs fp32 (x). C fp16. el/er warp-local epilogue.
template <int AHALF>
__global__ void __launch_bounds__(256) sgemm_fp16_elr128_kernel(
        const void* __restrict__ Av, const __half* __restrict__ Bt,
        __half* __restrict__ C, int M,
        const float* __restrict__ al, const float* __restrict__ ar,
        float* __restrict__ el, float* __restrict__ er) {
    const int K = 256, N = 256;
    __shared__ __half As[2][128 * AS_H];
    __shared__ __half Bs[2][128 * AS_H];

    int tid  = threadIdx.x;
    int wid  = tid >> 5;
    int lane = tid & 31;
    int row0 = blockIdx.y * 128, col0 = blockIdx.x * 128;

    int wm = (wid & 3) * 32;
    int wn = (wid >> 2) * 64;
    int head = (col0 >> 6) + (wid >> 2);

    int arow = tid >> 1;
    int kh   = (tid & 1) * 16;
    int ar_g = row0 + arow;
    bool avalid = (ar_g < M);

    const float*  Af = (const float*)Av;
    const __half* Ah = (const __half*)Av;

    float acc[2][8][4];
#pragma unroll
    for (int i = 0; i < 2; i++)
#pragma unroll
        for (int j = 0; j < 8; j++)
#pragma unroll
            for (int v = 0; v < 4; v++) acc[i][j][v] = 0.f;

    int fr = lane >> 2;
    int fc = lane & 3;

    uint4 rA[2], rB[2];
    // ---- prologue: load k-chunk 0 ----
    if (AHALF) {
#pragma unroll
        for (int i = 0; i < 2; i++)
            rA[i] = avalid ? *reinterpret_cast<const uint4*>(Ah + (size_t)ar_g * K + kh + 8 * i)
                           : make_uint4(0u, 0u, 0u, 0u);
    } else {
#pragma unroll
        for (int i = 0; i < 2; i++) {
            if (avalid) {
                float4 f0 = *reinterpret_cast<const float4*>(Af + (size_t)ar_g * K + kh + 8 * i);
                float4 f1 = *reinterpret_cast<const float4*>(Af + (size_t)ar_g * K + kh + 8 * i + 4);
                __half2 hh[4];
                hh[0] = __floats2half2_rn(f0.x, f0.y);
                hh[1] = __floats2half2_rn(f0.z, f0.w);
                hh[2] = __floats2half2_rn(f1.x, f1.y);
                hh[3] = __floats2half2_rn(f1.z, f1.w);
                rA[i] = *reinterpret_cast<const uint4*>(hh);
            } else rA[i] = make_uint4(0u, 0u, 0u, 0u);
        }
    }
#pragma unroll
    for (int i = 0; i < 2; i++)
        rB[i] = *reinterpret_cast<const uint4*>(Bt + (size_t)(col0 + arow) * K + kh + 8 * i);
#pragma unroll
    for (int i = 0; i < 2; i++) {
        *reinterpret_cast<uint4*>(&As[0][arow * AS_H + kh + 8 * i]) = rA[i];
        *reinterpret_cast<uint4*>(&Bs[0][arow * AS_H + kh + 8 * i]) = rB[i];
    }
    __syncthreads();

    int buf = 0;
    for (int k0 = 0; k0 < K; k0 += 32) {
        bool has_next = (k0 + 32 < K);
        if (has_next) {
            if (AHALF) {
#pragma unroll
                for (int i = 0; i < 2; i++)
                    rA[i] = avalid
                        ? *reinterpret_cast<const uint4*>(Ah + (size_t)ar_g * K + k0 + 32 + kh + 8 * i)
                        : make_uint4(0u, 0u, 0u, 0u);
            } else {
#pragma unroll
                for (int i = 0; i < 2; i++) {
                    if (avalid) {
                        float4 f0 = *reinterpret_cast<const float4*>(Af + (size_t)ar_g * K + k0 + 32 + kh + 8 * i);
                        float4 f1 = *reinterpret_cast<const float4*>(Af + (size_t)ar_g * K + k0 + 32 + kh + 8 * i + 4);
                        __half2 hh[4];
                        hh[0] = __floats2half2_rn(f0.x, f0.y);
                        hh[1] = __floats2half2_rn(f0.z, f0.w);
                        hh[2] = __floats2half2_rn(f1.x, f1.y);
                        hh[3] = __floats2half2_rn(f1.z, f1.w);
                        rA[i] = *reinterpret_cast<const uint4*>(hh);
                    } else rA[i] = make_uint4(0u, 0u, 0u, 0u);
                }
            }
#pragma unroll
            for (int i = 0; i < 2; i++)
                rB[i] = *reinterpret_cast<const uint4*>(Bt + (size_t)(col0 + arow) * K + k0 + 32 + kh + 8 * i);
        }

        const __half* Ab = As[buf];
        const __half* Bb = Bs[buf];
#pragma unroll
        for (int kb = 0; kb < 32; kb += 16) {
            unsigned a[2][4], b[8][2];
#pragma unroll
            for (int mt = 0; mt < 2; mt++) {
                int base = (wm + mt * 16 + fr) * AS_H + kb + 2 * fc;
                a[mt][0] = *reinterpret_cast<const unsigned*>(Ab + base);
                a[mt][1] = *reinterpret_cast<const unsigned*>(Ab + base + 8 * AS_H);
                a[mt][2] = *reinterpret_cast<const unsigned*>(Ab + base + 8);
                a[mt][3] = *reinterpret_cast<const unsigned*>(Ab + base + 8 * AS_H + 8);
            }
#pragma unroll
            for (int nt = 0; nt < 8; nt++) {
                int nbase = (wn + nt * 8 + fr) * AS_H + kb + 2 * fc;
                b[nt][0] = *reinterpret_cast<const unsigned*>(Bb + nbase);
                b[nt][1] = *reinterpret_cast<const unsigned*>(Bb + nbase + 8);
            }
#pragma unroll
            for (int mt = 0; mt < 2; mt++)
#pragma unroll
                for (int nt = 0; nt < 8; nt++) {
                    asm volatile(
                        "mma.sync.aligned.m16n8k16.row.col.f32.f16.f16.f32 "
                        "{%0,%1,%2,%3}, {%4,%5,%6,%7}, {%8,%9}, {%0,%1,%2,%3};\n"
                        : "+f"(acc[mt][nt][0]), "+f"(acc[mt][nt][1]),
                          "+f"(acc[mt][nt][2]), "+f"(acc[mt][nt][3])
                        : "r"(a[mt][0]), "r"(a[mt][1]), "r"(a[mt][2]), "r"(a[mt][3]),
                          "r"(b[nt][0]), "r"(b[nt][1]));
                }
        }

        if (has_next) {
#pragma unroll
            for (int i = 0; i < 2; i++) {
                *reinterpret_cast<uint4*>(&As[buf ^ 1][arow * AS_H + kh + 8 * i]) = rA[i];
                *reinterpret_cast<uint4*>(&Bs[buf ^ 1][arow * AS_H + kh + 8 * i]) = rB[i];
            }
            __syncthreads();
            buf ^= 1;
        }
    }

    // ---- C writeback (fp16) ----
#pragma unroll
    for (int mt = 0; mt < 2; mt++) {
#pragma unroll
        for (int nt = 0; nt < 8; nt++) {
            int crow = row0 + wm + mt * 16 + fr;
            int ccol = col0 + wn + nt * 8 + 2 * fc;
            if (crow < M)
                *reinterpret_cast<__half2*>(C + (size_t)crow * N + ccol) =
                    __floats2half2_rn(acc[mt][nt][0], acc[mt][nt][1]);
            if (crow + 8 < M)
                *reinterpret_cast<__half2*>(C + (size_t)(crow + 8) * N + ccol) =
                    __floats2half2_rn(acc[mt][nt][2], acc[mt][nt][3]);
        }
    }

    // ---- fused el/er (fp32 accumulators, warp-local) ----
    {
        const float* alh = al + head * 64;
        const float* arh = ar + head * 64;
        float sl[4] = {0.f, 0.f, 0.f, 0.f}, sr[4] = {0.f, 0.f, 0.f, 0.f};
#pragma unroll
        for (int mt = 0; mt < 2; mt++)
#pragma unroll
            for (int nt = 0; nt < 8; nt++) {
                int c = nt * 8 + 2 * fc;
                float a0 = alh[c], a1 = alh[c + 1];
                float r0 = arh[c], r1 = arh[c + 1];
                sl[mt * 2 + 0] += acc[mt][nt][0] * a0 + acc[mt][nt][1] * a1;
                sr[mt * 2 + 0] += acc[mt][nt][0] * r0 + acc[mt][nt][1] * r1;
                sl[mt * 2 + 1] += acc[mt][nt][2] * a0 + acc[mt][nt][3] * a1;
                sr[mt * 2 + 1] += acc[mt][nt][2] * r0 + acc[mt][nt][3] * r1;
            }
#pragma unroll
        for (int k = 0; k < 4; k++) {
            sl[k] += __shfl_xor_sync(0xffffffffu, sl[k], 1);
            sl[k] += __shfl_xor_sync(0xffffffffu, sl[k], 2);
            sr[k] += __shfl_xor_sync(0xffffffffu, sr[k], 1);
            sr[k] += __shfl_xor_sync(0xffffffffu, sr[k], 2);
        }
        if (fc == 0) {
            int rows[4] = {wm + fr, wm + fr + 8, wm + 16 + fr, wm + 16 + fr + 8};
#pragma unroll
            for (int k = 0; k < 4; k++) {
                int r = row0 + rows[k];
                if (r < M) {
                    el[(size_t)r * 4 + head] = sl[k];
                    er[(size_t)r * 4 + head] = sr[k];
                }
            }
        }
    }
}

// ================= fp16 MMA GEMM body, BN=64 (layer 2 dual) =================
// A fp16. OUTH=1: C fp16 + el/er; OUTH=0: C fp32 (residual).
template <int OUTH>
__device__ __forceinline__ void gemm_body64(const __half* __restrict__ A,
                                            const __half* __restrict__ Bt,
                                            void* __restrict__ Cv,
                                            int M, int N, int row0,
                                            const float* __restrict__ alh,
                                            const float* __restrict__ arh,
                                            float* __restrict__ el,
                                            float* __restrict__ er,
                                            bool do_elr) {
    const int K = 256;
    __shared__ __half As[2][128 * AS_H];
    __shared__ __half Bs[2][64 * AS_H];
    __shared__ float s_elr[128][2];

    int tid  = threadIdx.x;
    int wid  = tid >> 5;
    int lane = tid & 31;

    int wm = (wid & 3) * 32;
    int wn = (wid >> 2) * 32;

    int arow = tid >> 1;
    int kh   = (tid & 1) * 16;
    int ar_g = row0 + arow;
    bool avalid = (ar_g < M);

    int brow = tid >> 2;
    int bkq  = (tid & 3) * 8;

    float acc[2][4][4];
#pragma unroll
    for (int i = 0; i < 2; i++)
#pragma unroll
        for (int j = 0; j < 4; j++)
#pragma unroll
            for (int v = 0; v < 4; v++) acc[i][j][v] = 0.f;

    int fr = lane >> 2;
    int fc = lane & 3;

    uint4 rA[2], rB;
#pragma unroll
    for (int i = 0; i < 2; i++)
        rA[i] = avalid ? *reinterpret_cast<const uint4*>(A + (size_t)ar_g * K + kh + 8 * i)
                       : make_uint4(0u, 0u, 0u, 0u);
    rB = *reinterpret_cast<const uint4*>(Bt + (size_t)brow * K + bkq);
#pragma unroll
    for (int i = 0; i < 2; i++)
        *reinterpret_cast<uint4*>(&As[0][arow * AS_H + kh + 8 * i]) = rA[i];
    *reinterpret_cast<uint4*>(&Bs[0][brow * AS_H + bkq]) = rB;
    __syncthreads();

    int buf = 0;
    for (int k0 = 0; k0 < K; k0 += 32) {
        bool has_next = (k0 + 32 < K);
        if (has_next) {
#pragma unroll
            for (int i = 0; i < 2; i++)
                rA[i] = avalid
                    ? *reinterpret_cast<const uint4*>(A + (size_t)ar_g * K + k0 + 32 + kh + 8 * i)
                    : make_uint4(0u, 0u, 0u, 0u);
            rB = *reinterpret_cast<const uint4*>(Bt + (size_t)brow * K + k0 + 32 + bkq);
        }

        const __half* Ab = As[buf];
        const __half* Bb = Bs[buf];
#pragma unroll
        for (int kb = 0; kb < 32; kb += 16) {
            unsigned a[2][4], b[4][2];
#pragma unroll
            for (int mt = 0; mt < 2; mt++) {
                int base = (wm + mt * 16 + fr) * AS_H + kb + 2 * fc;
                a[mt][0] = *reinterpret_cast<const unsigned*>(Ab + base);
                a[mt][1] = *reinterpret_cast<const unsigned*>(Ab + base + 8 * AS_H);
                a[mt][2] = *reinterpret_cast<const unsigned*>(Ab + base + 8);
                a[mt][3] = *reinterpret_cast<const unsigned*>(Ab + base + 8 * AS_H + 8);
            }
#pragma unroll
            for (int nt = 0; nt < 4; nt++) {
                int nbase = (wn + nt * 8 + fr) * AS_H + kb + 2 * fc;
                b[nt][0] = *reinterpret_cast<const unsigned*>(Bb + nbase);
                b[nt][1] = *reinterpret_cast<const unsigned*>(Bb + nbase + 8);
            }
#pragma unroll
            for (int mt = 0; mt < 2; mt++)
#pragma unroll
                for (int nt = 0; nt < 4; nt++) {
                    asm volatile(
                        "mma.sync.aligned.m16n8k16.row.col.f32.f16.f16.f32 "
                        "{%0,%1,%2,%3}, {%4,%5,%6,%7}, {%8,%9}, {%0,%1,%2,%3};\n"
                        : "+f"(acc[mt][nt][0]), "+f"(acc[mt][nt][1]),
                          "+f"(acc[mt][nt][2]), "+f"(acc[mt][nt][3])
                        : "r"(a[mt][0]), "r"(a[mt][1]), "r"(a[mt][2]), "r"(a[mt][3]),
                          "r"(b[nt][0]), "r"(b[nt][1]));
                }
        }

        if (has_next) {
#pragma unroll
            for (int i = 0; i < 2; i++)
                *reinterpret_cast<uint4*>(&As[buf ^ 1][arow * AS_H + kh + 8 * i]) = rA[i];
            *reinterpret_cast<uint4*>(&Bs[buf ^ 1][brow * AS_H + bkq]) = rB;
            __syncthreads();
            buf ^= 1;
        }
    }

#pragma unroll
    for (int mt = 0; mt < 2; mt++) {
#pragma unroll
        for (int nt = 0; nt < 4; nt++) {
            int crow = row0 + wm + mt * 16 + fr;
            int ccol = wn + nt * 8 + 2 * fc;
            if (OUTH) {
                __half* C = (__half*)Cv;
                if (crow < M)
                    *reinterpret_cast<__half2*>(C + (size_t)crow * N + ccol) =
                        __floats2half2_rn(acc[mt][nt][0], acc[mt][nt][1]);
                if (crow + 8 < M)
                    *reinterpret_cast<__half2*>(C + (size_t)(crow + 8) * N + ccol) =
                        __floats2half2_rn(acc[mt][nt][2], acc[mt][nt][3]);
            } else {
                float* C = (float*)Cv;
                if (crow < M)
                    *reinterpret_cast<float2*>(C + (size_t)crow * N + ccol) =
                        make_float2(acc[mt][nt][0], acc[mt][nt][1]);
                if (crow + 8 < M)
                    *reinterpret_cast<float2*>(C + (size_t)(crow + 8) * N + ccol) =
                        make_float2(acc[mt][nt][2], acc[mt][nt][3]);
            }
        }
    }

    if (do_elr) {
        float sl[4] = {0.f, 0.f, 0.f, 0.f}, sr[4] = {0.f, 0.f, 0.f, 0.f};
#pragma unroll
        for (int mt = 0; mt < 2; mt++)
#pragma unroll
            for (int nt = 0; nt < 4; nt++) {
                int c = wn + nt * 8 + 2 * fc;
                float a0 = alh[c], a1 = alh[c + 1];
                float r0 = arh[c], r1 = arh[c + 1];
                sl[mt * 2 + 0] += acc[mt][nt][0] * a0 + acc[mt][nt][1] * a1;
                sr[mt * 2 + 0] += acc[mt][nt][0] * r0 + acc[mt][nt][1] * r1;
                sl[mt * 2 + 1] += acc[mt][nt][2] * a0 + acc[mt][nt][3] * a1;
                sr[mt * 2 + 1] += acc[mt][nt][2] * r0 + acc[mt][nt][3] * r1;
            }
#pragma unroll
        for (int k = 0; k < 4; k++) {
            sl[k] += __shfl_xor_sync(0xffffffffu, sl[k], 1);
            sl[k] += __shfl_xor_sync(0xffffffffu, sl[k], 2);
            sr[k] += __shfl_xor_sync(0xffffffffu, sr[k], 1);
            sr[k] += __shfl_xor_sync(0xffffffffu, sr[k], 2);
        }
        int nhalf = wid >> 2;
        int rows[4] = {wm + fr, wm + fr + 8, wm + 16 + fr, wm + 16 + fr + 8};
        if (nhalf == 0 && fc == 0) {
#pragma unroll
            for (int k = 0; k < 4; k++) {
                s_elr[rows[k]][0] = sl[k];
                s_elr[rows[k]][1] = sr[k];
            }
        }
        __syncthreads();
        if (nhalf == 1 && fc == 0) {
#pragma unroll
            for (int k = 0; k < 4; k++) {
                int r = row0 + rows[k];
                if (r < M) {
                    el[r] = s_elr[rows[k]][0] + sl[k];
                    er[r] = s_elr[rows[k]][1] + sr[k];
                }
            }
        }
    }
}

__global__ void __launch_bounds__(256) sgemm_fp16_dual_kernel(
        const __half* __restrict__ A, const __half* __restrict__ B0t,
        const __half* __restrict__ B1t, __half* __restrict__ C0,
        float* __restrict__ C1, int M,
        const float* __restrict__ al, const float* __restrict__ ar,
        float* __restrict__ el, float* __restrict__ er) {
    if (blockIdx.x == 0)
        gemm_body64<1>(A, B0t, C0, M, 64, blockIdx.y * 128, al, ar, el, er, true);
    else
        gemm_body64<0>(A, B1t, C1, M, 64, blockIdx.y * 128, al, ar, el, er, false);
}

// ---------------- CSR build ----------------
__global__ void zero_deg_kernel(int* __restrict__ deg) {
    int i = blockIdx.x * blockDim.x + threadIdx.x;
    if (i < NN) deg[i] = 0;
}

__global__ void hist_kernel(const int* __restrict__ dst, int* __restrict__ deg) {
    int e = blockIdx.x * blockDim.x + threadIdx.x;
    if (e < NE) atomicAdd(&deg[dst[e]], 1);
}

__global__ void scan_kernel(int* __restrict__ deg_cursor, int* __restrict__ rowptr) {
    __shared__ int warp_sums[32];
    __shared__ int s_carry;
    int tid = threadIdx.x;  // 1024 threads
    if (tid == 0) s_carry = 0;
    __syncthreads();
    for (int base = 0; base < NN; base += 1024) {
        int i = base + tid;
        int v = (i < NN) ? deg_cursor[i] : 0;
        int x = v;
#pragma unroll
        for (int o = 1; o < 32; o <<= 1) {
            int y = __shfl_up_sync(0xffffffffu, x, o);
            if ((tid & 31) >= o) x += y;
        }
        if ((tid & 31) == 31) warp_sums[tid >> 5] = x;
        __syncthreads();
        if (tid < 32) {
            int s = warp_sums[tid];
#pragma unroll
            for (int o = 1; o < 32; o <<= 1) {
                int y = __shfl_up_sync(0xffffffffu, s, o);
                if (tid >= o) s += y;
            }
            warp_sums[tid] = s;
        }
        __syncthreads();
        int excl = x - v + ((tid >= 32) ? warp_sums[(tid >> 5) - 1] : 0);
        int val  = s_carry + excl;
        if (i < NN) { rowptr[i] = val; deg_cursor[i] = val; }
        int chunk_total = warp_sums[31];
        __syncthreads();
        if (tid == 0) s_carry += chunk_total;
        __syncthreads();
    }
    if (tid == 0) rowptr[NN] = NE;
}

__global__ void scatter_kernel(const int* __restrict__ src, const int* __restrict__ dst,
                               int* __restrict__ cursor, int* __restrict__ srcs) {
    int e = blockIdx.x * blockDim.x + threadIdx.x;
    if (e < NE) {
        int p = atomicAdd(&cursor[dst[e]], 1);
        srcs[p] = src[e];
    }
}

// ---------------- single-pass softmax-aggregate, H=4, fp16 feat, unroll-2 ----------------
template <int ACT, int RES>
__global__ void __launch_bounds__(256) gat_agg4_kernel(
        const int* __restrict__ rowptr, const int* __restrict__ srcs,
        const float* __restrict__ el, const float* __restrict__ er,
        const __half* __restrict__ feat, const float* __restrict__ bias,
        const __half* __restrict__ resid, __half* __restrict__ out) {
    int w = blockIdx.x * (blockDim.x >> 5) + (threadIdx.x >> 5);
    if (w >= NN) return;
    int lane = threadIdx.x & 31;
    int start = rowptr[w], end = rowptr[w + 1];

    int h  = lane >> 3;
    int c0 = 8 * lane;
    float erv = er[(size_t)w * 4 + h];

    float acc[8] = {0.f, 0.f, 0.f, 0.f, 0.f, 0.f, 0.f, 0.f};
    float sd = 0.f;

    int i = start;
    for (; i + 1 < end; i += 2) {
        int s0 = srcs[i];
        int s1 = srcs[i + 1];
        float ev0 = el[(size_t)s0 * 4 + h];
        float ev1 = el[(size_t)s1 * 4 + h];
        uint4 u0 = *reinterpret_cast<const uint4*>(feat + (size_t)s0 * 256 + c0);
        uint4 u1 = *reinterpret_cast<const uint4*>(feat + (size_t)s1 * 256 + c0);

        float v0 = ev0 + erv; v0 = (v0 > 0.f) ? v0 : 0.2f * v0;
        float v1 = ev1 + erv; v1 = (v1 > 0.f) ? v1 : 0.2f * v1;
        float a0 = __expf(v0);
        float a1 = __expf(v1);
        sd += a0 + a1;

        const __half2* h0 = reinterpret_cast<const __half2*>(&u0);
        const __half2* h1p = reinterpret_cast<const __half2*>(&u1);
#pragma unroll
        for (int j = 0; j < 4; j++) {
            float2 f0 = __half22float2(h0[j]);
            float2 f1 = __half22float2(h1p[j]);
            acc[2 * j + 0] = fmaf(a0, f0.x, fmaf(a1, f1.x, acc[2 * j + 0]));
            acc[2 * j + 1] = fmaf(a0, f0.y, fmaf(a1, f1.y, acc[2 * j + 1]));
        }
    }
    if (i < end) {
        int s0 = srcs[i];
        float ev0 = el[(size_t)s0 * 4 + h];
        float v0 = ev0 + erv; v0 = (v0 > 0.f) ? v0 : 0.2f * v0;
        float a0 = __expf(v0);
        sd += a0;
        uint4 u0 = *reinterpret_cast<const uint4*>(feat + (size_t)s0 * 256 + c0);
        const __half2* h0 = reinterpret_cast<const __half2*>(&u0);
#pragma unroll
        for (int j = 0; j < 4; j++) {
            float2 f0 = __half22float2(h0[j]);
            acc[2 * j + 0] = fmaf(a0, f0.x, acc[2 * j + 0]);
            acc[2 * j + 1] = fmaf(a0, f0.y, acc[2 * j + 1]);
        }
    }

    float inv = (sd > 0.f) ? 1.f / sd : 0.f;
    float o[8];
    {
        float4 b0 = *reinterpret_cast<const float4*>(bias + c0);
        float4 b1 = *reinterpret_cast<const float4*>(bias + c0 + 4);
        o[0] = acc[0] * inv + b0.x; o[1] = acc[1] * inv + b0.y;
        o[2] = acc[2] * inv + b0.z; o[3] = acc[3] * inv + b0.w;
        o[4] = acc[4] * inv + b1.x; o[5] = acc[5] * inv + b1.y;
        o[6] = acc[6] * inv + b1.z; o[7] = acc[7] * inv + b1.w;
    }
    if (RES) {
        uint4 ur = *reinterpret_cast<const uint4*>(resid + (size_t)w * 256 + c0);
        const __half2* hr = reinterpret_cast<const __half2*>(&ur);
#pragma unroll
        for (int j = 0; j < 4; j++) {
            float2 f = __half22float2(hr[j]);
            o[2 * j + 0] += f.x;
            o[2 * j + 1] += f.y;
        }
    }
    if (ACT) {
#pragma unroll
        for (int j = 0; j < 8; j++)
            o[j] = (o[j] > 0.f) ? o[j] : expm1f(o[j]);
    }
    __half2 packed[4];
#pragma unroll
    for (int j = 0; j < 4; j++)
        packed[j] = __floats2half2_rn(o[2 * j], o[2 * j + 1]);
    *reinterpret_cast<uint4*>(out + (size_t)w * 256 + c0) =
        *reinterpret_cast<const uint4*>(packed);
}

// ---------------- single-pass softmax-aggregate, H=1, fp16 feat, unroll-2 ----------------
__global__ void __launch_bounds__(256) gat_agg1_kernel(
        const int* __restrict__ rowptr, const int* __restrict__ srcs,
        const float* __restrict__ el, const float* __restrict__ er,
        const __half* __restrict__ feat, const float* __restrict__ bias,
        const float* __restrict__ resid, float* __restrict__ out) {
    int w = blockIdx.x * (blockDim.x >> 5) + (threadIdx.x >> 5);
    if (w >= NN) return;
    int lane = threadIdx.x & 31;
    int start = rowptr[w], end = rowptr[w + 1];
    float erv = er[w];

    int c0 = 2 * lane;
    float2 acc = make_float2(0.f, 0.f);
    float ssum = 0.f;

    int i = start;
    for (; i + 1 < end; i += 2) {
        int s0 = srcs[i];
        int s1 = srcs[i + 1];
        float e0 = el[s0];
        float e1 = el[s1];
        __half2 q0 = *reinterpret_cast<const __half2*>(feat + (size_t)s0 * 64 + c0);
        __half2 q1 = *reinterpret_cast<const __half2*>(feat + (size_t)s1 * 64 + c0);

        float v0 = e0 + erv; v0 = (v0 > 0.f) ? v0 : 0.2f * v0;
        float v1 = e1 + erv; v1 = (v1 > 0.f) ? v1 : 0.2f * v1;
        float a0 = __expf(v0);
        float a1 = __expf(v1);
        ssum += a0 + a1;
        float2 f0 = __half22float2(q0);
        float2 f1 = __half22float2(q1);
        acc.x = fmaf(a0, f0.x, fmaf(a1, f1.x, acc.x));
        acc.y = fmaf(a0, f0.y, fmaf(a1, f1.y, acc.y));
    }
    if (i < end) {
        int s0 = srcs[i];
        float e0 = el[s0];
        float v0 = e0 + erv; v0 = (v0 > 0.f) ? v0 : 0.2f * v0;
        float a0 = __expf(v0);
        ssum += a0;
        float2 f0 = __half22float2(*reinterpret_cast<const __half2*>(feat + (size_t)s0 * 64 + c0));
        acc.x = fmaf(a0, f0.x, acc.x);
        acc.y = fmaf(a0, f0.y, acc.y);
    }
    float inv = (ssum > 0.f) ? 1.f / ssum : 0.f;
    acc.x *= inv;
    acc.y *= inv;

    float2 b = *reinterpret_cast<const float2*>(bias + c0);
    float2 r = *reinterpret_cast<const float2*>(resid + (size_t)w * 64 + c0);
    acc.x += b.x + r.x;
    acc.y += b.y + r.y;
    *reinterpret_cast<float2*>(out + (size_t)w * 64 + c0) = acc;
}

// ---------------- host ----------------
extern "C" void kernel_launch(void* const* d_in, const int* in_sizes, int n_in,
                              void* d_out, int out_size) {
    const float* x    = (const float*)d_in[0];
    const int*   src  = (const int*)d_in[1];
    const int*   dst  = (const int*)d_in[2];
    const float* W0   = (const float*)d_in[3];
    const float* al0  = (const float*)d_in[4];
    const float* ar0  = (const float*)d_in[5];
    const float* b0   = (const float*)d_in[6];
    const float* W1   = (const float*)d_in[7];
    const float* al1  = (const float*)d_in[8];
    const float* ar1  = (const float*)d_in[9];
    const float* b1   = (const float*)d_in[10];
    const float* W2   = (const float*)d_in[11];
    const float* al2  = (const float*)d_in[12];
    const float* ar2  = (const float*)d_in[13];
    const float* b2   = (const float*)d_in[14];
    const float* rw2  = (const float*)d_in[15];
    float* out = (float*)d_out;

    __half *feat16, *h1, *h2, *w0t, *w1t, *w2t, *rw2t;
    float *res2, *el, *er;
    int *rowptr, *cursor, *srcs;
    cudaGetSymbolAddress((void**)&feat16, g_feat16);
    cudaGetSymbolAddress((void**)&h1,     g_h1);
    cudaGetSymbolAddress((void**)&h2,     g_h2);
    cudaGetSymbolAddress((void**)&res2,   g_res2);
    cudaGetSymbolAddress((void**)&el,     g_el);
    cudaGetSymbolAddress((void**)&er,     g_er);
    cudaGetSymbolAddress((void**)&rowptr, g_rowptr);
    cudaGetSymbolAddress((void**)&cursor, g_cursor);
    cudaGetSymbolAddress((void**)&srcs,   g_srcs);
    cudaGetSymbolAddress((void**)&w0t,    g_w0t);
    cudaGetSymbolAddress((void**)&w1t,    g_w1t);
    cudaGetSymbolAddress((void**)&w2t,    g_w2t);
    cudaGetSymbolAddress((void**)&rw2t,   g_rw2t);

    static cudaStream_t s2 = nullptr;
    static cudaEvent_t ev_fork = nullptr, ev_join = nullptr;
    if (s2 == nullptr) {
        cudaStreamCreate(&s2);
        cudaEventCreateWithFlags(&ev_fork, cudaEventDisableTiming);
        cudaEventCreateWithFlags(&ev_join, cudaEventDisableTiming);
    }

    const int MTILES = (NN + 127) / 128;        // 391
    const int NODE_WARP_BLOCKS = (NN + 7) / 8;  // 6250

    // ---------- fork: weight preps + CSR build on s2 / w0t + layer-0 GEMM on main ----------
    cudaEventRecord(ev_fork, 0);
    cudaStreamWaitEvent(s2, ev_fork, 0);

    transpose_w_kernel<<<dim3(8, 8), dim3(32, 8), 0, s2>>>(W1, w1t, 256, 256);
    transpose_w_kernel<<<dim3(2, 8), dim3(32, 8), 0, s2>>>(W2, w2t, 256, 64);
    transpose_w_kernel<<<dim3(2, 8), dim3(32, 8), 0, s2>>>(rw2, rw2t, 256, 64);
    zero_deg_kernel<<<(NN + 255) / 256, 256, 0, s2>>>(cursor);
    hist_kernel<<<(NE + 255) / 256, 256, 0, s2>>>(dst, cursor);
    scan_kernel<<<1, 1024, 0, s2>>>(cursor, rowptr);
    scatter_kernel<<<(NE + 255) / 256, 256, 0, s2>>>(src, dst, cursor, srcs);
    cudaEventRecord(ev_join, s2);

    transpose_w_kernel<<<dim3(8, 8), dim3(32, 8)>>>(W0, w0t, 256, 256);
    sgemm_fp16_elr128_kernel<0><<<dim3(2, MTILES), 256>>>(x, w0t, feat16, NN, al0, ar0, el, er);

    cudaStreamWaitEvent(0, ev_join, 0);

    // ================= layer 0 aggregate =================
    gat_agg4_kernel<1, 0><<<NODE_WARP_BLOCKS, 256>>>(rowptr, srcs, el, er, feat16, b0, nullptr, h1);

    // ================= layer 1 =================
    sgemm_fp16_elr128_kernel<1><<<dim3(2, MTILES), 256>>>(h1, w1t, feat16, NN, al1, ar1, el, er);
    gat_agg4_kernel<1, 1><<<NODE_WARP_BLOCKS, 256>>>(rowptr, srcs, el, er, feat16, b1, h1, h2);

    // ================= layer 2 =================
    sgemm_fp16_dual_kernel<<<dim3(2, MTILES), 256>>>(h2, w2t, rw2t, feat16, res2, NN, al2, ar2, el, er);
    gat_agg1_kernel<<<NODE_WARP_BLOCKS, 256>>>(rowptr, srcs, el, er, feat16, b2, res2, out);
}